// round 2
// baseline (speedup 1.0000x reference)
#include <cuda_runtime.h>
#include <math.h>

#define HW 65536
#define NBUF (2*256*HW)

// ---------------- static scratch ----------------
__device__ float g_A[NBUF];   // conv_iem raw -> q (window layout)
__device__ float g_B[NBUF];   // conv_nem raw -> k (window layout)
__device__ float g_C[NBUF];   // illum map -> v (window layout)
__device__ float g_D[NBUF];   // noise map -> attn out (window layout)
__device__ float g_wct[2*589824];  // conv weights transposed [m][c][tap][oc]
__device__ float g_wt4[4*65536];   // 1x1 weights transposed [m][c][oc]
__device__ float g_bna[512];
__device__ float g_bnc[512];
__device__ float g_is[2*HW];
__device__ float g_ns[2*HW];

// ---------------- weight transposes ----------------
__global__ void tconv_kernel(const float* __restrict__ w0, const float* __restrict__ w1,
                             float* __restrict__ out) {
    int i = blockIdx.x * 256 + threadIdx.x;          // 2*589824
    int m = i / 589824;
    int r = i - m * 589824;                          // (c*9+tap)*256 + o
    int o  = r & 255;
    int ct = r >> 8;
    int tap = ct % 9;
    int c   = ct / 9;
    const float* w = m ? w1 : w0;
    out[i] = w[o * 2304 + c * 9 + tap];
}

__global__ void t1x1_kernel(const float* __restrict__ wq, const float* __restrict__ wk,
                            const float* __restrict__ wv, const float* __restrict__ wp,
                            float* __restrict__ out) {
    int i = blockIdx.x * 256 + threadIdx.x;          // 4*65536
    int m = i >> 16;
    int r = i & 65535;
    int c = r >> 8;
    int o = r & 255;
    const float* w = (m == 0) ? wq : (m == 1) ? wk : (m == 2) ? wv : wp;
    out[i] = w[o * 256 + c];
}

// ---------------- 3x3 conv, direct, fp32 ----------------
// tile: 64 oc x (32w x 8h), 256 threads, micro 8oc x 8px
__global__ void __launch_bounds__(256) conv3_kernel(const float* __restrict__ x,
                                                    const float* __restrict__ wt,
                                                    float* __restrict__ out) {
    __shared__ float xs[8][10][36];
    __shared__ float ws[8][9][64];
    const int tid = threadIdx.x;
    const int b   = blockIdx.z >> 2;
    const int oc0 = (blockIdx.z & 3) * 64;
    const int x0  = blockIdx.x * 32;
    const int y0  = blockIdx.y * 8;
    const int ocg = tid & 7;
    const int pxg = tid >> 3;
    const int row  = pxg >> 2;
    const int col8 = (pxg & 3) * 8;

    float acc[8][8];
#pragma unroll
    for (int o = 0; o < 8; o++)
#pragma unroll
        for (int j = 0; j < 8; j++) acc[o][j] = 0.f;

    for (int chunk = 0; chunk < 32; chunk++) {
        const int c0 = chunk * 8;
        for (int i = tid; i < 2720; i += 256) {       // 8ch x 10 x 34
            int c  = i / 340;
            int rr = (i % 340) / 34;
            int cl = i % 34;
            int gy = y0 + rr - 1;
            int gx = x0 + cl - 1;
            float v = 0.f;
            if ((unsigned)gy < 256u && (unsigned)gx < 256u)
                v = x[(((size_t)((b << 8) + c0 + c)) << 16) + (gy << 8) + gx];
            xs[c][rr][cl] = v;
        }
        for (int i = tid; i < 4608; i += 256) {       // 8ch x 9 taps x 64 oc
            int c   = i / 576;
            int rem = i - c * 576;
            int tap = rem >> 6;
            int o   = rem & 63;
            ws[c][tap][o] = wt[((c0 + c) * 9 + tap) * 256 + oc0 + o];
        }
        __syncthreads();

#pragma unroll
        for (int c = 0; c < 8; c++) {
            float xr[3][10];
#pragma unroll
            for (int ky = 0; ky < 3; ky++) {
                float4 a4 = *(const float4*)&xs[c][row + ky][col8];
                float4 b4 = *(const float4*)&xs[c][row + ky][col8 + 4];
                xr[ky][0]=a4.x; xr[ky][1]=a4.y; xr[ky][2]=a4.z; xr[ky][3]=a4.w;
                xr[ky][4]=b4.x; xr[ky][5]=b4.y; xr[ky][6]=b4.z; xr[ky][7]=b4.w;
                xr[ky][8]=xs[c][row + ky][col8 + 8];
                xr[ky][9]=xs[c][row + ky][col8 + 9];
            }
#pragma unroll
            for (int ky = 0; ky < 3; ky++)
#pragma unroll
                for (int kx = 0; kx < 3; kx++) {
                    const int tap = ky * 3 + kx;
                    float4 wa = *(const float4*)&ws[c][tap][ocg * 8];
                    float4 wb = *(const float4*)&ws[c][tap][ocg * 8 + 4];
                    float w8[8] = {wa.x, wa.y, wa.z, wa.w, wb.x, wb.y, wb.z, wb.w};
#pragma unroll
                    for (int o = 0; o < 8; o++)
#pragma unroll
                        for (int j = 0; j < 8; j++)
                            acc[o][j] = fmaf(w8[o], xr[ky][kx + j], acc[o][j]);
                }
        }
        __syncthreads();
    }

#pragma unroll
    for (int o = 0; o < 8; o++) {
        int oc = oc0 + ocg * 8 + o;
        size_t obase = (((size_t)(b * 256 + oc)) << 16) + ((y0 + row) << 8) + x0 + col8;
        float4 s0 = {acc[o][0], acc[o][1], acc[o][2], acc[o][3]};
        float4 s1 = {acc[o][4], acc[o][5], acc[o][6], acc[o][7]};
        *(float4*)&out[obase]     = s0;
        *(float4*)&out[obase + 4] = s1;
    }
}

// ---------------- BN stats (training mode, per channel over B,H,W) ----------------
__global__ void bnstats_kernel(const float* __restrict__ conv,
                               const float* __restrict__ gamma,
                               const float* __restrict__ beta,
                               float* __restrict__ pa, float* __restrict__ pc) {
    const int ch = blockIdx.x;
    const int tid = threadIdx.x;
    const float* p0 = conv + ((size_t)ch << 16);
    const float* p1 = conv + ((size_t)(256 + ch) << 16);
    float s = 0.f, s2 = 0.f;
    for (int k = tid; k < 65536; k += 256) {
        float v = p0[k]; s += v; s2 += v * v;
        v = p1[k]; s += v; s2 += v * v;
    }
    __shared__ float ss[256], ss2[256];
    ss[tid] = s; ss2[tid] = s2;
    __syncthreads();
    for (int st = 128; st > 0; st >>= 1) {
        if (tid < st) { ss[tid] += ss[tid + st]; ss2[tid] += ss2[tid + st]; }
        __syncthreads();
    }
    if (tid == 0) {
        float m   = ss[0]  * (1.f / 131072.f);
        float var = ss2[0] * (1.f / 131072.f) - m * m;
        float a = gamma[ch] * rsqrtf(var + 1e-5f);
        pa[ch] = a;
        pc[ch] = beta[ch] - m * a;
    }
}

// ---------------- depthwise conv (BN affine + relu6 fused on input) ----------------
__global__ void dwconv_kernel(const float* __restrict__ conv,
                              const float* __restrict__ pa, const float* __restrict__ pc,
                              const float* __restrict__ wdw, float* __restrict__ out) {
    int gi = blockIdx.x * 256 + threadIdx.x;   // (b*256+ch)*65536 + p
    int p  = gi & 65535;
    int bc = gi >> 16;
    int ch = bc & 255;
    int y  = p >> 8, xx = p & 255;
    float a = pa[ch], c = pc[ch];
    float w[9];
#pragma unroll
    for (int t = 0; t < 9; t++) w[t] = wdw[ch * 9 + t];
    const float* src = conv + ((size_t)bc << 16);
    float acc = 0.f;
#pragma unroll
    for (int ky = 0; ky < 3; ky++) {
        int yy = y + ky - 1;
        if ((unsigned)yy >= 256u) continue;
#pragma unroll
        for (int kx = 0; kx < 3; kx++) {
            int xv = xx + kx - 1;
            if ((unsigned)xv >= 256u) continue;
            float t = src[(yy << 8) + xv];
            t = t * a + c;
            t = fminf(fmaxf(t, 0.f), 6.f);
            acc = fmaf(w[ky * 3 + kx], t, acc);
        }
    }
    out[gi] = acc;
}

// ---------------- per-pixel channel mean of both maps ----------------
__global__ void chanmean_kernel(const float* __restrict__ il, const float* __restrict__ nm,
                                float* __restrict__ is, float* __restrict__ ns) {
    int p = blockIdx.x * 256 + threadIdx.x;
    int b = blockIdx.y;
    float s1 = 0.f, s2 = 0.f;
    for (int c = 0; c < 256; c++) {
        size_t idx = (((size_t)(b * 256 + c)) << 16) + p;
        s1 += il[idx];
        s2 += nm[idx];
    }
    is[(b << 16) + p] = s1 * (1.f / 256.f);
    ns[(b << 16) + p] = s2 * (1.f / 256.f);
}

// ---------------- 1x1 channel GEMM ----------------
// MODE 0: NCHW in -> window layout out [b,h,win,64,32]
// MODE 3: window-gather in -> NCHW out
template <int MODE>
__global__ void __launch_bounds__(128) gemm1x1(const float* __restrict__ wt,
                                               const float* __restrict__ in,
                                               float* __restrict__ out) {
    __shared__ float sIn[16][128];
    __shared__ float sW[16][64];
    const int tid = threadIdx.x;
    const int b   = blockIdx.z;
    const int oc0 = blockIdx.y * 64;
    const int pxbase = blockIdx.x * 128;
    const int ocg = tid & 7, pxg = tid >> 3;
    const int ocl = ocg * 8, pxl = pxg * 8;

    float acc[8][8];
#pragma unroll
    for (int o = 0; o < 8; o++)
#pragma unroll
        for (int j = 0; j < 8; j++) acc[o][j] = 0.f;

    for (int ch = 0; ch < 16; ch++) {
        const int c0 = ch * 16;
#pragma unroll
        for (int k = 0; k < 8; k++) {
            int idx = k * 128 + tid;
            int c = idx >> 6, o = idx & 63;
            sW[c][o] = wt[(c0 + c) * 256 + oc0 + o];
        }
        if (MODE < 3) {
#pragma unroll
            for (int k = 0; k < 16; k++) {
                int idx = k * 128 + tid;
                int c = idx >> 7, pxi = idx & 127;
                sIn[c][pxi] = in[(((size_t)((b << 8) + c0 + c)) << 16) + pxbase + pxi];
            }
        } else {
            int c = c0 + (tid & 15);
            int h = c >> 5, dd = c & 31;
            size_t hb = ((size_t)(b * 8 + h)) << 21;
#pragma unroll
            for (int k = 0; k < 16; k++) {
                int pxi = (tid >> 4) + k * 8;
                int p = pxbase + pxi;
                int y = p >> 8, xx = p & 255;
                int win = ((y >> 3) << 5) + (xx >> 3);
                int pix = ((y & 7) << 3) + (xx & 7);
                sIn[c - c0][pxi] = in[hb + ((size_t)win << 11) + (pix << 5) + dd];
            }
        }
        __syncthreads();
#pragma unroll
        for (int c = 0; c < 16; c++) {
            float4 w0 = *(const float4*)&sW[c][ocl];
            float4 w1 = *(const float4*)&sW[c][ocl + 4];
            float4 x0 = *(const float4*)&sIn[c][pxl];
            float4 x1 = *(const float4*)&sIn[c][pxl + 4];
            float wv[8] = {w0.x, w0.y, w0.z, w0.w, w1.x, w1.y, w1.z, w1.w};
            float xv[8] = {x0.x, x0.y, x0.z, x0.w, x1.x, x1.y, x1.z, x1.w};
#pragma unroll
            for (int o = 0; o < 8; o++)
#pragma unroll
                for (int j = 0; j < 8; j++)
                    acc[o][j] = fmaf(wv[o], xv[j], acc[o][j]);
        }
        __syncthreads();
    }

    if (MODE < 3) {
        int pwin[8], ppix[8];
#pragma unroll
        for (int j = 0; j < 8; j++) {
            int p = pxbase + pxl + j;
            int y = p >> 8, xx = p & 255;
            pwin[j] = ((y >> 3) << 5) + (xx >> 3);
            ppix[j] = ((y & 7) << 3) + (xx & 7);
        }
#pragma unroll
        for (int o = 0; o < 8; o++) {
            int oc = oc0 + ocl + o;
            int h = oc >> 5, dd = oc & 31;
            size_t basep = (((size_t)(b * 8 + h)) << 21) + dd;
#pragma unroll
            for (int j = 0; j < 8; j++)
                out[basep + ((size_t)pwin[j] << 11) + (ppix[j] << 5)] = acc[o][j];
        }
    } else {
#pragma unroll
        for (int o = 0; o < 8; o++) {
            int oc = oc0 + ocl + o;
            size_t basep = (((size_t)(b * 256 + oc)) << 16) + pxbase + pxl;
            float4 s0 = {acc[o][0], acc[o][1], acc[o][2], acc[o][3]};
            float4 s1 = {acc[o][4], acc[o][5], acc[o][6], acc[o][7]};
            *(float4*)&out[basep]     = s0;
            *(float4*)&out[basep + 4] = s1;
        }
    }
}

// ---------------- windowed attention ----------------
// one block per (b, head, window); 64 threads, thread i = query row i
__global__ void __launch_bounds__(64) attn_kernel(const float* __restrict__ q,
                                                  const float* __restrict__ k,
                                                  const float* __restrict__ v,
                                                  const float* __restrict__ is,
                                                  const float* __restrict__ ns,
                                                  const float* __restrict__ temp,
                                                  float* __restrict__ out) {
    __shared__ float ks[64][32];
    __shared__ float vs[64][32];
    __shared__ float sc[64][66];
    const int i   = threadIdx.x;
    const int win = blockIdx.x;
    const int h   = blockIdx.y;
    const int b   = blockIdx.z;
    const size_t base = (((size_t)(b * 8 + h)) << 21) + ((size_t)win << 11);

    // pixel coords of row i within this window
    const int y = ((win >> 5) << 3) + (i >> 3);
    const int x = ((win & 31) << 3) + (i & 7);
    const int pidx = (b << 16) + (y << 8) + x;

    // load k row i, fold clip(1-noise)/norm into it; load v row i
    float kr[32];
    float kn = 0.f;
#pragma unroll
    for (int d = 0; d < 32; d++) {
        kr[d] = k[base + (i << 5) + d];
        kn = fmaf(kr[d], kr[d], kn);
        vs[i][d] = v[base + (i << 5) + d];
    }
    float nsv = ns[pidx];
    float kmul = fminf(fmaxf(1.f - nsv, 0.f), 1.f) / fmaxf(sqrtf(kn), 1e-12f);
#pragma unroll
    for (int d = 0; d < 32; d++) ks[i][d] = kr[d] * kmul;

    // load q row i, fold (1+illum)/norm * scale * temperature into it
    float qr[32];
    float qn = 0.f;
#pragma unroll
    for (int d = 0; d < 32; d++) {
        qr[d] = q[base + (i << 5) + d];
        qn = fmaf(qr[d], qr[d], qn);
    }
    float qmul = (1.f + is[pidx]) / fmaxf(sqrtf(qn), 1e-12f)
               * 0.17677669529663687f /* 32^-0.5 */ * temp[h];
#pragma unroll
    for (int d = 0; d < 32; d++) qr[d] *= qmul;

    __syncthreads();

    // scores
    float mx = -1e30f;
#pragma unroll
    for (int j = 0; j < 64; j++) {
        float s = 0.f;
#pragma unroll
        for (int d = 0; d < 32; d++) s = fmaf(qr[d], ks[j][d], s);
        sc[i][j] = s;
        mx = fmaxf(mx, s);
    }
    float sum = 0.f;
#pragma unroll
    for (int j = 0; j < 64; j++) {
        float e = __expf(sc[i][j] - mx);
        sc[i][j] = e;
        sum += e;
    }
    float inv = 1.f / sum;

    float acc[32];
#pragma unroll
    for (int d = 0; d < 32; d++) acc[d] = 0.f;
#pragma unroll
    for (int j = 0; j < 64; j++) {
        float p = sc[i][j] * inv;
#pragma unroll
        for (int d = 0; d < 32; d++) acc[d] = fmaf(p, vs[j][d], acc[d]);
    }
#pragma unroll
    for (int d = 0; d < 32; d++) out[base + (i << 5) + d] = acc[d];
}

// ---------------- launch ----------------
extern "C" void kernel_launch(void* const* d_in, const int* in_sizes, int n_in,
                              void* d_out, int out_size) {
    const float* x      = (const float*)d_in[0];
    const float* w_iem  = (const float*)d_in[1];
    const float* g_iem  = (const float*)d_in[2];
    const float* b_iem  = (const float*)d_in[3];
    const float* w_nem  = (const float*)d_in[4];
    const float* g_nem  = (const float*)d_in[5];
    const float* b_nem  = (const float*)d_in[6];
    const float* w_idw  = (const float*)d_in[7];
    const float* w_ndw  = (const float*)d_in[8];
    const float* w_q    = (const float*)d_in[9];
    const float* w_k    = (const float*)d_in[10];
    const float* w_v    = (const float*)d_in[11];
    const float* w_proj = (const float*)d_in[12];
    const float* temp   = (const float*)d_in[13];
    float* out = (float*)d_out;

    float *A, *B, *C, *D, *WCT, *WT4, *BNA, *BNC, *IS, *NS;
    cudaGetSymbolAddress((void**)&A,   g_A);
    cudaGetSymbolAddress((void**)&B,   g_B);
    cudaGetSymbolAddress((void**)&C,   g_C);
    cudaGetSymbolAddress((void**)&D,   g_D);
    cudaGetSymbolAddress((void**)&WCT, g_wct);
    cudaGetSymbolAddress((void**)&WT4, g_wt4);
    cudaGetSymbolAddress((void**)&BNA, g_bna);
    cudaGetSymbolAddress((void**)&BNC, g_bnc);
    cudaGetSymbolAddress((void**)&IS,  g_is);
    cudaGetSymbolAddress((void**)&NS,  g_ns);

    tconv_kernel<<<4608, 256>>>(w_iem, w_nem, WCT);
    t1x1_kernel<<<1024, 256>>>(w_q, w_k, w_v, w_proj, WT4);

    dim3 cg(8, 32, 8);
    conv3_kernel<<<cg, 256>>>(x, WCT,          A);
    conv3_kernel<<<cg, 256>>>(x, WCT + 589824, B);

    bnstats_kernel<<<256, 256>>>(A, g_iem, b_iem, BNA,       BNC);
    bnstats_kernel<<<256, 256>>>(B, g_nem, b_nem, BNA + 256, BNC + 256);

    dwconv_kernel<<<131072, 256>>>(A, BNA,       BNC,       w_idw, C);
    dwconv_kernel<<<131072, 256>>>(B, BNA + 256, BNC + 256, w_ndw, D);

    chanmean_kernel<<<dim3(256, 2), 256>>>(C, D, IS, NS);

    dim3 gg(512, 4, 2);
    gemm1x1<0><<<gg, 128>>>(WT4,             C, A);   // q from illum map
    gemm1x1<0><<<gg, 128>>>(WT4 + 65536,     D, B);   // k from noise map
    gemm1x1<0><<<gg, 128>>>(WT4 + 2 * 65536, x, C);   // v from x

    attn_kernel<<<dim3(1024, 8, 2), 64>>>(A, B, C, IS, NS, temp, D);

    gemm1x1<3><<<gg, 128>>>(WT4 + 3 * 65536, D, out); // proj -> NCHW output
}

// round 3
// speedup vs baseline: 1.2151x; 1.2151x over previous
#include <cuda_runtime.h>
#include <math.h>

#define HW 65536
#define NBUF (2*256*HW)

// ---------------- static scratch ----------------
__device__ float g_A[NBUF];   // conv_iem raw -> q (window layout)
__device__ float g_B[NBUF];   // conv_nem raw -> k (window layout)
__device__ float g_C[NBUF];   // illum map -> v (window layout)
__device__ float g_D[NBUF];   // noise map -> attn out (window layout)
__device__ float g_wct[2*589824];  // conv weights transposed [m][c][tap][oc]
__device__ float g_wt4[4*65536];   // 1x1 weights transposed [m][c][oc]
__device__ float g_bna[512];
__device__ float g_bnc[512];
__device__ float g_is[2*HW];
__device__ float g_ns[2*HW];

// ---------------- packed f32x2 helpers ----------------
__device__ __forceinline__ void ffma2(unsigned long long& d, unsigned long long a,
                                      unsigned long long b) {
    asm("fma.rn.f32x2 %0, %1, %2, %0;" : "+l"(d) : "l"(a), "l"(b));
}
__device__ __forceinline__ unsigned long long pack2(float lo, float hi) {
    unsigned long long r;
    asm("mov.b64 %0, {%1, %2};" : "=l"(r) : "f"(lo), "f"(hi));
    return r;
}
__device__ __forceinline__ void unpack2(unsigned long long p, float& lo, float& hi) {
    asm("mov.b64 {%0, %1}, %2;" : "=f"(lo), "=f"(hi) : "l"(p));
}

// ---------------- weight transposes ----------------
__global__ void tconv_kernel(const float* __restrict__ w0, const float* __restrict__ w1,
                             float* __restrict__ out) {
    int i = blockIdx.x * 256 + threadIdx.x;          // 2*589824
    int m = i / 589824;
    int r = i - m * 589824;                          // (c*9+tap)*256 + o
    int o  = r & 255;
    int ct = r >> 8;
    int tap = ct % 9;
    int c   = ct / 9;
    const float* w = m ? w1 : w0;
    out[i] = w[o * 2304 + c * 9 + tap];
}

__global__ void t1x1_kernel(const float* __restrict__ wq, const float* __restrict__ wk,
                            const float* __restrict__ wv, const float* __restrict__ wp,
                            float* __restrict__ out) {
    int i = blockIdx.x * 256 + threadIdx.x;          // 4*65536
    int m = i >> 16;
    int r = i & 65535;
    int c = r >> 8;
    int o = r & 255;
    const float* w = (m == 0) ? wq : (m == 1) ? wk : (m == 2) ? wv : wp;
    out[i] = w[o * 256 + c];
}

// ---------------- 3x3 conv, direct, packed f32x2 ----------------
// tile: 64 oc x (32w x 8h), 256 threads, micro 8oc x 8px (4 oc-pairs)
__global__ void __launch_bounds__(256) conv3_kernel(const float* __restrict__ x,
                                                    const float* __restrict__ wt,
                                                    float* __restrict__ out) {
    __shared__ __align__(16) float xs[8][10][36];
    __shared__ __align__(16) float ws[8][9][64];
    const int tid = threadIdx.x;
    const int b   = blockIdx.z >> 2;
    const int oc0 = (blockIdx.z & 3) * 64;
    const int x0  = blockIdx.x * 32;
    const int y0  = blockIdx.y * 8;
    const int ocg = tid & 7;
    const int pxg = tid >> 3;
    const int row  = pxg >> 2;
    const int col8 = (pxg & 3) * 8;
    const int ocl  = ocg * 8;

    unsigned long long acc2[4][8];   // [oc-pair][pixel]
#pragma unroll
    for (int op = 0; op < 4; op++)
#pragma unroll
        for (int j = 0; j < 8; j++) acc2[op][j] = 0ULL;

    for (int chunk = 0; chunk < 32; chunk++) {
        const int c0 = chunk * 8;
        for (int i = tid; i < 2720; i += 256) {       // 8ch x 10 x 34
            int c  = i / 340;
            int rr = (i % 340) / 34;
            int cl = i % 34;
            int gy = y0 + rr - 1;
            int gx = x0 + cl - 1;
            float v = 0.f;
            if ((unsigned)gy < 256u && (unsigned)gx < 256u)
                v = x[(((size_t)((b << 8) + c0 + c)) << 16) + (gy << 8) + gx];
            xs[c][rr][cl] = v;
        }
        for (int i = tid; i < 4608; i += 256) {       // 8ch x 9 taps x 64 oc
            int c   = i / 576;
            int rem = i - c * 576;
            int tap = rem >> 6;
            int o   = rem & 63;
            ws[c][tap][o] = wt[((c0 + c) * 9 + tap) * 256 + oc0 + o];
        }
        __syncthreads();

#pragma unroll
        for (int c = 0; c < 8; c++) {
#pragma unroll
            for (int ky = 0; ky < 3; ky++) {
                float4 a4 = *(const float4*)&xs[c][row + ky][col8];
                float4 b4 = *(const float4*)&xs[c][row + ky][col8 + 4];
                float f8 = xs[c][row + ky][col8 + 8];
                float f9 = xs[c][row + ky][col8 + 9];
                unsigned long long xb[10];
                xb[0] = pack2(a4.x, a4.x); xb[1] = pack2(a4.y, a4.y);
                xb[2] = pack2(a4.z, a4.z); xb[3] = pack2(a4.w, a4.w);
                xb[4] = pack2(b4.x, b4.x); xb[5] = pack2(b4.y, b4.y);
                xb[6] = pack2(b4.z, b4.z); xb[7] = pack2(b4.w, b4.w);
                xb[8] = pack2(f8, f8);     xb[9] = pack2(f9, f9);
#pragma unroll
                for (int kx = 0; kx < 3; kx++) {
                    const int tap = ky * 3 + kx;
                    ulonglong2 wA = *(const ulonglong2*)&ws[c][tap][ocl];
                    ulonglong2 wB = *(const ulonglong2*)&ws[c][tap][ocl + 4];
#pragma unroll
                    for (int j = 0; j < 8; j++) {
                        ffma2(acc2[0][j], wA.x, xb[kx + j]);
                        ffma2(acc2[1][j], wA.y, xb[kx + j]);
                        ffma2(acc2[2][j], wB.x, xb[kx + j]);
                        ffma2(acc2[3][j], wB.y, xb[kx + j]);
                    }
                }
            }
        }
        __syncthreads();
    }

    float acc[8][8];
#pragma unroll
    for (int op = 0; op < 4; op++)
#pragma unroll
        for (int j = 0; j < 8; j++)
            unpack2(acc2[op][j], acc[2 * op][j], acc[2 * op + 1][j]);

#pragma unroll
    for (int o = 0; o < 8; o++) {
        int oc = oc0 + ocl + o;
        size_t obase = (((size_t)(b * 256 + oc)) << 16) + ((y0 + row) << 8) + x0 + col8;
        float4 s0 = {acc[o][0], acc[o][1], acc[o][2], acc[o][3]};
        float4 s1 = {acc[o][4], acc[o][5], acc[o][6], acc[o][7]};
        *(float4*)&out[obase]     = s0;
        *(float4*)&out[obase + 4] = s1;
    }
}

// ---------------- BN stats (training mode, per channel over B,H,W) ----------------
__global__ void bnstats_kernel(const float* __restrict__ conv,
                               const float* __restrict__ gamma,
                               const float* __restrict__ beta,
                               float* __restrict__ pa, float* __restrict__ pc) {
    const int ch = blockIdx.x;
    const int tid = threadIdx.x;
    const float* p0 = conv + ((size_t)ch << 16);
    const float* p1 = conv + ((size_t)(256 + ch) << 16);
    float s = 0.f, s2 = 0.f;
    for (int k = tid; k < 65536; k += 256) {
        float v = p0[k]; s += v; s2 += v * v;
        v = p1[k]; s += v; s2 += v * v;
    }
    __shared__ float ss[256], ss2[256];
    ss[tid] = s; ss2[tid] = s2;
    __syncthreads();
    for (int st = 128; st > 0; st >>= 1) {
        if (tid < st) { ss[tid] += ss[tid + st]; ss2[tid] += ss2[tid + st]; }
        __syncthreads();
    }
    if (tid == 0) {
        float m   = ss[0]  * (1.f / 131072.f);
        float var = ss2[0] * (1.f / 131072.f) - m * m;
        float a = gamma[ch] * rsqrtf(var + 1e-5f);
        pa[ch] = a;
        pc[ch] = beta[ch] - m * a;
    }
}

// ---------------- depthwise conv (BN affine + relu6 fused on input) ----------------
__global__ void dwconv_kernel(const float* __restrict__ conv,
                              const float* __restrict__ pa, const float* __restrict__ pc,
                              const float* __restrict__ wdw, float* __restrict__ out) {
    int gi = blockIdx.x * 256 + threadIdx.x;   // (b*256+ch)*65536 + p
    int p  = gi & 65535;
    int bc = gi >> 16;
    int ch = bc & 255;
    int y  = p >> 8, xx = p & 255;
    float a = pa[ch], c = pc[ch];
    float w[9];
#pragma unroll
    for (int t = 0; t < 9; t++) w[t] = wdw[ch * 9 + t];
    const float* src = conv + ((size_t)bc << 16);
    float acc = 0.f;
#pragma unroll
    for (int ky = 0; ky < 3; ky++) {
        int yy = y + ky - 1;
        if ((unsigned)yy >= 256u) continue;
#pragma unroll
        for (int kx = 0; kx < 3; kx++) {
            int xv = xx + kx - 1;
            if ((unsigned)xv >= 256u) continue;
            float t = src[(yy << 8) + xv];
            t = t * a + c;
            t = fminf(fmaxf(t, 0.f), 6.f);
            acc = fmaf(w[ky * 3 + kx], t, acc);
        }
    }
    out[gi] = acc;
}

// ---------------- per-pixel channel mean of both maps ----------------
__global__ void chanmean_kernel(const float* __restrict__ il, const float* __restrict__ nm,
                                float* __restrict__ is, float* __restrict__ ns) {
    int p = blockIdx.x * 256 + threadIdx.x;
    int b = blockIdx.y;
    float s1 = 0.f, s2 = 0.f;
    for (int c = 0; c < 256; c++) {
        size_t idx = (((size_t)(b * 256 + c)) << 16) + p;
        s1 += il[idx];
        s2 += nm[idx];
    }
    is[(b << 16) + p] = s1 * (1.f / 256.f);
    ns[(b << 16) + p] = s2 * (1.f / 256.f);
}

// ---------------- 1x1 channel GEMM (packed f32x2) ----------------
// MODE 0: NCHW in -> window layout out [b,h,win,64,32]
// MODE 3: window-gather in -> NCHW out
template <int MODE>
__global__ void __launch_bounds__(128) gemm1x1(const float* __restrict__ wt,
                                               const float* __restrict__ in,
                                               float* __restrict__ out) {
    __shared__ __align__(16) float sIn[16][128];
    __shared__ __align__(16) float sW[16][64];
    const int tid = threadIdx.x;
    const int b   = blockIdx.z;
    const int oc0 = blockIdx.y * 64;
    const int pxbase = blockIdx.x * 128;
    const int ocg = tid & 7, pxg = tid >> 3;
    const int ocl = ocg * 8, pxl = pxg * 8;

    unsigned long long acc2[4][8];
#pragma unroll
    for (int op = 0; op < 4; op++)
#pragma unroll
        for (int j = 0; j < 8; j++) acc2[op][j] = 0ULL;

    for (int ch = 0; ch < 16; ch++) {
        const int c0 = ch * 16;
#pragma unroll
        for (int k = 0; k < 8; k++) {
            int idx = k * 128 + tid;
            int c = idx >> 6, o = idx & 63;
            sW[c][o] = wt[(c0 + c) * 256 + oc0 + o];
        }
        if (MODE < 3) {
#pragma unroll
            for (int k = 0; k < 16; k++) {
                int idx = k * 128 + tid;
                int c = idx >> 7, pxi = idx & 127;
                sIn[c][pxi] = in[(((size_t)((b << 8) + c0 + c)) << 16) + pxbase + pxi];
            }
        } else {
            int c = c0 + (tid & 15);
            int h = c >> 5, dd = c & 31;
            size_t hb = ((size_t)(b * 8 + h)) << 21;
#pragma unroll
            for (int k = 0; k < 16; k++) {
                int pxi = (tid >> 4) + k * 8;
                int p = pxbase + pxi;
                int y = p >> 8, xx = p & 255;
                int win = ((y >> 3) << 5) + (xx >> 3);
                int pix = ((y & 7) << 3) + (xx & 7);
                sIn[c - c0][pxi] = in[hb + ((size_t)win << 11) + (pix << 5) + dd];
            }
        }
        __syncthreads();
#pragma unroll
        for (int c = 0; c < 16; c++) {
            ulonglong2 wA = *(const ulonglong2*)&sW[c][ocl];
            ulonglong2 wB = *(const ulonglong2*)&sW[c][ocl + 4];
            float4 x0 = *(const float4*)&sIn[c][pxl];
            float4 x1 = *(const float4*)&sIn[c][pxl + 4];
            unsigned long long xb[8];
            xb[0] = pack2(x0.x, x0.x); xb[1] = pack2(x0.y, x0.y);
            xb[2] = pack2(x0.z, x0.z); xb[3] = pack2(x0.w, x0.w);
            xb[4] = pack2(x1.x, x1.x); xb[5] = pack2(x1.y, x1.y);
            xb[6] = pack2(x1.z, x1.z); xb[7] = pack2(x1.w, x1.w);
#pragma unroll
            for (int j = 0; j < 8; j++) {
                ffma2(acc2[0][j], wA.x, xb[j]);
                ffma2(acc2[1][j], wA.y, xb[j]);
                ffma2(acc2[2][j], wB.x, xb[j]);
                ffma2(acc2[3][j], wB.y, xb[j]);
            }
        }
        __syncthreads();
    }

    float acc[8][8];
#pragma unroll
    for (int op = 0; op < 4; op++)
#pragma unroll
        for (int j = 0; j < 8; j++)
            unpack2(acc2[op][j], acc[2 * op][j], acc[2 * op + 1][j]);

    if (MODE < 3) {
        int pwin[8], ppix[8];
#pragma unroll
        for (int j = 0; j < 8; j++) {
            int p = pxbase + pxl + j;
            int y = p >> 8, xx = p & 255;
            pwin[j] = ((y >> 3) << 5) + (xx >> 3);
            ppix[j] = ((y & 7) << 3) + (xx & 7);
        }
#pragma unroll
        for (int o = 0; o < 8; o++) {
            int oc = oc0 + ocl + o;
            int h = oc >> 5, dd = oc & 31;
            size_t basep = (((size_t)(b * 8 + h)) << 21) + dd;
#pragma unroll
            for (int j = 0; j < 8; j++)
                out[basep + ((size_t)pwin[j] << 11) + (ppix[j] << 5)] = acc[o][j];
        }
    } else {
#pragma unroll
        for (int o = 0; o < 8; o++) {
            int oc = oc0 + ocl + o;
            size_t basep = (((size_t)(b * 256 + oc)) << 16) + pxbase + pxl;
            float4 s0 = {acc[o][0], acc[o][1], acc[o][2], acc[o][3]};
            float4 s1 = {acc[o][4], acc[o][5], acc[o][6], acc[o][7]};
            *(float4*)&out[basep]     = s0;
            *(float4*)&out[basep + 4] = s1;
        }
    }
}

// ---------------- windowed attention ----------------
// one block per (b, head, window); 64 threads, thread i = query row i
__global__ void __launch_bounds__(64) attn_kernel(const float* __restrict__ q,
                                                  const float* __restrict__ k,
                                                  const float* __restrict__ v,
                                                  const float* __restrict__ is,
                                                  const float* __restrict__ ns,
                                                  const float* __restrict__ temp,
                                                  float* __restrict__ out) {
    __shared__ float ks[64][32];
    __shared__ float vs[64][32];
    __shared__ float sc[64][66];
    const int i   = threadIdx.x;
    const int win = blockIdx.x;
    const int h   = blockIdx.y;
    const int b   = blockIdx.z;
    const size_t base = (((size_t)(b * 8 + h)) << 21) + ((size_t)win << 11);

    const int y = ((win >> 5) << 3) + (i >> 3);
    const int x = ((win & 31) << 3) + (i & 7);
    const int pidx = (b << 16) + (y << 8) + x;

    float kr[32];
    float kn = 0.f;
#pragma unroll
    for (int d = 0; d < 32; d++) {
        kr[d] = k[base + (i << 5) + d];
        kn = fmaf(kr[d], kr[d], kn);
        vs[i][d] = v[base + (i << 5) + d];
    }
    float nsv = ns[pidx];
    float kmul = fminf(fmaxf(1.f - nsv, 0.f), 1.f) / fmaxf(sqrtf(kn), 1e-12f);
#pragma unroll
    for (int d = 0; d < 32; d++) ks[i][d] = kr[d] * kmul;

    float qr[32];
    float qn = 0.f;
#pragma unroll
    for (int d = 0; d < 32; d++) {
        qr[d] = q[base + (i << 5) + d];
        qn = fmaf(qr[d], qr[d], qn);
    }
    float qmul = (1.f + is[pidx]) / fmaxf(sqrtf(qn), 1e-12f)
               * 0.17677669529663687f * temp[h];
#pragma unroll
    for (int d = 0; d < 32; d++) qr[d] *= qmul;

    __syncthreads();

    float mx = -1e30f;
#pragma unroll
    for (int j = 0; j < 64; j++) {
        float s = 0.f;
#pragma unroll
        for (int d = 0; d < 32; d++) s = fmaf(qr[d], ks[j][d], s);
        sc[i][j] = s;
        mx = fmaxf(mx, s);
    }
    float sum = 0.f;
#pragma unroll
    for (int j = 0; j < 64; j++) {
        float e = __expf(sc[i][j] - mx);
        sc[i][j] = e;
        sum += e;
    }
    float inv = 1.f / sum;

    float acc[32];
#pragma unroll
    for (int d = 0; d < 32; d++) acc[d] = 0.f;
#pragma unroll
    for (int j = 0; j < 64; j++) {
        float p = sc[i][j] * inv;
#pragma unroll
        for (int d = 0; d < 32; d++) acc[d] = fmaf(p, vs[j][d], acc[d]);
    }
#pragma unroll
    for (int d = 0; d < 32; d++) out[base + (i << 5) + d] = acc[d];
}

// ---------------- launch ----------------
extern "C" void kernel_launch(void* const* d_in, const int* in_sizes, int n_in,
                              void* d_out, int out_size) {
    const float* x      = (const float*)d_in[0];
    const float* w_iem  = (const float*)d_in[1];
    const float* g_iem  = (const float*)d_in[2];
    const float* b_iem  = (const float*)d_in[3];
    const float* w_nem  = (const float*)d_in[4];
    const float* g_nem  = (const float*)d_in[5];
    const float* b_nem  = (const float*)d_in[6];
    const float* w_idw  = (const float*)d_in[7];
    const float* w_ndw  = (const float*)d_in[8];
    const float* w_q    = (const float*)d_in[9];
    const float* w_k    = (const float*)d_in[10];
    const float* w_v    = (const float*)d_in[11];
    const float* w_proj = (const float*)d_in[12];
    const float* temp   = (const float*)d_in[13];
    float* out = (float*)d_out;

    float *A, *B, *C, *D, *WCT, *WT4, *BNA, *BNC, *IS, *NS;
    cudaGetSymbolAddress((void**)&A,   g_A);
    cudaGetSymbolAddress((void**)&B,   g_B);
    cudaGetSymbolAddress((void**)&C,   g_C);
    cudaGetSymbolAddress((void**)&D,   g_D);
    cudaGetSymbolAddress((void**)&WCT, g_wct);
    cudaGetSymbolAddress((void**)&WT4, g_wt4);
    cudaGetSymbolAddress((void**)&BNA, g_bna);
    cudaGetSymbolAddress((void**)&BNC, g_bnc);
    cudaGetSymbolAddress((void**)&IS,  g_is);
    cudaGetSymbolAddress((void**)&NS,  g_ns);

    tconv_kernel<<<4608, 256>>>(w_iem, w_nem, WCT);
    t1x1_kernel<<<1024, 256>>>(w_q, w_k, w_v, w_proj, WT4);

    dim3 cg(8, 32, 8);
    conv3_kernel<<<cg, 256>>>(x, WCT,          A);
    conv3_kernel<<<cg, 256>>>(x, WCT + 589824, B);

    bnstats_kernel<<<256, 256>>>(A, g_iem, b_iem, BNA,       BNC);
    bnstats_kernel<<<256, 256>>>(B, g_nem, b_nem, BNA + 256, BNC + 256);

    dwconv_kernel<<<131072, 256>>>(A, BNA,       BNC,       w_idw, C);
    dwconv_kernel<<<131072, 256>>>(B, BNA + 256, BNC + 256, w_ndw, D);

    chanmean_kernel<<<dim3(256, 2), 256>>>(C, D, IS, NS);

    dim3 gg(512, 4, 2);
    gemm1x1<0><<<gg, 128>>>(WT4,             C, A);   // q from illum map
    gemm1x1<0><<<gg, 128>>>(WT4 + 65536,     D, B);   // k from noise map
    gemm1x1<0><<<gg, 128>>>(WT4 + 2 * 65536, x, C);   // v from x

    attn_kernel<<<dim3(1024, 8, 2), 64>>>(A, B, C, IS, NS, temp, D);

    gemm1x1<3><<<gg, 128>>>(WT4 + 3 * 65536, D, out); // proj -> NCHW output
}

// round 5
// speedup vs baseline: 2.2524x; 1.8536x over previous
#include <cuda_runtime.h>
#include <math.h>
#include <stdint.h>

#define HW 65536
#define NBUF (2*256*HW)

// ---------------- static scratch ----------------
__device__ float g_A[NBUF];   // conv_iem raw -> q (window layout)
__device__ float g_B[NBUF];   // conv_nem raw -> k (window layout)
__device__ float g_C[NBUF];   // illum map -> v (window layout)
__device__ float g_D[NBUF];   // noise map -> attn out (window layout)
__device__ float g_X[NBUF];   // x transposed [b][px][c], tf32-rounded
__device__ float g_wct[2*589824];  // conv weights [m][tap][c][oc], tf32-rounded
__device__ float g_wt4[4*65536];   // 1x1 weights transposed [m][c][oc]
__device__ float g_bna[512];
__device__ float g_bnc[512];
__device__ float g_is[2*HW];
__device__ float g_ns[2*HW];

// ---------------- helpers ----------------
__device__ __forceinline__ void ffma2(unsigned long long& d, unsigned long long a,
                                      unsigned long long b) {
    asm("fma.rn.f32x2 %0, %1, %2, %0;" : "+l"(d) : "l"(a), "l"(b));
}
__device__ __forceinline__ unsigned long long pack2(float lo, float hi) {
    unsigned long long r;
    asm("mov.b64 %0, {%1, %2};" : "=l"(r) : "f"(lo), "f"(hi));
    return r;
}
__device__ __forceinline__ void unpack2(unsigned long long p, float& lo, float& hi) {
    asm("mov.b64 {%0, %1}, %2;" : "=f"(lo), "=f"(hi) : "l"(p));
}
__device__ __forceinline__ float to_tf32(float f) {
    float r;
    asm("cvt.rna.tf32.f32 %0, %1;" : "=f"(r) : "f"(f));
    return r;
}
__device__ __forceinline__ uint32_t smem_u32(const void* p) {
    uint32_t a;
    asm("{ .reg .u64 t; cvta.to.shared.u64 t, %1; cvt.u32.u64 %0, t; }" : "=r"(a) : "l"(p));
    return a;
}
__device__ __forceinline__ void cpa16(uint32_t s, const float* g, uint32_t n) {
    asm volatile("cp.async.cg.shared.global [%0], [%1], 16, %2;"
                 :: "r"(s), "l"(g), "r"(n) : "memory");
}
#define CP_COMMIT()  asm volatile("cp.async.commit_group;" ::: "memory")
#define CP_WAIT0()   asm volatile("cp.async.wait_group 0;" ::: "memory")

// tf32 m16n8k8 mma (family-portable HMMA path; NO tcgen05 — ptxas target is compute_103)
__device__ __forceinline__ void mma8(float* d, const uint32_t* a, const uint32_t* b) {
    asm volatile("mma.sync.aligned.m16n8k8.row.col.f32.tf32.tf32.f32 "
        "{%0,%1,%2,%3}, {%4,%5,%6,%7}, {%8,%9}, {%0,%1,%2,%3};"
        : "+f"(d[0]), "+f"(d[1]), "+f"(d[2]), "+f"(d[3])
        : "r"(a[0]), "r"(a[1]), "r"(a[2]), "r"(a[3]), "r"(b[0]), "r"(b[1]));
}

// ---------------- weight prep: [m][tap][c][oc], tf32-rounded ----------------
__global__ void tconv_kernel(const float* __restrict__ w0, const float* __restrict__ w1,
                             float* __restrict__ out) {
    int i = blockIdx.x * 256 + threadIdx.x;          // 2*589824
    int m = i / 589824;
    int r = i - m * 589824;
    int tap = r >> 16;
    int rem = r & 65535;
    int c   = rem >> 8;
    int oc  = rem & 255;
    const float* w = m ? w1 : w0;
    out[i] = to_tf32(w[oc * 2304 + c * 9 + tap]);
}

__global__ void t1x1_kernel(const float* __restrict__ wq, const float* __restrict__ wk,
                            const float* __restrict__ wv, const float* __restrict__ wp,
                            float* __restrict__ out) {
    int i = blockIdx.x * 256 + threadIdx.x;          // 4*65536
    int m = i >> 16;
    int r = i & 65535;
    int c = r >> 8;
    int o = r & 255;
    const float* w = (m == 0) ? wq : (m == 1) ? wk : (m == 2) ? wv : wp;
    out[i] = w[o * 256 + c];
}

// ---------------- x transpose: NCHW -> [b][px][c], tf32-rounded ----------------
__global__ void xT_kernel(const float* __restrict__ x, float* __restrict__ xT) {
    __shared__ float t[32][33];
    int b  = blockIdx.z;
    int c0 = blockIdx.y * 32;
    int p0 = blockIdx.x * 32;
    int tx = threadIdx.x, ty = threadIdx.y;
    t[ty][tx] = to_tf32(x[(((size_t)((b << 8) + c0 + ty)) << 16) + p0 + tx]);
    __syncthreads();
    xT[(((size_t)((b << 16) + p0 + ty)) << 8) + c0 + tx] = t[tx][ty];
}

// ---------------- 3x3 conv as implicit GEMM on mma.sync tf32 ----------------
// CTA: 128 px (half row) x 128 oc. 8 warps = 2(M px) x 4(N oc); warp 64px x 32oc.
// K loop: 8 c-chunks x 3 ky; kx handled by smem row offset in the x slab.
__global__ void __launch_bounds__(256, 2) conv_mma(const float* __restrict__ xT,
                                                   const float* __restrict__ W2,
                                                   float* __restrict__ out) {
    extern __shared__ float sm[];
    float* Xs = sm;                 // [130][36]  (c chunk of 32 + pad 4)
    float* Ws = sm + 130 * 36;      // [3 kx][32 c][136] (oc 128 + pad 8)
    const int tid  = threadIdx.x;
    const int w    = tid >> 5, lane = tid & 31;
    const int g    = lane >> 2, tg = lane & 3;
    const int y    = blockIdx.x >> 1;
    const int p0   = (blockIdx.x & 1) << 7;
    const int oc0  = blockIdx.y << 7;
    const int b    = blockIdx.z;
    const int wm   = w >> 2, wn = w & 3;
    const uint32_t xs_u = smem_u32(Xs);
    const uint32_t ws_u = smem_u32(Ws);

    float acc[4][4][4];
#pragma unroll
    for (int mi = 0; mi < 4; mi++)
#pragma unroll
        for (int ni = 0; ni < 4; ni++)
#pragma unroll
            for (int r = 0; r < 4; r++) acc[mi][ni][r] = 0.f;

    for (int cc = 0; cc < 8; cc++) {
        const int c0 = cc * 32;
        for (int ky = 0; ky < 3; ky++) {
            __syncthreads();
            const int yin = y + ky - 1;
            const bool yok = (unsigned)yin < 256u;
            // x slab: 130 rows (xin = p0-1 .. p0+128) x 32 ch
#pragma unroll
            for (int jj = 0; jj < 5; jj++) {
                int j = jj * 256 + tid;
                if (j < 1040) {
                    int r = j >> 3, q = j & 7;
                    int xin = p0 + r - 1;
                    bool ok = yok && ((unsigned)xin < 256u);
                    const float* src = ok
                        ? xT + ((((size_t)b << 16) + ((size_t)yin << 8) + xin) << 8) + c0 + q * 4
                        : xT;
                    cpa16(xs_u + r * 144 + q * 16, src, ok ? 16u : 0u);
                }
            }
            // weights: 3 kx taps x [32 c][128 oc]
#pragma unroll
            for (int jj = 0; jj < 12; jj++) {
                int j = jj * 256 + tid;
                int kx = j >> 10, rem = j & 1023;
                int c = rem >> 5, q = rem & 31;
                int tap = ky * 3 + kx;
                cpa16(ws_u + (kx * 32 + c) * 544 + q * 16,
                      W2 + ((size_t)(tap * 256 + c0 + c) << 8) + oc0 + q * 4, 16u);
            }
            CP_COMMIT(); CP_WAIT0();
            __syncthreads();

#pragma unroll
            for (int kx = 0; kx < 3; kx++) {
#pragma unroll
                for (int ks = 0; ks < 4; ks++) {
                    const int col = ks * 8 + tg;
                    uint32_t af[4][4];
#pragma unroll
                    for (int mi = 0; mi < 4; mi++) {
                        int r0 = (wm * 64 + mi * 16 + g + kx) * 36 + col;
                        af[mi][0] = __float_as_uint(Xs[r0]);
                        af[mi][1] = __float_as_uint(Xs[r0 + 8 * 36]);
                        af[mi][2] = __float_as_uint(Xs[r0 + 4]);
                        af[mi][3] = __float_as_uint(Xs[r0 + 8 * 36 + 4]);
                    }
                    uint32_t bf[4][2];
#pragma unroll
                    for (int ni = 0; ni < 4; ni++) {
                        int nbase = wn * 32 + ni * 8 + g;
                        int rb = (kx * 32 + col) * 136 + nbase;
                        bf[ni][0] = __float_as_uint(Ws[rb]);
                        bf[ni][1] = __float_as_uint(Ws[rb + 4 * 136]);
                    }
#pragma unroll
                    for (int mi = 0; mi < 4; mi++)
#pragma unroll
                        for (int ni = 0; ni < 4; ni++)
                            mma8(acc[mi][ni], af[mi], bf[ni]);
                }
            }
        }
    }

    // epilogue: regs -> smem [128 oc][132] -> coalesced NCHW
    __syncthreads();
    float* S = sm;
#pragma unroll
    for (int mi = 0; mi < 4; mi++) {
        int px = wm * 64 + mi * 16 + g;
#pragma unroll
        for (int ni = 0; ni < 4; ni++) {
            int oc = wn * 32 + ni * 8 + 2 * tg;
            S[oc * 132 + px]           = acc[mi][ni][0];
            S[(oc + 1) * 132 + px]     = acc[mi][ni][1];
            S[oc * 132 + px + 8]       = acc[mi][ni][2];
            S[(oc + 1) * 132 + px + 8] = acc[mi][ni][3];
        }
    }
    __syncthreads();
#pragma unroll
    for (int it = 0; it < 16; it++) {
        int row = w + it * 8;
        float4 v = *(float4*)&S[row * 132 + lane * 4];
        *(float4*)&out[(((size_t)(b * 256 + oc0 + row)) << 16) + (y << 8) + p0 + lane * 4] = v;
    }
}

// ---------------- BN stats ----------------
__global__ void bnstats_kernel(const float* __restrict__ conv,
                               const float* __restrict__ gamma,
                               const float* __restrict__ beta,
                               float* __restrict__ pa, float* __restrict__ pc) {
    const int ch = blockIdx.x;
    const int tid = threadIdx.x;
    const float* p0 = conv + ((size_t)ch << 16);
    const float* p1 = conv + ((size_t)(256 + ch) << 16);
    float s = 0.f, s2 = 0.f;
    for (int k = tid; k < 65536; k += 256) {
        float v = p0[k]; s += v; s2 += v * v;
        v = p1[k]; s += v; s2 += v * v;
    }
    __shared__ float ss[256], ss2[256];
    ss[tid] = s; ss2[tid] = s2;
    __syncthreads();
    for (int st = 128; st > 0; st >>= 1) {
        if (tid < st) { ss[tid] += ss[tid + st]; ss2[tid] += ss2[tid + st]; }
        __syncthreads();
    }
    if (tid == 0) {
        float m   = ss[0]  * (1.f / 131072.f);
        float var = ss2[0] * (1.f / 131072.f) - m * m;
        float a = gamma[ch] * rsqrtf(var + 1e-5f);
        pa[ch] = a;
        pc[ch] = beta[ch] - m * a;
    }
}

// ---------------- depthwise conv (BN affine + relu6 fused) ----------------
__global__ void dwconv_kernel(const float* __restrict__ conv,
                              const float* __restrict__ pa, const float* __restrict__ pc,
                              const float* __restrict__ wdw, float* __restrict__ out) {
    int gi = blockIdx.x * 256 + threadIdx.x;
    int p  = gi & 65535;
    int bc = gi >> 16;
    int ch = bc & 255;
    int y  = p >> 8, xx = p & 255;
    float a = pa[ch], c = pc[ch];
    float w[9];
#pragma unroll
    for (int t = 0; t < 9; t++) w[t] = wdw[ch * 9 + t];
    const float* src = conv + ((size_t)bc << 16);
    float acc = 0.f;
#pragma unroll
    for (int ky = 0; ky < 3; ky++) {
        int yy = y + ky - 1;
        if ((unsigned)yy >= 256u) continue;
#pragma unroll
        for (int kx = 0; kx < 3; kx++) {
            int xv = xx + kx - 1;
            if ((unsigned)xv >= 256u) continue;
            float t = src[(yy << 8) + xv];
            t = t * a + c;
            t = fminf(fmaxf(t, 0.f), 6.f);
            acc = fmaf(w[ky * 3 + kx], t, acc);
        }
    }
    out[gi] = acc;
}

// ---------------- per-pixel channel mean ----------------
__global__ void chanmean_kernel(const float* __restrict__ il, const float* __restrict__ nm,
                                float* __restrict__ is, float* __restrict__ ns) {
    int p = blockIdx.x * 256 + threadIdx.x;
    int b = blockIdx.y;
    float s1 = 0.f, s2 = 0.f;
    for (int c = 0; c < 256; c++) {
        size_t idx = (((size_t)(b * 256 + c)) << 16) + p;
        s1 += il[idx];
        s2 += nm[idx];
    }
    is[(b << 16) + p] = s1 * (1.f / 256.f);
    ns[(b << 16) + p] = s2 * (1.f / 256.f);
}

// ---------------- 1x1 channel GEMM (packed f32x2) ----------------
template <int MODE>
__global__ void __launch_bounds__(128) gemm1x1(const float* __restrict__ wt,
                                               const float* __restrict__ in,
                                               float* __restrict__ out) {
    __shared__ __align__(16) float sIn[16][128];
    __shared__ __align__(16) float sW[16][64];
    const int tid = threadIdx.x;
    const int b   = blockIdx.z;
    const int oc0 = blockIdx.y * 64;
    const int pxbase = blockIdx.x * 128;
    const int ocg = tid & 7, pxg = tid >> 3;
    const int ocl = ocg * 8, pxl = pxg * 8;

    unsigned long long acc2[4][8];
#pragma unroll
    for (int op = 0; op < 4; op++)
#pragma unroll
        for (int j = 0; j < 8; j++) acc2[op][j] = 0ULL;

    for (int ch = 0; ch < 16; ch++) {
        const int c0 = ch * 16;
#pragma unroll
        for (int k = 0; k < 8; k++) {
            int idx = k * 128 + tid;
            int c = idx >> 6, o = idx & 63;
            sW[c][o] = wt[(c0 + c) * 256 + oc0 + o];
        }
        if (MODE < 3) {
#pragma unroll
            for (int k = 0; k < 16; k++) {
                int idx = k * 128 + tid;
                int c = idx >> 7, pxi = idx & 127;
                sIn[c][pxi] = in[(((size_t)((b << 8) + c0 + c)) << 16) + pxbase + pxi];
            }
        } else {
            int c = c0 + (tid & 15);
            int h = c >> 5, dd = c & 31;
            size_t hb = ((size_t)(b * 8 + h)) << 21;
#pragma unroll
            for (int k = 0; k < 16; k++) {
                int pxi = (tid >> 4) + k * 8;
                int p = pxbase + pxi;
                int y = p >> 8, xx = p & 255;
                int win = ((y >> 3) << 5) + (xx >> 3);
                int pix = ((y & 7) << 3) + (xx & 7);
                sIn[c - c0][pxi] = in[hb + ((size_t)win << 11) + (pix << 5) + dd];
            }
        }
        __syncthreads();
#pragma unroll
        for (int c = 0; c < 16; c++) {
            ulonglong2 wA = *(const ulonglong2*)&sW[c][ocl];
            ulonglong2 wB = *(const ulonglong2*)&sW[c][ocl + 4];
            float4 x0 = *(const float4*)&sIn[c][pxl];
            float4 x1 = *(const float4*)&sIn[c][pxl + 4];
            unsigned long long xb[8];
            xb[0] = pack2(x0.x, x0.x); xb[1] = pack2(x0.y, x0.y);
            xb[2] = pack2(x0.z, x0.z); xb[3] = pack2(x0.w, x0.w);
            xb[4] = pack2(x1.x, x1.x); xb[5] = pack2(x1.y, x1.y);
            xb[6] = pack2(x1.z, x1.z); xb[7] = pack2(x1.w, x1.w);
#pragma unroll
            for (int j = 0; j < 8; j++) {
                ffma2(acc2[0][j], wA.x, xb[j]);
                ffma2(acc2[1][j], wA.y, xb[j]);
                ffma2(acc2[2][j], wB.x, xb[j]);
                ffma2(acc2[3][j], wB.y, xb[j]);
            }
        }
        __syncthreads();
    }

    float acc[8][8];
#pragma unroll
    for (int op = 0; op < 4; op++)
#pragma unroll
        for (int j = 0; j < 8; j++)
            unpack2(acc2[op][j], acc[2 * op][j], acc[2 * op + 1][j]);

    if (MODE < 3) {
        int pwin[8], ppix[8];
#pragma unroll
        for (int j = 0; j < 8; j++) {
            int p = pxbase + pxl + j;
            int y = p >> 8, xx = p & 255;
            pwin[j] = ((y >> 3) << 5) + (xx >> 3);
            ppix[j] = ((y & 7) << 3) + (xx & 7);
        }
#pragma unroll
        for (int o = 0; o < 8; o++) {
            int oc = oc0 + ocl + o;
            int h = oc >> 5, dd = oc & 31;
            size_t basep = (((size_t)(b * 8 + h)) << 21) + dd;
#pragma unroll
            for (int j = 0; j < 8; j++)
                out[basep + ((size_t)pwin[j] << 11) + (ppix[j] << 5)] = acc[o][j];
        }
    } else {
#pragma unroll
        for (int o = 0; o < 8; o++) {
            int oc = oc0 + ocl + o;
            size_t basep = (((size_t)(b * 256 + oc)) << 16) + pxbase + pxl;
            float4 s0 = {acc[o][0], acc[o][1], acc[o][2], acc[o][3]};
            float4 s1 = {acc[o][4], acc[o][5], acc[o][6], acc[o][7]};
            *(float4*)&out[basep]     = s0;
            *(float4*)&out[basep + 4] = s1;
        }
    }
}

// ---------------- windowed attention ----------------
__global__ void __launch_bounds__(64) attn_kernel(const float* __restrict__ q,
                                                  const float* __restrict__ k,
                                                  const float* __restrict__ v,
                                                  const float* __restrict__ is,
                                                  const float* __restrict__ ns,
                                                  const float* __restrict__ temp,
                                                  float* __restrict__ out) {
    __shared__ float ks[64][32];
    __shared__ float vs[64][32];
    __shared__ float sc[64][66];
    const int i   = threadIdx.x;
    const int win = blockIdx.x;
    const int h   = blockIdx.y;
    const int b   = blockIdx.z;
    const size_t base = (((size_t)(b * 8 + h)) << 21) + ((size_t)win << 11);

    const int y = ((win >> 5) << 3) + (i >> 3);
    const int x = ((win & 31) << 3) + (i & 7);
    const int pidx = (b << 16) + (y << 8) + x;

    float kr[32];
    float kn = 0.f;
#pragma unroll
    for (int d = 0; d < 32; d++) {
        kr[d] = k[base + (i << 5) + d];
        kn = fmaf(kr[d], kr[d], kn);
        vs[i][d] = v[base + (i << 5) + d];
    }
    float nsv = ns[pidx];
    float kmul = fminf(fmaxf(1.f - nsv, 0.f), 1.f) / fmaxf(sqrtf(kn), 1e-12f);
#pragma unroll
    for (int d = 0; d < 32; d++) ks[i][d] = kr[d] * kmul;

    float qr[32];
    float qn = 0.f;
#pragma unroll
    for (int d = 0; d < 32; d++) {
        qr[d] = q[base + (i << 5) + d];
        qn = fmaf(qr[d], qr[d], qn);
    }
    float qmul = (1.f + is[pidx]) / fmaxf(sqrtf(qn), 1e-12f)
               * 0.17677669529663687f * temp[h];
#pragma unroll
    for (int d = 0; d < 32; d++) qr[d] *= qmul;

    __syncthreads();

    float mx = -1e30f;
#pragma unroll
    for (int j = 0; j < 64; j++) {
        float s = 0.f;
#pragma unroll
        for (int d = 0; d < 32; d++) s = fmaf(qr[d], ks[j][d], s);
        sc[i][j] = s;
        mx = fmaxf(mx, s);
    }
    float sum = 0.f;
#pragma unroll
    for (int j = 0; j < 64; j++) {
        float e = __expf(sc[i][j] - mx);
        sc[i][j] = e;
        sum += e;
    }
    float inv = 1.f / sum;

    float acc[32];
#pragma unroll
    for (int d = 0; d < 32; d++) acc[d] = 0.f;
#pragma unroll
    for (int j = 0; j < 64; j++) {
        float p = sc[i][j] * inv;
#pragma unroll
        for (int d = 0; d < 32; d++) acc[d] = fmaf(p, vs[j][d], acc[d]);
    }
#pragma unroll
    for (int d = 0; d < 32; d++) out[base + (i << 5) + d] = acc[d];
}

// ---------------- launch ----------------
extern "C" void kernel_launch(void* const* d_in, const int* in_sizes, int n_in,
                              void* d_out, int out_size) {
    const float* x      = (const float*)d_in[0];
    const float* w_iem  = (const float*)d_in[1];
    const float* g_iem  = (const float*)d_in[2];
    const float* b_iem  = (const float*)d_in[3];
    const float* w_nem  = (const float*)d_in[4];
    const float* g_nem  = (const float*)d_in[5];
    const float* b_nem  = (const float*)d_in[6];
    const float* w_idw  = (const float*)d_in[7];
    const float* w_ndw  = (const float*)d_in[8];
    const float* w_q    = (const float*)d_in[9];
    const float* w_k    = (const float*)d_in[10];
    const float* w_v    = (const float*)d_in[11];
    const float* w_proj = (const float*)d_in[12];
    const float* temp   = (const float*)d_in[13];
    float* out = (float*)d_out;

    float *A, *B, *C, *D, *X, *WCT, *WT4, *BNA, *BNC, *IS, *NS;
    cudaGetSymbolAddress((void**)&A,   g_A);
    cudaGetSymbolAddress((void**)&B,   g_B);
    cudaGetSymbolAddress((void**)&C,   g_C);
    cudaGetSymbolAddress((void**)&D,   g_D);
    cudaGetSymbolAddress((void**)&X,   g_X);
    cudaGetSymbolAddress((void**)&WCT, g_wct);
    cudaGetSymbolAddress((void**)&WT4, g_wt4);
    cudaGetSymbolAddress((void**)&BNA, g_bna);
    cudaGetSymbolAddress((void**)&BNC, g_bnc);
    cudaGetSymbolAddress((void**)&IS,  g_is);
    cudaGetSymbolAddress((void**)&NS,  g_ns);

    const int SMEM = (130 * 36 + 3 * 32 * 136) * 4;   // 70944 bytes
    cudaFuncSetAttribute(conv_mma, cudaFuncAttributeMaxDynamicSharedMemorySize, SMEM);

    tconv_kernel<<<4608, 256>>>(w_iem, w_nem, WCT);
    t1x1_kernel<<<1024, 256>>>(w_q, w_k, w_v, w_proj, WT4);
    xT_kernel<<<dim3(2048, 8, 2), dim3(32, 32)>>>(x, X);

    dim3 cg(512, 2, 2);
    conv_mma<<<cg, 256, SMEM>>>(X, WCT,          A);
    conv_mma<<<cg, 256, SMEM>>>(X, WCT + 589824, B);

    bnstats_kernel<<<256, 256>>>(A, g_iem, b_iem, BNA,       BNC);
    bnstats_kernel<<<256, 256>>>(B, g_nem, b_nem, BNA + 256, BNC + 256);

    dwconv_kernel<<<131072, 256>>>(A, BNA,       BNC,       w_idw, C);
    dwconv_kernel<<<131072, 256>>>(B, BNA + 256, BNC + 256, w_ndw, D);

    chanmean_kernel<<<dim3(256, 2), 256>>>(C, D, IS, NS);

    dim3 gg(512, 4, 2);
    gemm1x1<0><<<gg, 128>>>(WT4,             C, A);   // q from illum map
    gemm1x1<0><<<gg, 128>>>(WT4 + 65536,     D, B);   // k from noise map
    gemm1x1<0><<<gg, 128>>>(WT4 + 2 * 65536, x, C);   // v from x

    attn_kernel<<<dim3(1024, 8, 2), 64>>>(A, B, C, IS, NS, temp, D);

    gemm1x1<3><<<gg, 128>>>(WT4 + 3 * 65536, D, out); // proj -> NCHW output
}

// round 6
// speedup vs baseline: 2.9723x; 1.3196x over previous
#include <cuda_runtime.h>
#include <math.h>
#include <stdint.h>

#define HW 65536
#define NBUF (2*256*HW)

// ---------------- static scratch ----------------
__device__ float g_A[NBUF];   // conv_iem raw [r][c] -> q (window layout)
__device__ float g_B[NBUF];   // conv_nem raw [r][c] -> k (window layout)
__device__ float g_C[NBUF];   // illum map [r][c] -> v (window layout)
__device__ float g_D[NBUF];   // noise map [r][c] -> attn out [r][c]
__device__ float g_X[NBUF];   // x transposed [b][px][c], tf32-rounded
__device__ float g_wct[2*589824];  // conv weights [m][tap][c][oc], tf32
__device__ float g_wt4[4*65536];   // 1x1 weights [m][c][oc], tf32
__device__ float g_part[131072];   // bn partials [256 blk][2][256 ch]
__device__ float g_bna[512];
__device__ float g_bnc[512];
__device__ float g_is[2*HW];
__device__ float g_ns[2*HW];

// ---------------- helpers ----------------
__device__ __forceinline__ float to_tf32(float f) {
    float r;
    asm("cvt.rna.tf32.f32 %0, %1;" : "=f"(r) : "f"(f));
    return r;
}
__device__ __forceinline__ uint32_t smem_u32(const void* p) {
    uint32_t a;
    asm("{ .reg .u64 t; cvta.to.shared.u64 t, %1; cvt.u32.u64 %0, t; }" : "=r"(a) : "l"(p));
    return a;
}
__device__ __forceinline__ void cpa16(uint32_t s, const float* g, uint32_t n) {
    asm volatile("cp.async.cg.shared.global [%0], [%1], 16, %2;"
                 :: "r"(s), "l"(g), "r"(n) : "memory");
}
#define CP_COMMIT()  asm volatile("cp.async.commit_group;" ::: "memory")
#define CP_WAIT1()   asm volatile("cp.async.wait_group 1;" ::: "memory")
#define CP_WAIT0()   asm volatile("cp.async.wait_group 0;" ::: "memory")

// tf32 m16n8k8 mma (family-portable HMMA; tcgen05 PTX rejected at compute_103)
__device__ __forceinline__ void mma8(float* d, const uint32_t* a, const uint32_t* b) {
    asm volatile("mma.sync.aligned.m16n8k8.row.col.f32.tf32.tf32.f32 "
        "{%0,%1,%2,%3}, {%4,%5,%6,%7}, {%8,%9}, {%0,%1,%2,%3};"
        : "+f"(d[0]), "+f"(d[1]), "+f"(d[2]), "+f"(d[3])
        : "r"(a[0]), "r"(a[1]), "r"(a[2]), "r"(a[3]), "r"(b[0]), "r"(b[1]));
}

// ---------------- weight prep ----------------
__global__ void tconv_kernel(const float* __restrict__ w0, const float* __restrict__ w1,
                             float* __restrict__ out) {
    int i = blockIdx.x * 256 + threadIdx.x;          // 2*589824
    int m = i / 589824;
    int r = i - m * 589824;
    int tap = r >> 16;
    int rem = r & 65535;
    int c   = rem >> 8;
    int oc  = rem & 255;
    const float* w = m ? w1 : w0;
    out[i] = to_tf32(w[oc * 2304 + c * 9 + tap]);
}

__global__ void t1x1_kernel(const float* __restrict__ wq, const float* __restrict__ wk,
                            const float* __restrict__ wv, const float* __restrict__ wp,
                            float* __restrict__ out) {
    int i = blockIdx.x * 256 + threadIdx.x;          // 4*65536
    int m = i >> 16;
    int r = i & 65535;
    int c = r >> 8;
    int o = r & 255;
    const float* w = (m == 0) ? wq : (m == 1) ? wk : (m == 2) ? wv : wp;
    out[i] = to_tf32(w[o * 256 + c]);
}

// ---------------- x transpose: NCHW -> [b][px][c], tf32 ----------------
__global__ void xT_kernel(const float* __restrict__ x, float* __restrict__ xT) {
    __shared__ float t[32][33];
    int b  = blockIdx.z;
    int c0 = blockIdx.y * 32;
    int p0 = blockIdx.x * 32;
    int tx = threadIdx.x, ty = threadIdx.y;
    t[ty][tx] = to_tf32(x[(((size_t)((b << 8) + c0 + ty)) << 16) + p0 + tx]);
    __syncthreads();
    xT[(((size_t)((b << 16) + p0 + ty)) << 8) + c0 + tx] = t[tx][ty];
}

// ---------------- 3x3 conv implicit GEMM, 2-stage pipeline ----------------
// CTA 128px x 128oc; K = 24 steps (8 c-chunks x 3 ky), kx via smem row shift.
// Output written channel-last [b][px][oc].
#define CONV_STG 17736   // floats per stage: 130*36 + 3*32*136
__global__ void __launch_bounds__(256, 1) conv_mma(const float* __restrict__ xT,
                                                   const float* __restrict__ W2,
                                                   float* __restrict__ out) {
    extern __shared__ float sm[];
    const int tid  = threadIdx.x;
    const int w    = tid >> 5, lane = tid & 31;
    const int g    = lane >> 2, tg = lane & 3;
    const int y    = blockIdx.x >> 1;
    const int p0   = (blockIdx.x & 1) << 7;
    const int oc0  = blockIdx.y << 7;
    const int b    = blockIdx.z;
    const int wm   = w >> 2, wn = w & 3;
    const uint32_t sm_u = smem_u32(sm);

    float acc[4][4][4];
#pragma unroll
    for (int mi = 0; mi < 4; mi++)
#pragma unroll
        for (int ni = 0; ni < 4; ni++)
#pragma unroll
            for (int r = 0; r < 4; r++) acc[mi][ni][r] = 0.f;

    auto do_load = [&](int step, int buf) {
        int cc = step / 3;
        int ky = step - cc * 3;
        int c0 = cc * 32;
        uint32_t xs_u = sm_u + buf * (CONV_STG * 4);
        uint32_t ws_u = xs_u + 4680 * 4;
        int yin = y + ky - 1;
        bool yok = (unsigned)yin < 256u;
#pragma unroll
        for (int jj = 0; jj < 5; jj++) {
            int j = jj * 256 + tid;
            if (j < 1040) {
                int r = j >> 3, q = j & 7;
                int xin = p0 + r - 1;
                bool ok = yok && ((unsigned)xin < 256u);
                const float* src = ok
                    ? xT + ((((size_t)b << 16) + ((size_t)yin << 8) + xin) << 8) + c0 + q * 4
                    : xT;
                cpa16(xs_u + r * 144 + q * 16, src, ok ? 16u : 0u);
            }
        }
#pragma unroll
        for (int jj = 0; jj < 12; jj++) {
            int j = jj * 256 + tid;
            int kx = j >> 10, rem = j & 1023;
            int c = rem >> 5, q = rem & 31;
            int tap = ky * 3 + kx;
            cpa16(ws_u + (kx * 32 + c) * 544 + q * 16,
                  W2 + ((size_t)(tap * 256 + c0 + c) << 8) + oc0 + q * 4, 16u);
        }
        CP_COMMIT();
    };

    auto do_compute = [&](int buf) {
        float* Xs = sm + buf * CONV_STG;
        float* Ws = Xs + 4680;
#pragma unroll
        for (int kx = 0; kx < 3; kx++) {
#pragma unroll
            for (int ks = 0; ks < 4; ks++) {
                const int col = ks * 8 + tg;
                uint32_t af[4][4];
#pragma unroll
                for (int mi = 0; mi < 4; mi++) {
                    int r0 = (wm * 64 + mi * 16 + g + kx) * 36 + col;
                    af[mi][0] = __float_as_uint(Xs[r0]);
                    af[mi][1] = __float_as_uint(Xs[r0 + 8 * 36]);
                    af[mi][2] = __float_as_uint(Xs[r0 + 4]);
                    af[mi][3] = __float_as_uint(Xs[r0 + 8 * 36 + 4]);
                }
                uint32_t bf[4][2];
#pragma unroll
                for (int ni = 0; ni < 4; ni++) {
                    int rb = (kx * 32 + col) * 136 + wn * 32 + ni * 8 + g;
                    bf[ni][0] = __float_as_uint(Ws[rb]);
                    bf[ni][1] = __float_as_uint(Ws[rb + 4 * 136]);
                }
#pragma unroll
                for (int mi = 0; mi < 4; mi++)
#pragma unroll
                    for (int ni = 0; ni < 4; ni++)
                        mma8(acc[mi][ni], af[mi], bf[ni]);
            }
        }
    };

    do_load(0, 0);
    do_load(1, 1);
    for (int s = 0; s < 24; s++) {
        if (s < 23) { CP_WAIT1(); } else { CP_WAIT0(); }
        __syncthreads();
        do_compute(s & 1);
        __syncthreads();
        if (s + 2 < 24) do_load(s + 2, s & 1);
    }

    // epilogue: fragments -> smem S[px][oc] -> channel-last rows
    float* S = sm;
#pragma unroll
    for (int mi = 0; mi < 4; mi++) {
        int px = wm * 64 + mi * 16 + g;
#pragma unroll
        for (int ni = 0; ni < 4; ni++) {
            int oc = wn * 32 + ni * 8 + 2 * tg;
            S[px * 132 + oc]           = acc[mi][ni][0];
            S[px * 132 + oc + 1]       = acc[mi][ni][1];
            S[(px + 8) * 132 + oc]     = acc[mi][ni][2];
            S[(px + 8) * 132 + oc + 1] = acc[mi][ni][3];
        }
    }
    __syncthreads();
#pragma unroll
    for (int it = 0; it < 16; it++) {
        int px = w + it * 8;
        float4 v = *(float4*)&S[px * 132 + lane * 4];
        *(float4*)&out[(((size_t)((b << 16) + (y << 8) + p0 + px)) << 8) + oc0 + lane * 4] = v;
    }
}

// ---------------- BN stats: deterministic 2-stage, channel-last ----------------
__global__ void bnstats1(const float* __restrict__ conv, float* __restrict__ part) {
    int c = threadIdx.x;
    int j = blockIdx.x;
    size_t r0 = (size_t)j * 512;
    float s = 0.f, s2 = 0.f;
    for (int i = 0; i < 512; i++) {
        float v = conv[(r0 + i) * 256 + c];
        s += v; s2 += v * v;
    }
    part[j * 512 + c]       = s;
    part[j * 512 + 256 + c] = s2;
}

__global__ void bnstats2(const float* __restrict__ part,
                         const float* __restrict__ gamma, const float* __restrict__ beta,
                         float* __restrict__ pa, float* __restrict__ pc) {
    int c = threadIdx.x;
    float s = 0.f, s2 = 0.f;
    for (int j = 0; j < 256; j++) {
        s  += part[j * 512 + c];
        s2 += part[j * 512 + 256 + c];
    }
    float m   = s  * (1.f / 131072.f);
    float var = s2 * (1.f / 131072.f) - m * m;
    float a = gamma[c] * rsqrtf(var + 1e-5f);
    pa[c] = a;
    pc[c] = beta[c] - m * a;
}

// ---------------- depthwise conv, channel-last, BN+relu6 fused, tf32 out ----------------
__global__ void dwconv_t(const float* __restrict__ in,
                         const float* __restrict__ pa, const float* __restrict__ pc,
                         const float* __restrict__ wdw, float* __restrict__ out) {
    int r = blockIdx.x;          // global row (b*65536 + px)
    int c = threadIdx.x;
    int p = r & 65535;
    int y = p >> 8, xx = p & 255;
    float a = pa[c], cb = pc[c];
    float w[9];
#pragma unroll
    for (int t = 0; t < 9; t++) w[t] = wdw[c * 9 + t];
    float acc = 0.f;
#pragma unroll
    for (int ky = 0; ky < 3; ky++) {
        int yy = y + ky - 1;
        if ((unsigned)yy >= 256u) continue;
#pragma unroll
        for (int kx = 0; kx < 3; kx++) {
            int xv = xx + kx - 1;
            if ((unsigned)xv >= 256u) continue;
            float v = in[((size_t)r + (ky - 1) * 256 + (kx - 1)) * 256 + c];
            v = fminf(fmaxf(v * a + cb, 0.f), 6.f);
            acc = fmaf(w[ky * 3 + kx], v, acc);
        }
    }
    out[(size_t)r * 256 + c] = to_tf32(acc);
}

// ---------------- per-pixel channel mean (warp row-sum) ----------------
__global__ void chanmean_t(const float* __restrict__ il, const float* __restrict__ nm,
                           float* __restrict__ is, float* __restrict__ ns) {
    int w = threadIdx.x >> 5, lane = threadIdx.x & 31;
    int r = blockIdx.x * 8 + w;
    size_t base = (size_t)r * 256;
    float s1 = 0.f, s2 = 0.f;
#pragma unroll
    for (int k = 0; k < 8; k++) {
        s1 += il[base + lane + k * 32];
        s2 += nm[base + lane + k * 32];
    }
#pragma unroll
    for (int off = 16; off; off >>= 1) {
        s1 += __shfl_xor_sync(0xffffffffu, s1, off);
        s2 += __shfl_xor_sync(0xffffffffu, s2, off);
    }
    if (lane == 0) {
        is[r] = s1 * (1.f / 256.f);
        ns[r] = s2 * (1.f / 256.f);
    }
}

// ---------------- 1x1 channel GEMM on tensor cores, 2-stage ----------------
// CTA 128px x 128oc, K=256 (8 chunks). MODE 0: window-layout out. MODE 1: NCHW out.
#define GEMM_STG 8960    // floats per stage: 128*36 + 32*136
template <int MODE>
__global__ void __launch_bounds__(256, 2) gemm_mma(const float* __restrict__ wt,
                                                   const float* __restrict__ in,
                                                   float* __restrict__ out) {
    extern __shared__ float sm[];
    const int tid  = threadIdx.x;
    const int w    = tid >> 5, lane = tid & 31;
    const int g    = lane >> 2, tg = lane & 3;
    const int tile = blockIdx.x;
    const int oc0  = blockIdx.y << 7;
    const int b    = blockIdx.z;
    const int wm   = w >> 2, wn = w & 3;
    const uint32_t sm_u = smem_u32(sm);
    const size_t r0 = ((size_t)b << 16) + (size_t)tile * 128;

    float acc[4][4][4];
#pragma unroll
    for (int mi = 0; mi < 4; mi++)
#pragma unroll
        for (int ni = 0; ni < 4; ni++)
#pragma unroll
            for (int r = 0; r < 4; r++) acc[mi][ni][r] = 0.f;

    auto do_load = [&](int cc, int buf) {
        int c0 = cc * 32;
        uint32_t xs_u = sm_u + buf * (GEMM_STG * 4);
        uint32_t ws_u = xs_u + 4608 * 4;
#pragma unroll
        for (int jj = 0; jj < 4; jj++) {
            int j = jj * 256 + tid;
            int r = j >> 3, q = j & 7;
            cpa16(xs_u + r * 144 + q * 16, in + (r0 + r) * 256 + c0 + q * 4, 16u);
        }
#pragma unroll
        for (int jj = 0; jj < 4; jj++) {
            int j = jj * 256 + tid;
            int c = j >> 5, q = j & 31;
            cpa16(ws_u + c * 544 + q * 16, wt + (size_t)(c0 + c) * 256 + oc0 + q * 4, 16u);
        }
        CP_COMMIT();
    };

    auto do_compute = [&](int buf) {
        float* Xs = sm + buf * GEMM_STG;
        float* Ws = Xs + 4608;
#pragma unroll
        for (int ks = 0; ks < 4; ks++) {
            const int col = ks * 8 + tg;
            uint32_t af[4][4];
#pragma unroll
            for (int mi = 0; mi < 4; mi++) {
                int rr = (wm * 64 + mi * 16 + g) * 36 + col;
                af[mi][0] = __float_as_uint(Xs[rr]);
                af[mi][1] = __float_as_uint(Xs[rr + 8 * 36]);
                af[mi][2] = __float_as_uint(Xs[rr + 4]);
                af[mi][3] = __float_as_uint(Xs[rr + 8 * 36 + 4]);
            }
            uint32_t bf[4][2];
#pragma unroll
            for (int ni = 0; ni < 4; ni++) {
                int rb = col * 136 + wn * 32 + ni * 8 + g;
                bf[ni][0] = __float_as_uint(Ws[rb]);
                bf[ni][1] = __float_as_uint(Ws[rb + 4 * 136]);
            }
#pragma unroll
            for (int mi = 0; mi < 4; mi++)
#pragma unroll
                for (int ni = 0; ni < 4; ni++)
                    mma8(acc[mi][ni], af[mi], bf[ni]);
        }
    };

    do_load(0, 0);
    do_load(1, 1);
    for (int s = 0; s < 8; s++) {
        if (s < 7) { CP_WAIT1(); } else { CP_WAIT0(); }
        __syncthreads();
        do_compute(s & 1);
        __syncthreads();
        if (s + 2 < 8) do_load(s + 2, s & 1);
    }

    float* S = sm;
    if (MODE == 0) {
        // S[px][oc]
#pragma unroll
        for (int mi = 0; mi < 4; mi++) {
            int px = wm * 64 + mi * 16 + g;
#pragma unroll
            for (int ni = 0; ni < 4; ni++) {
                int oc = wn * 32 + ni * 8 + 2 * tg;
                S[px * 132 + oc]           = acc[mi][ni][0];
                S[px * 132 + oc + 1]       = acc[mi][ni][1];
                S[(px + 8) * 132 + oc]     = acc[mi][ni][2];
                S[(px + 8) * 132 + oc + 1] = acc[mi][ni][3];
            }
        }
        __syncthreads();
        // scatter into window layout [b,h,win,64,32]
#pragma unroll
        for (int s2 = tid; s2 < 512; s2 += 256) {
            int px = s2 >> 2, seg = s2 & 3;
            int gp = tile * 128 + px;
            int y = gp >> 8, x = gp & 255;
            int win = ((y >> 3) << 5) + (x >> 3);
            int pix = ((y & 7) << 3) + (x & 7);
            int h = (oc0 >> 5) + seg;
            size_t dst = (((size_t)(b * 8 + h)) << 21) + ((size_t)win << 11) + (pix << 5);
            float4* src = (float4*)&S[px * 132 + seg * 32];
            float4* d4  = (float4*)&out[dst];
#pragma unroll
            for (int k = 0; k < 8; k++) d4[k] = src[k];
        }
    } else {
        // S[oc][px] -> NCHW
#pragma unroll
        for (int mi = 0; mi < 4; mi++) {
            int px = wm * 64 + mi * 16 + g;
#pragma unroll
            for (int ni = 0; ni < 4; ni++) {
                int oc = wn * 32 + ni * 8 + 2 * tg;
                S[oc * 132 + px]           = acc[mi][ni][0];
                S[(oc + 1) * 132 + px]     = acc[mi][ni][1];
                S[oc * 132 + px + 8]       = acc[mi][ni][2];
                S[(oc + 1) * 132 + px + 8] = acc[mi][ni][3];
            }
        }
        __syncthreads();
#pragma unroll
        for (int it = 0; it < 16; it++) {
            int oc = w + it * 8;
            float4 v = *(float4*)&S[oc * 132 + lane * 4];
            *(float4*)&out[(((size_t)(b * 256 + oc0 + oc)) << 16) + tile * 128 + lane * 4] = v;
        }
    }
}

// ---------------- windowed attention (out -> channel-last, tf32) ----------------
__global__ void __launch_bounds__(64) attn_kernel(const float* __restrict__ q,
                                                  const float* __restrict__ k,
                                                  const float* __restrict__ v,
                                                  const float* __restrict__ is,
                                                  const float* __restrict__ ns,
                                                  const float* __restrict__ temp,
                                                  float* __restrict__ out) {
    __shared__ float ks[64][32];
    __shared__ float vs[64][32];
    __shared__ float sc[64][66];
    const int i   = threadIdx.x;
    const int win = blockIdx.x;
    const int h   = blockIdx.y;
    const int b   = blockIdx.z;
    const size_t base = (((size_t)(b * 8 + h)) << 21) + ((size_t)win << 11);

    const int y = ((win >> 5) << 3) + (i >> 3);
    const int x = ((win & 31) << 3) + (i & 7);
    const int pidx = (b << 16) + (y << 8) + x;

    float kr[32];
    float kn = 0.f;
#pragma unroll
    for (int d = 0; d < 32; d++) {
        kr[d] = k[base + (i << 5) + d];
        kn = fmaf(kr[d], kr[d], kn);
        vs[i][d] = v[base + (i << 5) + d];
    }
    float nsv = ns[pidx];
    float kmul = fminf(fmaxf(1.f - nsv, 0.f), 1.f) / fmaxf(sqrtf(kn), 1e-12f);
#pragma unroll
    for (int d = 0; d < 32; d++) ks[i][d] = kr[d] * kmul;

    float qr[32];
    float qn = 0.f;
#pragma unroll
    for (int d = 0; d < 32; d++) {
        qr[d] = q[base + (i << 5) + d];
        qn = fmaf(qr[d], qr[d], qn);
    }
    float qmul = (1.f + is[pidx]) / fmaxf(sqrtf(qn), 1e-12f)
               * 0.17677669529663687f * temp[h];
#pragma unroll
    for (int d = 0; d < 32; d++) qr[d] *= qmul;

    __syncthreads();

    float mx = -1e30f;
#pragma unroll
    for (int j = 0; j < 64; j++) {
        float s = 0.f;
#pragma unroll
        for (int d = 0; d < 32; d++) s = fmaf(qr[d], ks[j][d], s);
        sc[i][j] = s;
        mx = fmaxf(mx, s);
    }
    float sum = 0.f;
#pragma unroll
    for (int j = 0; j < 64; j++) {
        float e = __expf(sc[i][j] - mx);
        sc[i][j] = e;
        sum += e;
    }
    float inv = 1.f / sum;

    float acc[32];
#pragma unroll
    for (int d = 0; d < 32; d++) acc[d] = 0.f;
#pragma unroll
    for (int j = 0; j < 64; j++) {
        float p = sc[i][j] * inv;
#pragma unroll
        for (int d = 0; d < 32; d++) acc[d] = fmaf(p, vs[j][d], acc[d]);
    }
    size_t obase = ((size_t)pidx << 8) + (h << 5);
#pragma unroll
    for (int d = 0; d < 32; d++) out[obase + d] = to_tf32(acc[d]);
}

// ---------------- launch ----------------
extern "C" void kernel_launch(void* const* d_in, const int* in_sizes, int n_in,
                              void* d_out, int out_size) {
    const float* x      = (const float*)d_in[0];
    const float* w_iem  = (const float*)d_in[1];
    const float* g_iem  = (const float*)d_in[2];
    const float* b_iem  = (const float*)d_in[3];
    const float* w_nem  = (const float*)d_in[4];
    const float* g_nem  = (const float*)d_in[5];
    const float* b_nem  = (const float*)d_in[6];
    const float* w_idw  = (const float*)d_in[7];
    const float* w_ndw  = (const float*)d_in[8];
    const float* w_q    = (const float*)d_in[9];
    const float* w_k    = (const float*)d_in[10];
    const float* w_v    = (const float*)d_in[11];
    const float* w_proj = (const float*)d_in[12];
    const float* temp   = (const float*)d_in[13];
    float* out = (float*)d_out;

    float *A, *B, *C, *D, *X, *WCT, *WT4, *PART, *BNA, *BNC, *IS, *NS;
    cudaGetSymbolAddress((void**)&A,    g_A);
    cudaGetSymbolAddress((void**)&B,    g_B);
    cudaGetSymbolAddress((void**)&C,    g_C);
    cudaGetSymbolAddress((void**)&D,    g_D);
    cudaGetSymbolAddress((void**)&X,    g_X);
    cudaGetSymbolAddress((void**)&WCT,  g_wct);
    cudaGetSymbolAddress((void**)&WT4,  g_wt4);
    cudaGetSymbolAddress((void**)&PART, g_part);
    cudaGetSymbolAddress((void**)&BNA,  g_bna);
    cudaGetSymbolAddress((void**)&BNC,  g_bnc);
    cudaGetSymbolAddress((void**)&IS,   g_is);
    cudaGetSymbolAddress((void**)&NS,   g_ns);

    const int CSM = CONV_STG * 4 * 2;   // 141888
    const int GSM = GEMM_STG * 4 * 2;   // 71680
    cudaFuncSetAttribute(conv_mma,    cudaFuncAttributeMaxDynamicSharedMemorySize, CSM);
    cudaFuncSetAttribute(gemm_mma<0>, cudaFuncAttributeMaxDynamicSharedMemorySize, GSM);
    cudaFuncSetAttribute(gemm_mma<1>, cudaFuncAttributeMaxDynamicSharedMemorySize, GSM);

    tconv_kernel<<<4608, 256>>>(w_iem, w_nem, WCT);
    t1x1_kernel<<<1024, 256>>>(w_q, w_k, w_v, w_proj, WT4);
    xT_kernel<<<dim3(2048, 8, 2), dim3(32, 32)>>>(x, X);

    dim3 cg(512, 2, 2);
    conv_mma<<<cg, 256, CSM>>>(X, WCT,          A);
    conv_mma<<<cg, 256, CSM>>>(X, WCT + 589824, B);

    bnstats1<<<256, 256>>>(A, PART);
    bnstats2<<<1, 256>>>(PART, g_iem, b_iem, BNA, BNC);
    bnstats1<<<256, 256>>>(B, PART);
    bnstats2<<<1, 256>>>(PART, g_nem, b_nem, BNA + 256, BNC + 256);

    dwconv_t<<<131072, 256>>>(A, BNA,       BNC,       w_idw, C);
    dwconv_t<<<131072, 256>>>(B, BNA + 256, BNC + 256, w_ndw, D);

    chanmean_t<<<16384, 256>>>(C, D, IS, NS);

    gemm_mma<0><<<cg, 256, GSM>>>(WT4,              C, A);   // q
    gemm_mma<0><<<cg, 256, GSM>>>(WT4 + 65536,      D, B);   // k
    gemm_mma<0><<<cg, 256, GSM>>>(WT4 + 2 * 65536,  X, C);   // v

    attn_kernel<<<dim3(1024, 8, 2), 64>>>(A, B, C, IS, NS, temp, D);

    gemm_mma<1><<<cg, 256, GSM>>>(WT4 + 3 * 65536,  D, out); // proj -> NCHW
}

// round 7
// speedup vs baseline: 3.0016x; 1.0099x over previous
#include <cuda_runtime.h>
#include <math.h>
#include <stdint.h>

#define HW 65536
#define NBUF (2*256*HW)

// ---------------- static scratch ----------------
__device__ float g_A[NBUF];   // conv_iem raw [r][c] -> q (window layout)
__device__ float g_B[NBUF];   // conv_nem raw [r][c] -> k (window layout)
__device__ float g_C[NBUF];   // illum map [r][c] -> v (window layout)
__device__ float g_D[NBUF];   // noise map [r][c] -> attn out [r][c]
__device__ float g_X[NBUF];   // x transposed [b][px][c], tf32-rounded
__device__ float g_wct[2*589824];  // conv weights [m][tap][c][oc], tf32
__device__ float g_wt4[4*65536];   // 1x1 weights [m][c][oc], tf32
__device__ float g_part[131072];   // bn partials [256 blk][2][256 ch]
__device__ float g_bna[512];
__device__ float g_bnc[512];
__device__ float g_is[2*HW];
__device__ float g_ns[2*HW];

// ---------------- helpers ----------------
__device__ __forceinline__ float to_tf32(float f) {
    float r;
    asm("cvt.rna.tf32.f32 %0, %1;" : "=f"(r) : "f"(f));
    return r;
}
__device__ __forceinline__ uint32_t smem_u32(const void* p) {
    uint32_t a;
    asm("{ .reg .u64 t; cvta.to.shared.u64 t, %1; cvt.u32.u64 %0, t; }" : "=r"(a) : "l"(p));
    return a;
}
__device__ __forceinline__ void cpa16(uint32_t s, const float* g, uint32_t n) {
    asm volatile("cp.async.cg.shared.global [%0], [%1], 16, %2;"
                 :: "r"(s), "l"(g), "r"(n) : "memory");
}
#define CP_COMMIT()  asm volatile("cp.async.commit_group;" ::: "memory")
#define CP_WAIT1()   asm volatile("cp.async.wait_group 1;" ::: "memory")
#define CP_WAIT0()   asm volatile("cp.async.wait_group 0;" ::: "memory")

// tf32 m16n8k8 mma (family-portable HMMA; tcgen05 PTX rejected at compute_103)
__device__ __forceinline__ void mma8(float* d, const uint32_t* a, const uint32_t* b) {
    asm volatile("mma.sync.aligned.m16n8k8.row.col.f32.tf32.tf32.f32 "
        "{%0,%1,%2,%3}, {%4,%5,%6,%7}, {%8,%9}, {%0,%1,%2,%3};"
        : "+f"(d[0]), "+f"(d[1]), "+f"(d[2]), "+f"(d[3])
        : "r"(a[0]), "r"(a[1]), "r"(a[2]), "r"(a[3]), "r"(b[0]), "r"(b[1]));
}

// ---------------- weight prep ----------------
__global__ void tconv_kernel(const float* __restrict__ w0, const float* __restrict__ w1,
                             float* __restrict__ out) {
    int i = blockIdx.x * 256 + threadIdx.x;          // 2*589824
    int m = i / 589824;
    int r = i - m * 589824;
    int tap = r >> 16;
    int rem = r & 65535;
    int c   = rem >> 8;
    int oc  = rem & 255;
    const float* w = m ? w1 : w0;
    out[i] = to_tf32(w[oc * 2304 + c * 9 + tap]);
}

__global__ void t1x1_kernel(const float* __restrict__ wq, const float* __restrict__ wk,
                            const float* __restrict__ wv, const float* __restrict__ wp,
                            float* __restrict__ out) {
    int i = blockIdx.x * 256 + threadIdx.x;          // 4*65536
    int m = i >> 16;
    int r = i & 65535;
    int c = r >> 8;
    int o = r & 255;
    const float* w = (m == 0) ? wq : (m == 1) ? wk : (m == 2) ? wv : wp;
    out[i] = to_tf32(w[o * 256 + c]);
}

// ---------------- x transpose: NCHW -> [b][px][c], tf32 ----------------
__global__ void xT_kernel(const float* __restrict__ x, float* __restrict__ xT) {
    __shared__ float t[32][33];
    int b  = blockIdx.z;
    int c0 = blockIdx.y * 32;
    int p0 = blockIdx.x * 32;
    int tx = threadIdx.x, ty = threadIdx.y;
    t[ty][tx] = to_tf32(x[(((size_t)((b << 8) + c0 + ty)) << 16) + p0 + tx]);
    __syncthreads();
    xT[(((size_t)((b << 16) + p0 + ty)) << 8) + c0 + tx] = t[tx][ty];
}

// ---------------- 3x3 conv implicit GEMM, 2-stage pipeline, 2 CTA/SM ----------------
// CTA 128px x 128oc; K = 48 steps (16 c-chunks of 16 x 3 ky), kx via smem row shift.
// Output channel-last [b][px][oc].
#define CONV_STG 9128    // floats per stage: 130*20 + 3*16*136
__global__ void __launch_bounds__(256, 2) conv_mma(const float* __restrict__ xT,
                                                   const float* __restrict__ W2,
                                                   float* __restrict__ out) {
    extern __shared__ float sm[];
    const int tid  = threadIdx.x;
    const int w    = tid >> 5, lane = tid & 31;
    const int g    = lane >> 2, tg = lane & 3;
    const int y    = blockIdx.x >> 1;
    const int p0   = (blockIdx.x & 1) << 7;
    const int oc0  = blockIdx.y << 7;
    const int b    = blockIdx.z;
    const int wm   = w >> 2, wn = w & 3;
    const uint32_t sm_u = smem_u32(sm);

    float acc[4][4][4];
#pragma unroll
    for (int mi = 0; mi < 4; mi++)
#pragma unroll
        for (int ni = 0; ni < 4; ni++)
#pragma unroll
            for (int r = 0; r < 4; r++) acc[mi][ni][r] = 0.f;

    auto do_load = [&](int step, int buf) {
        int cc = step / 3;
        int ky = step - cc * 3;
        int c0 = cc * 16;
        uint32_t xs_u = sm_u + buf * (CONV_STG * 4);
        uint32_t ws_u = xs_u + 2600 * 4;
        int yin = y + ky - 1;
        bool yok = (unsigned)yin < 256u;
        // x slab: 130 rows x 16 ch (4 x 16B per row)
#pragma unroll
        for (int jj = 0; jj < 3; jj++) {
            int j = jj * 256 + tid;
            if (j < 520) {
                int r = j >> 2, q = j & 3;
                int xin = p0 + r - 1;
                bool ok = yok && ((unsigned)xin < 256u);
                const float* src = ok
                    ? xT + ((((size_t)b << 16) + ((size_t)yin << 8) + xin) << 8) + c0 + q * 4
                    : xT;
                cpa16(xs_u + r * 80 + q * 16, src, ok ? 16u : 0u);
            }
        }
        // weights: 3 kx x [16 c][128 oc]
#pragma unroll
        for (int jj = 0; jj < 6; jj++) {
            int j = jj * 256 + tid;
            int kxc = j >> 5, q = j & 31;         // kxc = kx*16+c (0..47)
            int kx = kxc >> 4, c = kxc & 15;
            int tap = ky * 3 + kx;
            cpa16(ws_u + kxc * 544 + q * 16,
                  W2 + ((size_t)(tap * 256 + c0 + c) << 8) + oc0 + q * 4, 16u);
        }
        CP_COMMIT();
    };

    auto do_compute = [&](int buf) {
        float* Xs = sm + buf * CONV_STG;
        float* Ws = Xs + 2600;
#pragma unroll
        for (int kx = 0; kx < 3; kx++) {
#pragma unroll
            for (int ks = 0; ks < 2; ks++) {
                const int col = ks * 8 + tg;
                uint32_t af[4][4];
#pragma unroll
                for (int mi = 0; mi < 4; mi++) {
                    int r0 = (wm * 64 + mi * 16 + g + kx) * 20 + col;
                    af[mi][0] = __float_as_uint(Xs[r0]);
                    af[mi][1] = __float_as_uint(Xs[r0 + 8 * 20]);
                    af[mi][2] = __float_as_uint(Xs[r0 + 4]);
                    af[mi][3] = __float_as_uint(Xs[r0 + 8 * 20 + 4]);
                }
                uint32_t bf[4][2];
#pragma unroll
                for (int ni = 0; ni < 4; ni++) {
                    int rb = (kx * 16 + col) * 136 + wn * 32 + ni * 8 + g;
                    bf[ni][0] = __float_as_uint(Ws[rb]);
                    bf[ni][1] = __float_as_uint(Ws[rb + 4 * 136]);
                }
#pragma unroll
                for (int mi = 0; mi < 4; mi++)
#pragma unroll
                    for (int ni = 0; ni < 4; ni++)
                        mma8(acc[mi][ni], af[mi], bf[ni]);
            }
        }
    };

    do_load(0, 0);
    do_load(1, 1);
    for (int s = 0; s < 48; s++) {
        if (s < 47) { CP_WAIT1(); } else { CP_WAIT0(); }
        __syncthreads();
        do_compute(s & 1);
        __syncthreads();
        if (s + 2 < 48) do_load(s + 2, s & 1);
    }

    // epilogue: fragments -> smem S[px][oc] -> channel-last rows
    float* S = sm;   // 128*132 = 16896 floats <= 2*CONV_STG
#pragma unroll
    for (int mi = 0; mi < 4; mi++) {
        int px = wm * 64 + mi * 16 + g;
#pragma unroll
        for (int ni = 0; ni < 4; ni++) {
            int oc = wn * 32 + ni * 8 + 2 * tg;
            S[px * 132 + oc]           = acc[mi][ni][0];
            S[px * 132 + oc + 1]       = acc[mi][ni][1];
            S[(px + 8) * 132 + oc]     = acc[mi][ni][2];
            S[(px + 8) * 132 + oc + 1] = acc[mi][ni][3];
        }
    }
    __syncthreads();
#pragma unroll
    for (int it = 0; it < 16; it++) {
        int px = w + it * 8;
        float4 v = *(float4*)&S[px * 132 + lane * 4];
        *(float4*)&out[(((size_t)((b << 16) + (y << 8) + p0 + px)) << 8) + oc0 + lane * 4] = v;
    }
}

// ---------------- BN stats: deterministic 2-stage, channel-last ----------------
__global__ void bnstats1(const float* __restrict__ conv, float* __restrict__ part) {
    int c = threadIdx.x;
    int j = blockIdx.x;
    size_t r0 = (size_t)j * 512;
    float s = 0.f, s2 = 0.f;
    for (int i = 0; i < 512; i++) {
        float v = conv[(r0 + i) * 256 + c];
        s += v; s2 += v * v;
    }
    part[j * 512 + c]       = s;
    part[j * 512 + 256 + c] = s2;
}

__global__ void bnstats2(const float* __restrict__ part,
                         const float* __restrict__ gamma, const float* __restrict__ beta,
                         float* __restrict__ pa, float* __restrict__ pc) {
    int c = threadIdx.x;
    float s = 0.f, s2 = 0.f;
    for (int j = 0; j < 256; j++) {
        s  += part[j * 512 + c];
        s2 += part[j * 512 + 256 + c];
    }
    float m   = s  * (1.f / 131072.f);
    float var = s2 * (1.f / 131072.f) - m * m;
    float a = gamma[c] * rsqrtf(var + 1e-5f);
    pa[c] = a;
    pc[c] = beta[c] - m * a;
}

// ---------------- depthwise conv, channel-last, BN+relu6 fused, tf32 out,
//                  channel-mean fused (one block = one pixel row) ----------------
__global__ void dwconv_t(const float* __restrict__ in,
                         const float* __restrict__ pa, const float* __restrict__ pc,
                         const float* __restrict__ wdw, float* __restrict__ out,
                         float* __restrict__ mean_out) {
    __shared__ float red[8];
    int r = blockIdx.x;          // global row (b*65536 + px)
    int c = threadIdx.x;
    int p = r & 65535;
    int y = p >> 8, xx = p & 255;
    float a = pa[c], cb = pc[c];
    float w[9];
#pragma unroll
    for (int t = 0; t < 9; t++) w[t] = wdw[c * 9 + t];
    float acc = 0.f;
#pragma unroll
    for (int ky = 0; ky < 3; ky++) {
        int yy = y + ky - 1;
        if ((unsigned)yy >= 256u) continue;
#pragma unroll
        for (int kx = 0; kx < 3; kx++) {
            int xv = xx + kx - 1;
            if ((unsigned)xv >= 256u) continue;
            float v = in[((size_t)r + (ky - 1) * 256 + (kx - 1)) * 256 + c];
            v = fminf(fmaxf(v * a + cb, 0.f), 6.f);
            acc = fmaf(w[ky * 3 + kx], v, acc);
        }
    }
    out[(size_t)r * 256 + c] = to_tf32(acc);

    // fused channel mean
    float s = acc;
#pragma unroll
    for (int off = 16; off; off >>= 1) s += __shfl_xor_sync(0xffffffffu, s, off);
    if ((c & 31) == 0) red[c >> 5] = s;
    __syncthreads();
    if (c < 8) {
        float t = red[c];
#pragma unroll
        for (int off = 4; off; off >>= 1) t += __shfl_xor_sync(0xffu, t, off);
        if (c == 0) mean_out[r] = t * (1.f / 256.f);
    }
}

// ---------------- 1x1 channel GEMM on tensor cores, 2-stage ----------------
// CTA 128px x 128oc, K=256 (8 chunks). MODE 0: window-layout out. MODE 1: NCHW out.
#define GEMM_STG 8960    // floats per stage: 128*36 + 32*136
template <int MODE>
__global__ void __launch_bounds__(256, 2) gemm_mma(const float* __restrict__ wt,
                                                   const float* __restrict__ in,
                                                   float* __restrict__ out) {
    extern __shared__ float sm[];
    const int tid  = threadIdx.x;
    const int w    = tid >> 5, lane = tid & 31;
    const int g    = lane >> 2, tg = lane & 3;
    const int tile = blockIdx.x;
    const int oc0  = blockIdx.y << 7;
    const int b    = blockIdx.z;
    const int wm   = w >> 2, wn = w & 3;
    const uint32_t sm_u = smem_u32(sm);
    const size_t r0 = ((size_t)b << 16) + (size_t)tile * 128;

    float acc[4][4][4];
#pragma unroll
    for (int mi = 0; mi < 4; mi++)
#pragma unroll
        for (int ni = 0; ni < 4; ni++)
#pragma unroll
            for (int r = 0; r < 4; r++) acc[mi][ni][r] = 0.f;

    auto do_load = [&](int cc, int buf) {
        int c0 = cc * 32;
        uint32_t xs_u = sm_u + buf * (GEMM_STG * 4);
        uint32_t ws_u = xs_u + 4608 * 4;
#pragma unroll
        for (int jj = 0; jj < 4; jj++) {
            int j = jj * 256 + tid;
            int r = j >> 3, q = j & 7;
            cpa16(xs_u + r * 144 + q * 16, in + (r0 + r) * 256 + c0 + q * 4, 16u);
        }
#pragma unroll
        for (int jj = 0; jj < 4; jj++) {
            int j = jj * 256 + tid;
            int c = j >> 5, q = j & 31;
            cpa16(ws_u + c * 544 + q * 16, wt + (size_t)(c0 + c) * 256 + oc0 + q * 4, 16u);
        }
        CP_COMMIT();
    };

    auto do_compute = [&](int buf) {
        float* Xs = sm + buf * GEMM_STG;
        float* Ws = Xs + 4608;
#pragma unroll
        for (int ks = 0; ks < 4; ks++) {
            const int col = ks * 8 + tg;
            uint32_t af[4][4];
#pragma unroll
            for (int mi = 0; mi < 4; mi++) {
                int rr = (wm * 64 + mi * 16 + g) * 36 + col;
                af[mi][0] = __float_as_uint(Xs[rr]);
                af[mi][1] = __float_as_uint(Xs[rr + 8 * 36]);
                af[mi][2] = __float_as_uint(Xs[rr + 4]);
                af[mi][3] = __float_as_uint(Xs[rr + 8 * 36 + 4]);
            }
            uint32_t bf[4][2];
#pragma unroll
            for (int ni = 0; ni < 4; ni++) {
                int rb = col * 136 + wn * 32 + ni * 8 + g;
                bf[ni][0] = __float_as_uint(Ws[rb]);
                bf[ni][1] = __float_as_uint(Ws[rb + 4 * 136]);
            }
#pragma unroll
            for (int mi = 0; mi < 4; mi++)
#pragma unroll
                for (int ni = 0; ni < 4; ni++)
                    mma8(acc[mi][ni], af[mi], bf[ni]);
        }
    };

    do_load(0, 0);
    do_load(1, 1);
    for (int s = 0; s < 8; s++) {
        if (s < 7) { CP_WAIT1(); } else { CP_WAIT0(); }
        __syncthreads();
        do_compute(s & 1);
        __syncthreads();
        if (s + 2 < 8) do_load(s + 2, s & 1);
    }

    float* S = sm;
    if (MODE == 0) {
#pragma unroll
        for (int mi = 0; mi < 4; mi++) {
            int px = wm * 64 + mi * 16 + g;
#pragma unroll
            for (int ni = 0; ni < 4; ni++) {
                int oc = wn * 32 + ni * 8 + 2 * tg;
                S[px * 132 + oc]           = acc[mi][ni][0];
                S[px * 132 + oc + 1]       = acc[mi][ni][1];
                S[(px + 8) * 132 + oc]     = acc[mi][ni][2];
                S[(px + 8) * 132 + oc + 1] = acc[mi][ni][3];
            }
        }
        __syncthreads();
#pragma unroll
        for (int s2 = tid; s2 < 512; s2 += 256) {
            int px = s2 >> 2, seg = s2 & 3;
            int gp = tile * 128 + px;
            int y = gp >> 8, x = gp & 255;
            int win = ((y >> 3) << 5) + (x >> 3);
            int pix = ((y & 7) << 3) + (x & 7);
            int h = (oc0 >> 5) + seg;
            size_t dst = (((size_t)(b * 8 + h)) << 21) + ((size_t)win << 11) + (pix << 5);
            float4* src = (float4*)&S[px * 132 + seg * 32];
            float4* d4  = (float4*)&out[dst];
#pragma unroll
            for (int k = 0; k < 8; k++) d4[k] = src[k];
        }
    } else {
#pragma unroll
        for (int mi = 0; mi < 4; mi++) {
            int px = wm * 64 + mi * 16 + g;
#pragma unroll
            for (int ni = 0; ni < 4; ni++) {
                int oc = wn * 32 + ni * 8 + 2 * tg;
                S[oc * 132 + px]           = acc[mi][ni][0];
                S[(oc + 1) * 132 + px]     = acc[mi][ni][1];
                S[oc * 132 + px + 8]       = acc[mi][ni][2];
                S[(oc + 1) * 132 + px + 8] = acc[mi][ni][3];
            }
        }
        __syncthreads();
#pragma unroll
        for (int it = 0; it < 16; it++) {
            int oc = w + it * 8;
            float4 v = *(float4*)&S[oc * 132 + lane * 4];
            *(float4*)&out[(((size_t)(b * 256 + oc0 + oc)) << 16) + tile * 128 + lane * 4] = v;
        }
    }
}

// ---------------- windowed attention (out -> channel-last, tf32) ----------------
__global__ void __launch_bounds__(64) attn_kernel(const float* __restrict__ q,
                                                  const float* __restrict__ k,
                                                  const float* __restrict__ v,
                                                  const float* __restrict__ is,
                                                  const float* __restrict__ ns,
                                                  const float* __restrict__ temp,
                                                  float* __restrict__ out) {
    __shared__ float ks[64][32];
    __shared__ float vs[64][32];
    __shared__ float sc[64][66];
    const int i   = threadIdx.x;
    const int win = blockIdx.x;
    const int h   = blockIdx.y;
    const int b   = blockIdx.z;
    const size_t base = (((size_t)(b * 8 + h)) << 21) + ((size_t)win << 11);

    const int y = ((win >> 5) << 3) + (i >> 3);
    const int x = ((win & 31) << 3) + (i & 7);
    const int pidx = (b << 16) + (y << 8) + x;

    float kr[32];
    float kn = 0.f;
#pragma unroll
    for (int d = 0; d < 32; d++) {
        kr[d] = k[base + (i << 5) + d];
        kn = fmaf(kr[d], kr[d], kn);
        vs[i][d] = v[base + (i << 5) + d];
    }
    float nsv = ns[pidx];
    float kmul = fminf(fmaxf(1.f - nsv, 0.f), 1.f) / fmaxf(sqrtf(kn), 1e-12f);
#pragma unroll
    for (int d = 0; d < 32; d++) ks[i][d] = kr[d] * kmul;

    float qr[32];
    float qn = 0.f;
#pragma unroll
    for (int d = 0; d < 32; d++) {
        qr[d] = q[base + (i << 5) + d];
        qn = fmaf(qr[d], qr[d], qn);
    }
    float qmul = (1.f + is[pidx]) / fmaxf(sqrtf(qn), 1e-12f)
               * 0.17677669529663687f * temp[h];
#pragma unroll
    for (int d = 0; d < 32; d++) qr[d] *= qmul;

    __syncthreads();

    float mx = -1e30f;
#pragma unroll
    for (int j = 0; j < 64; j++) {
        float s = 0.f;
#pragma unroll
        for (int d = 0; d < 32; d++) s = fmaf(qr[d], ks[j][d], s);
        sc[i][j] = s;
        mx = fmaxf(mx, s);
    }
    float sum = 0.f;
#pragma unroll
    for (int j = 0; j < 64; j++) {
        float e = __expf(sc[i][j] - mx);
        sc[i][j] = e;
        sum += e;
    }
    float inv = 1.f / sum;

    float acc[32];
#pragma unroll
    for (int d = 0; d < 32; d++) acc[d] = 0.f;
#pragma unroll
    for (int j = 0; j < 64; j++) {
        float p = sc[i][j] * inv;
#pragma unroll
        for (int d = 0; d < 32; d++) acc[d] = fmaf(p, vs[j][d], acc[d]);
    }
    size_t obase = ((size_t)pidx << 8) + (h << 5);
#pragma unroll
    for (int d = 0; d < 32; d++) out[obase + d] = to_tf32(acc[d]);
}

// ---------------- launch ----------------
extern "C" void kernel_launch(void* const* d_in, const int* in_sizes, int n_in,
                              void* d_out, int out_size) {
    const float* x      = (const float*)d_in[0];
    const float* w_iem  = (const float*)d_in[1];
    const float* g_iem  = (const float*)d_in[2];
    const float* b_iem  = (const float*)d_in[3];
    const float* w_nem  = (const float*)d_in[4];
    const float* g_nem  = (const float*)d_in[5];
    const float* b_nem  = (const float*)d_in[6];
    const float* w_idw  = (const float*)d_in[7];
    const float* w_ndw  = (const float*)d_in[8];
    const float* w_q    = (const float*)d_in[9];
    const float* w_k    = (const float*)d_in[10];
    const float* w_v    = (const float*)d_in[11];
    const float* w_proj = (const float*)d_in[12];
    const float* temp   = (const float*)d_in[13];
    float* out = (float*)d_out;

    float *A, *B, *C, *D, *X, *WCT, *WT4, *PART, *BNA, *BNC, *IS, *NS;
    cudaGetSymbolAddress((void**)&A,    g_A);
    cudaGetSymbolAddress((void**)&B,    g_B);
    cudaGetSymbolAddress((void**)&C,    g_C);
    cudaGetSymbolAddress((void**)&D,    g_D);
    cudaGetSymbolAddress((void**)&X,    g_X);
    cudaGetSymbolAddress((void**)&WCT,  g_wct);
    cudaGetSymbolAddress((void**)&WT4,  g_wt4);
    cudaGetSymbolAddress((void**)&PART, g_part);
    cudaGetSymbolAddress((void**)&BNA,  g_bna);
    cudaGetSymbolAddress((void**)&BNC,  g_bnc);
    cudaGetSymbolAddress((void**)&IS,   g_is);
    cudaGetSymbolAddress((void**)&NS,   g_ns);

    const int CSM = CONV_STG * 4 * 2;   // 73024
    const int GSM = GEMM_STG * 4 * 2;   // 71680
    cudaFuncSetAttribute(conv_mma,    cudaFuncAttributeMaxDynamicSharedMemorySize, CSM);
    cudaFuncSetAttribute(gemm_mma<0>, cudaFuncAttributeMaxDynamicSharedMemorySize, GSM);
    cudaFuncSetAttribute(gemm_mma<1>, cudaFuncAttributeMaxDynamicSharedMemorySize, GSM);

    tconv_kernel<<<4608, 256>>>(w_iem, w_nem, WCT);
    t1x1_kernel<<<1024, 256>>>(w_q, w_k, w_v, w_proj, WT4);
    xT_kernel<<<dim3(2048, 8, 2), dim3(32, 32)>>>(x, X);

    dim3 cg(512, 2, 2);
    conv_mma<<<cg, 256, CSM>>>(X, WCT,          A);
    conv_mma<<<cg, 256, CSM>>>(X, WCT + 589824, B);

    bnstats1<<<256, 256>>>(A, PART);
    bnstats2<<<1, 256>>>(PART, g_iem, b_iem, BNA, BNC);
    bnstats1<<<256, 256>>>(B, PART);
    bnstats2<<<1, 256>>>(PART, g_nem, b_nem, BNA + 256, BNC + 256);

    dwconv_t<<<131072, 256>>>(A, BNA,       BNC,       w_idw, C, IS);
    dwconv_t<<<131072, 256>>>(B, BNA + 256, BNC + 256, w_ndw, D, NS);

    gemm_mma<0><<<cg, 256, GSM>>>(WT4,              C, A);   // q
    gemm_mma<0><<<cg, 256, GSM>>>(WT4 + 65536,      D, B);   // k
    gemm_mma<0><<<cg, 256, GSM>>>(WT4 + 2 * 65536,  X, C);   // v

    attn_kernel<<<dim3(1024, 8, 2), 64>>>(A, B, C, IS, NS, temp, D);

    gemm_mma<1><<<cg, 256, GSM>>>(WT4 + 3 * 65536,  D, out); // proj -> NCHW
}

// round 8
// speedup vs baseline: 3.5654x; 1.1878x over previous
#include <cuda_runtime.h>
#include <math.h>
#include <stdint.h>

#define HW 65536
#define NBUF (2*256*HW)

// ---------------- static scratch ----------------
__device__ float g_A[NBUF];   // conv_iem raw [r][c] -> q (window layout)
__device__ float g_B[NBUF];   // conv_nem raw [r][c] -> k (window layout)
__device__ float g_C[NBUF];   // illum map [r][c] -> v (window layout)
__device__ float g_D[NBUF];   // noise map [r][c] -> attn out [r][c]
__device__ float g_X[NBUF];   // x transposed [b][px][c], tf32-rounded
__device__ float g_wct[2*589824];  // conv weights [m][tap][c][oc], tf32
__device__ float g_wt4[4*65536];   // 1x1 weights [m][c][oc], tf32
__device__ float g_part[262144];   // bn partials [512 blk][2][256 ch]
__device__ float g_bna[512];
__device__ float g_bnc[512];
__device__ float g_is[2*HW];
__device__ float g_ns[2*HW];

// ---------------- helpers ----------------
__device__ __forceinline__ float to_tf32(float f) {
    float r;
    asm("cvt.rna.tf32.f32 %0, %1;" : "=f"(r) : "f"(f));
    return r;
}
__device__ __forceinline__ void ffma2(unsigned long long& d, unsigned long long a,
                                      unsigned long long b) {
    asm("fma.rn.f32x2 %0, %1, %2, %0;" : "+l"(d) : "l"(a), "l"(b));
}
__device__ __forceinline__ unsigned long long pack2(float lo, float hi) {
    unsigned long long r;
    asm("mov.b64 %0, {%1, %2};" : "=l"(r) : "f"(lo), "f"(hi));
    return r;
}
__device__ __forceinline__ void unpack2(unsigned long long p, float& lo, float& hi) {
    asm("mov.b64 {%0, %1}, %2;" : "=f"(lo), "=f"(hi) : "l"(p));
}
__device__ __forceinline__ uint32_t smem_u32(const void* p) {
    uint32_t a;
    asm("{ .reg .u64 t; cvta.to.shared.u64 t, %1; cvt.u32.u64 %0, t; }" : "=r"(a) : "l"(p));
    return a;
}
__device__ __forceinline__ void cpa16(uint32_t s, const float* g, uint32_t n) {
    asm volatile("cp.async.cg.shared.global [%0], [%1], 16, %2;"
                 :: "r"(s), "l"(g), "r"(n) : "memory");
}
#define CP_COMMIT()  asm volatile("cp.async.commit_group;" ::: "memory")
#define CP_WAIT1()   asm volatile("cp.async.wait_group 1;" ::: "memory")
#define CP_WAIT0()   asm volatile("cp.async.wait_group 0;" ::: "memory")

// tf32 m16n8k8 mma (family-portable HMMA; tcgen05 PTX rejected at compute_103)
__device__ __forceinline__ void mma8(float* d, const uint32_t* a, const uint32_t* b) {
    asm volatile("mma.sync.aligned.m16n8k8.row.col.f32.tf32.tf32.f32 "
        "{%0,%1,%2,%3}, {%4,%5,%6,%7}, {%8,%9}, {%0,%1,%2,%3};"
        : "+f"(d[0]), "+f"(d[1]), "+f"(d[2]), "+f"(d[3])
        : "r"(a[0]), "r"(a[1]), "r"(a[2]), "r"(a[3]), "r"(b[0]), "r"(b[1]));
}

// ---------------- weight prep ----------------
__global__ void tconv_kernel(const float* __restrict__ w0, const float* __restrict__ w1,
                             float* __restrict__ out) {
    int i = blockIdx.x * 256 + threadIdx.x;          // 2*589824
    int m = i / 589824;
    int r = i - m * 589824;
    int tap = r >> 16;
    int rem = r & 65535;
    int c   = rem >> 8;
    int oc  = rem & 255;
    const float* w = m ? w1 : w0;
    out[i] = to_tf32(w[oc * 2304 + c * 9 + tap]);
}

__global__ void t1x1_kernel(const float* __restrict__ wq, const float* __restrict__ wk,
                            const float* __restrict__ wv, const float* __restrict__ wp,
                            float* __restrict__ out) {
    int i = blockIdx.x * 256 + threadIdx.x;          // 4*65536
    int m = i >> 16;
    int r = i & 65535;
    int c = r >> 8;
    int o = r & 255;
    const float* w = (m == 0) ? wq : (m == 1) ? wk : (m == 2) ? wv : wp;
    out[i] = to_tf32(w[o * 256 + c]);
}

// ---------------- x transpose: NCHW -> [b][px][c], tf32 ----------------
__global__ void xT_kernel(const float* __restrict__ x, float* __restrict__ xT) {
    __shared__ float t[32][33];
    int b  = blockIdx.z;
    int c0 = blockIdx.y * 32;
    int p0 = blockIdx.x * 32;
    int tx = threadIdx.x, ty = threadIdx.y;
    t[ty][tx] = to_tf32(x[(((size_t)((b << 8) + c0 + ty)) << 16) + p0 + tx]);
    __syncthreads();
    xT[(((size_t)((b << 16) + p0 + ty)) << 8) + c0 + tx] = t[tx][ty];
}

// ---------------- 3x3 conv implicit GEMM, 3-stage pipeline, 1 sync/step ----------------
// CTA 128px x 128oc; K = 48 steps (16 c-chunks of 16 x 3 ky), kx via smem row shift.
// Output channel-last [b][px][oc].
#define CONV_STG 9128    // floats per stage: 130*20 + 3*16*136
__global__ void __launch_bounds__(256, 2) conv_mma(const float* __restrict__ xT,
                                                   const float* __restrict__ W2,
                                                   float* __restrict__ out) {
    extern __shared__ float sm[];
    const int tid  = threadIdx.x;
    const int w    = tid >> 5, lane = tid & 31;
    const int g    = lane >> 2, tg = lane & 3;
    const int y    = blockIdx.x >> 1;
    const int p0   = (blockIdx.x & 1) << 7;
    const int oc0  = blockIdx.y << 7;
    const int b    = blockIdx.z;
    const int wm   = w >> 2, wn = w & 3;
    const uint32_t sm_u = smem_u32(sm);

    float acc[4][4][4];
#pragma unroll
    for (int mi = 0; mi < 4; mi++)
#pragma unroll
        for (int ni = 0; ni < 4; ni++)
#pragma unroll
            for (int r = 0; r < 4; r++) acc[mi][ni][r] = 0.f;

    auto do_load = [&](int step, int buf) {
        int cc = step / 3;
        int ky = step - cc * 3;
        int c0 = cc * 16;
        uint32_t xs_u = sm_u + buf * (CONV_STG * 4);
        uint32_t ws_u = xs_u + 2600 * 4;
        int yin = y + ky - 1;
        bool yok = (unsigned)yin < 256u;
        // x slab: 130 rows x 16 ch (4 x 16B per row)
#pragma unroll
        for (int jj = 0; jj < 3; jj++) {
            int j = jj * 256 + tid;
            if (j < 520) {
                int r = j >> 2, q = j & 3;
                int xin = p0 + r - 1;
                bool ok = yok && ((unsigned)xin < 256u);
                const float* src = ok
                    ? xT + ((((size_t)b << 16) + ((size_t)yin << 8) + xin) << 8) + c0 + q * 4
                    : xT;
                cpa16(xs_u + r * 80 + q * 16, src, ok ? 16u : 0u);
            }
        }
        // weights: 3 kx x [16 c][128 oc]
#pragma unroll
        for (int jj = 0; jj < 6; jj++) {
            int j = jj * 256 + tid;
            int kxc = j >> 5, q = j & 31;         // kxc = kx*16+c (0..47)
            int kx = kxc >> 4, c = kxc & 15;
            int tap = ky * 3 + kx;
            cpa16(ws_u + kxc * 544 + q * 16,
                  W2 + ((size_t)(tap * 256 + c0 + c) << 8) + oc0 + q * 4, 16u);
        }
        CP_COMMIT();
    };

    auto do_compute = [&](int buf) {
        float* Xs = sm + buf * CONV_STG;
        float* Ws = Xs + 2600;
#pragma unroll
        for (int kx = 0; kx < 3; kx++) {
#pragma unroll
            for (int ks = 0; ks < 2; ks++) {
                const int col = ks * 8 + tg;
                uint32_t af[4][4];
#pragma unroll
                for (int mi = 0; mi < 4; mi++) {
                    int r0 = (wm * 64 + mi * 16 + g + kx) * 20 + col;
                    af[mi][0] = __float_as_uint(Xs[r0]);
                    af[mi][1] = __float_as_uint(Xs[r0 + 8 * 20]);
                    af[mi][2] = __float_as_uint(Xs[r0 + 4]);
                    af[mi][3] = __float_as_uint(Xs[r0 + 8 * 20 + 4]);
                }
                uint32_t bf[4][2];
#pragma unroll
                for (int ni = 0; ni < 4; ni++) {
                    int rb = (kx * 16 + col) * 136 + wn * 32 + ni * 8 + g;
                    bf[ni][0] = __float_as_uint(Ws[rb]);
                    bf[ni][1] = __float_as_uint(Ws[rb + 4 * 136]);
                }
#pragma unroll
                for (int mi = 0; mi < 4; mi++)
#pragma unroll
                    for (int ni = 0; ni < 4; ni++)
                        mma8(acc[mi][ni], af[mi], bf[ni]);
            }
        }
    };

    // 3-buffer, 2-deep prefetch, ONE barrier per step:
    // load(s+2) targets buf (s+2)%3, last read at compute(s-1), fenced by this sync.
    do_load(0, 0);
    do_load(1, 1);
    for (int s = 0; s < 48; s++) {
        if (s < 47) { CP_WAIT1(); } else { CP_WAIT0(); }
        __syncthreads();
        if (s + 2 < 48) do_load(s + 2, (s + 2) % 3);
        do_compute(s % 3);
    }
    __syncthreads();   // epilogue smem aliases pipeline buffers

    // epilogue: fragments -> smem S[px][oc] -> channel-last rows
    float* S = sm;   // 128*132 = 16896 floats <= 3*CONV_STG
#pragma unroll
    for (int mi = 0; mi < 4; mi++) {
        int px = wm * 64 + mi * 16 + g;
#pragma unroll
        for (int ni = 0; ni < 4; ni++) {
            int oc = wn * 32 + ni * 8 + 2 * tg;
            S[px * 132 + oc]           = acc[mi][ni][0];
            S[px * 132 + oc + 1]       = acc[mi][ni][1];
            S[(px + 8) * 132 + oc]     = acc[mi][ni][2];
            S[(px + 8) * 132 + oc + 1] = acc[mi][ni][3];
        }
    }
    __syncthreads();
#pragma unroll
    for (int it = 0; it < 16; it++) {
        int px = w + it * 8;
        float4 v = *(float4*)&S[px * 132 + lane * 4];
        *(float4*)&out[(((size_t)((b << 16) + (y << 8) + p0 + px)) << 8) + oc0 + lane * 4] = v;
    }
}

// ---------------- BN stats: deterministic 2-stage, channel-last ----------------
__global__ void bnstats1(const float* __restrict__ conv, float* __restrict__ part) {
    int c = threadIdx.x;
    int j = blockIdx.x;                 // 512 blocks x 256 rows
    size_t r0 = (size_t)j * 256;
    float s = 0.f, s2 = 0.f;
    for (int i = 0; i < 256; i++) {
        float v = conv[(r0 + i) * 256 + c];
        s += v; s2 += v * v;
    }
    part[j * 512 + c]       = s;
    part[j * 512 + 256 + c] = s2;
}

__global__ void bnstats2(const float* __restrict__ part,
                         const float* __restrict__ gamma, const float* __restrict__ beta,
                         float* __restrict__ pa, float* __restrict__ pc) {
    int c = threadIdx.x;
    float s = 0.f, s2 = 0.f;
    for (int j = 0; j < 512; j++) {
        s  += part[j * 512 + c];
        s2 += part[j * 512 + 256 + c];
    }
    float m   = s  * (1.f / 131072.f);
    float var = s2 * (1.f / 131072.f) - m * m;
    float a = gamma[c] * rsqrtf(var + 1e-5f);
    pa[c] = a;
    pc[c] = beta[c] - m * a;
}

// ---------------- depthwise conv, channel-last, BN+relu6 fused, tf32 out,
//                  2 pixels/thread, channel-mean fused ----------------
__global__ void dwconv_t(const float* __restrict__ in,
                         const float* __restrict__ pa, const float* __restrict__ pc,
                         const float* __restrict__ wdw, float* __restrict__ out,
                         float* __restrict__ mean_out) {
    __shared__ float red0[8], red1[8];
    int j = blockIdx.x;          // handles global rows 2j, 2j+1 (same image row)
    int c = threadIdx.x;
    int r0 = j << 1;
    int p  = r0 & 65535;
    int y = p >> 8, xx = p & 255;          // xx even
    size_t bb = (size_t)(r0 - p) << 8;     // batch base (rows) * 256 ch
    float a = pa[c], cb = pc[c];
    float w[9];
#pragma unroll
    for (int t = 0; t < 9; t++) w[t] = wdw[c * 9 + t];
    float acc0 = 0.f, acc1 = 0.f;
#pragma unroll
    for (int ky = 0; ky < 3; ky++) {
        int yy = y + ky - 1;
        if ((unsigned)yy >= 256u) continue;
        float v[4];
#pragma unroll
        for (int dx = 0; dx < 4; dx++) {
            int xv = xx + dx - 1;
            bool ok = (unsigned)xv < 256u;
            float t = ok ? in[bb + (size_t)((yy << 8) + xv) * 256 + c] : 0.f;
            t = fminf(fmaxf(t * a + cb, 0.f), 6.f);
            v[dx] = ok ? t : 0.f;          // invalid tap contributes exact 0
        }
        acc0 = fmaf(w[ky * 3 + 0], v[0], acc0);
        acc0 = fmaf(w[ky * 3 + 1], v[1], acc0);
        acc0 = fmaf(w[ky * 3 + 2], v[2], acc0);
        acc1 = fmaf(w[ky * 3 + 0], v[1], acc1);
        acc1 = fmaf(w[ky * 3 + 1], v[2], acc1);
        acc1 = fmaf(w[ky * 3 + 2], v[3], acc1);
    }
    out[(size_t)r0 * 256 + c]       = to_tf32(acc0);
    out[(size_t)(r0 + 1) * 256 + c] = to_tf32(acc1);

    float s0 = acc0, s1 = acc1;
#pragma unroll
    for (int off = 16; off; off >>= 1) {
        s0 += __shfl_xor_sync(0xffffffffu, s0, off);
        s1 += __shfl_xor_sync(0xffffffffu, s1, off);
    }
    if ((c & 31) == 0) { red0[c >> 5] = s0; red1[c >> 5] = s1; }
    __syncthreads();
    if (c < 8) {
        float t0 = red0[c], t1 = red1[c];
#pragma unroll
        for (int off = 4; off; off >>= 1) {
            t0 += __shfl_xor_sync(0xffu, t0, off);
            t1 += __shfl_xor_sync(0xffu, t1, off);
        }
        if (c == 0) {
            mean_out[r0]     = t0 * (1.f / 256.f);
            mean_out[r0 + 1] = t1 * (1.f / 256.f);
        }
    }
}

// ---------------- 1x1 channel GEMM on tensor cores, 3-stage ----------------
// CTA 128px x 128oc, K=256 (8 chunks). MODE 0: window-layout out. MODE 1: NCHW out.
#define GEMM_STG 8960    // floats per stage: 128*36 + 32*136
template <int MODE>
__global__ void __launch_bounds__(256, 2) gemm_mma(const float* __restrict__ wt,
                                                   const float* __restrict__ in,
                                                   float* __restrict__ out) {
    extern __shared__ float sm[];
    const int tid  = threadIdx.x;
    const int w    = tid >> 5, lane = tid & 31;
    const int g    = lane >> 2, tg = lane & 3;
    const int tile = blockIdx.x;
    const int oc0  = blockIdx.y << 7;
    const int b    = blockIdx.z;
    const int wm   = w >> 2, wn = w & 3;
    const uint32_t sm_u = smem_u32(sm);
    const size_t r0 = ((size_t)b << 16) + (size_t)tile * 128;

    float acc[4][4][4];
#pragma unroll
    for (int mi = 0; mi < 4; mi++)
#pragma unroll
        for (int ni = 0; ni < 4; ni++)
#pragma unroll
            for (int r = 0; r < 4; r++) acc[mi][ni][r] = 0.f;

    auto do_load = [&](int cc, int buf) {
        int c0 = cc * 32;
        uint32_t xs_u = sm_u + buf * (GEMM_STG * 4);
        uint32_t ws_u = xs_u + 4608 * 4;
#pragma unroll
        for (int jj = 0; jj < 4; jj++) {
            int j = jj * 256 + tid;
            int r = j >> 3, q = j & 7;
            cpa16(xs_u + r * 144 + q * 16, in + (r0 + r) * 256 + c0 + q * 4, 16u);
        }
#pragma unroll
        for (int jj = 0; jj < 4; jj++) {
            int j = jj * 256 + tid;
            int c = j >> 5, q = j & 31;
            cpa16(ws_u + c * 544 + q * 16, wt + (size_t)(c0 + c) * 256 + oc0 + q * 4, 16u);
        }
        CP_COMMIT();
    };

    auto do_compute = [&](int buf) {
        float* Xs = sm + buf * GEMM_STG;
        float* Ws = Xs + 4608;
#pragma unroll
        for (int ks = 0; ks < 4; ks++) {
            const int col = ks * 8 + tg;
            uint32_t af[4][4];
#pragma unroll
            for (int mi = 0; mi < 4; mi++) {
                int rr = (wm * 64 + mi * 16 + g) * 36 + col;
                af[mi][0] = __float_as_uint(Xs[rr]);
                af[mi][1] = __float_as_uint(Xs[rr + 8 * 36]);
                af[mi][2] = __float_as_uint(Xs[rr + 4]);
                af[mi][3] = __float_as_uint(Xs[rr + 8 * 36 + 4]);
            }
            uint32_t bf[4][2];
#pragma unroll
            for (int ni = 0; ni < 4; ni++) {
                int rb = col * 136 + wn * 32 + ni * 8 + g;
                bf[ni][0] = __float_as_uint(Ws[rb]);
                bf[ni][1] = __float_as_uint(Ws[rb + 4 * 136]);
            }
#pragma unroll
            for (int mi = 0; mi < 4; mi++)
#pragma unroll
                for (int ni = 0; ni < 4; ni++)
                    mma8(acc[mi][ni], af[mi], bf[ni]);
        }
    };

    do_load(0, 0);
    do_load(1, 1);
    for (int s = 0; s < 8; s++) {
        if (s < 7) { CP_WAIT1(); } else { CP_WAIT0(); }
        __syncthreads();
        if (s + 2 < 8) do_load(s + 2, (s + 2) % 3);
        do_compute(s % 3);
    }
    __syncthreads();   // epilogue smem aliases pipeline buffers

    float* S = sm;
    if (MODE == 0) {
#pragma unroll
        for (int mi = 0; mi < 4; mi++) {
            int px = wm * 64 + mi * 16 + g;
#pragma unroll
            for (int ni = 0; ni < 4; ni++) {
                int oc = wn * 32 + ni * 8 + 2 * tg;
                S[px * 132 + oc]           = acc[mi][ni][0];
                S[px * 132 + oc + 1]       = acc[mi][ni][1];
                S[(px + 8) * 132 + oc]     = acc[mi][ni][2];
                S[(px + 8) * 132 + oc + 1] = acc[mi][ni][3];
            }
        }
        __syncthreads();
#pragma unroll
        for (int s2 = tid; s2 < 512; s2 += 256) {
            int px = s2 >> 2, seg = s2 & 3;
            int gp = tile * 128 + px;
            int y = gp >> 8, x = gp & 255;
            int win = ((y >> 3) << 5) + (x >> 3);
            int pix = ((y & 7) << 3) + (x & 7);
            int h = (oc0 >> 5) + seg;
            size_t dst = (((size_t)(b * 8 + h)) << 21) + ((size_t)win << 11) + (pix << 5);
            float4* src = (float4*)&S[px * 132 + seg * 32];
            float4* d4  = (float4*)&out[dst];
#pragma unroll
            for (int k = 0; k < 8; k++) d4[k] = src[k];
        }
    } else {
#pragma unroll
        for (int mi = 0; mi < 4; mi++) {
            int px = wm * 64 + mi * 16 + g;
#pragma unroll
            for (int ni = 0; ni < 4; ni++) {
                int oc = wn * 32 + ni * 8 + 2 * tg;
                S[oc * 132 + px]           = acc[mi][ni][0];
                S[(oc + 1) * 132 + px]     = acc[mi][ni][1];
                S[oc * 132 + px + 8]       = acc[mi][ni][2];
                S[(oc + 1) * 132 + px + 8] = acc[mi][ni][3];
            }
        }
        __syncthreads();
#pragma unroll
        for (int it = 0; it < 16; it++) {
            int oc = w + it * 8;
            float4 v = *(float4*)&S[oc * 132 + lane * 4];
            *(float4*)&out[(((size_t)(b * 256 + oc0 + oc)) << 16) + tile * 128 + lane * 4] = v;
        }
    }
}

// ---------------- windowed attention (packed f32x2; out channel-last tf32) ----------------
__global__ void __launch_bounds__(64) attn_kernel(const float* __restrict__ q,
                                                  const float* __restrict__ k,
                                                  const float* __restrict__ v,
                                                  const float* __restrict__ is,
                                                  const float* __restrict__ ns,
                                                  const float* __restrict__ temp,
                                                  float* __restrict__ out) {
    __shared__ __align__(16) float ks[64][32];
    __shared__ __align__(16) float vs[64][32];
    __shared__ float sc[64][65];
    const int i   = threadIdx.x;
    const int win = blockIdx.x;
    const int h   = blockIdx.y;
    const int b   = blockIdx.z;
    const size_t base = (((size_t)(b * 8 + h)) << 21) + ((size_t)win << 11);

    const int y = ((win >> 5) << 3) + (i >> 3);
    const int x = ((win & 31) << 3) + (i & 7);
    const int pidx = (b << 16) + (y << 8) + x;

    // k, v rows (float4)
    const float4* kp4 = (const float4*)(k + base + ((size_t)i << 5));
    const float4* vp4 = (const float4*)(v + base + ((size_t)i << 5));
    float kr[32];
    float kn = 0.f;
#pragma unroll
    for (int t = 0; t < 8; t++) {
        float4 kv = kp4[t];
        kr[4*t]   = kv.x; kr[4*t+1] = kv.y; kr[4*t+2] = kv.z; kr[4*t+3] = kv.w;
        kn = fmaf(kv.x, kv.x, kn); kn = fmaf(kv.y, kv.y, kn);
        kn = fmaf(kv.z, kv.z, kn); kn = fmaf(kv.w, kv.w, kn);
        *(float4*)&vs[i][4*t] = vp4[t];
    }
    float nsv = ns[pidx];
    float kmul = fminf(fmaxf(1.f - nsv, 0.f), 1.f) / fmaxf(sqrtf(kn), 1e-12f);
#pragma unroll
    for (int t = 0; t < 8; t++) {
        float4 o = {kr[4*t] * kmul, kr[4*t+1] * kmul, kr[4*t+2] * kmul, kr[4*t+3] * kmul};
        *(float4*)&ks[i][4*t] = o;
    }

    // q row
    const float4* qp4 = (const float4*)(q + base + ((size_t)i << 5));
    float qr[32];
    float qn = 0.f;
#pragma unroll
    for (int t = 0; t < 8; t++) {
        float4 qv = qp4[t];
        qr[4*t]   = qv.x; qr[4*t+1] = qv.y; qr[4*t+2] = qv.z; qr[4*t+3] = qv.w;
        qn = fmaf(qv.x, qv.x, qn); qn = fmaf(qv.y, qv.y, qn);
        qn = fmaf(qv.z, qv.z, qn); qn = fmaf(qv.w, qv.w, qn);
    }
    float qmul = (1.f + is[pidx]) / fmaxf(sqrtf(qn), 1e-12f)
               * 0.17677669529663687f * temp[h];
    unsigned long long qp[16];
#pragma unroll
    for (int t = 0; t < 16; t++)
        qp[t] = pack2(qr[2*t] * qmul, qr[2*t+1] * qmul);

    __syncthreads();

    // scores: packed dot products, 2 split accumulators per j
    float mx = -1e30f;
#pragma unroll 4
    for (int j = 0; j < 64; j++) {
        const unsigned long long* kj = (const unsigned long long*)ks[j];
        unsigned long long a0 = 0ULL, a1 = 0ULL;
#pragma unroll
        for (int t = 0; t < 8; t++) {
            ffma2(a0, qp[2*t],     kj[2*t]);
            ffma2(a1, qp[2*t + 1], kj[2*t + 1]);
        }
        float l0, h0, l1, h1;
        unpack2(a0, l0, h0);
        unpack2(a1, l1, h1);
        float s = (l0 + h0) + (l1 + h1);
        sc[i][j] = s;
        mx = fmaxf(mx, s);
    }
    float sum = 0.f;
#pragma unroll
    for (int j = 0; j < 64; j++) {
        float e = __expf(sc[i][j] - mx);
        sc[i][j] = e;
        sum += e;
    }
    float inv = 1.f / sum;

    // PV: 16 independent packed accumulators
    unsigned long long av[16];
#pragma unroll
    for (int t = 0; t < 16; t++) av[t] = 0ULL;
#pragma unroll 4
    for (int j = 0; j < 64; j++) {
        float p = sc[i][j];
        unsigned long long pp = pack2(p, p);
        const unsigned long long* vj = (const unsigned long long*)vs[j];
#pragma unroll
        for (int t = 0; t < 16; t++) ffma2(av[t], pp, vj[t]);
    }

    size_t obase = ((size_t)pidx << 8) + (h << 5);
#pragma unroll
    for (int t = 0; t < 8; t++) {
        float l0, h0, l1, h1;
        unpack2(av[2*t],     l0, h0);
        unpack2(av[2*t + 1], l1, h1);
        float4 o = {to_tf32(l0 * inv), to_tf32(h0 * inv),
                    to_tf32(l1 * inv), to_tf32(h1 * inv)};
        *(float4*)&out[obase + 4*t] = o;
    }
}

// ---------------- launch ----------------
extern "C" void kernel_launch(void* const* d_in, const int* in_sizes, int n_in,
                              void* d_out, int out_size) {
    const float* x      = (const float*)d_in[0];
    const float* w_iem  = (const float*)d_in[1];
    const float* g_iem  = (const float*)d_in[2];
    const float* b_iem  = (const float*)d_in[3];
    const float* w_nem  = (const float*)d_in[4];
    const float* g_nem  = (const float*)d_in[5];
    const float* b_nem  = (const float*)d_in[6];
    const float* w_idw  = (const float*)d_in[7];
    const float* w_ndw  = (const float*)d_in[8];
    const float* w_q    = (const float*)d_in[9];
    const float* w_k    = (const float*)d_in[10];
    const float* w_v    = (const float*)d_in[11];
    const float* w_proj = (const float*)d_in[12];
    const float* temp   = (const float*)d_in[13];
    float* out = (float*)d_out;

    float *A, *B, *C, *D, *X, *WCT, *WT4, *PART, *BNA, *BNC, *IS, *NS;
    cudaGetSymbolAddress((void**)&A,    g_A);
    cudaGetSymbolAddress((void**)&B,    g_B);
    cudaGetSymbolAddress((void**)&C,    g_C);
    cudaGetSymbolAddress((void**)&D,    g_D);
    cudaGetSymbolAddress((void**)&X,    g_X);
    cudaGetSymbolAddress((void**)&WCT,  g_wct);
    cudaGetSymbolAddress((void**)&WT4,  g_wt4);
    cudaGetSymbolAddress((void**)&PART, g_part);
    cudaGetSymbolAddress((void**)&BNA,  g_bna);
    cudaGetSymbolAddress((void**)&BNC,  g_bnc);
    cudaGetSymbolAddress((void**)&IS,   g_is);
    cudaGetSymbolAddress((void**)&NS,   g_ns);

    const int CSM = CONV_STG * 4 * 3;   // 109536
    const int GSM = GEMM_STG * 4 * 3;   // 107520
    cudaFuncSetAttribute(conv_mma,    cudaFuncAttributeMaxDynamicSharedMemorySize, CSM);
    cudaFuncSetAttribute(gemm_mma<0>, cudaFuncAttributeMaxDynamicSharedMemorySize, GSM);
    cudaFuncSetAttribute(gemm_mma<1>, cudaFuncAttributeMaxDynamicSharedMemorySize, GSM);

    tconv_kernel<<<4608, 256>>>(w_iem, w_nem, WCT);
    t1x1_kernel<<<1024, 256>>>(w_q, w_k, w_v, w_proj, WT4);
    xT_kernel<<<dim3(2048, 8, 2), dim3(32, 32)>>>(x, X);

    dim3 cg(512, 2, 2);
    conv_mma<<<cg, 256, CSM>>>(X, WCT,          A);
    conv_mma<<<cg, 256, CSM>>>(X, WCT + 589824, B);

    bnstats1<<<512, 256>>>(A, PART);
    bnstats2<<<1, 256>>>(PART, g_iem, b_iem, BNA, BNC);
    bnstats1<<<512, 256>>>(B, PART);
    bnstats2<<<1, 256>>>(PART, g_nem, b_nem, BNA + 256, BNC + 256);

    dwconv_t<<<65536, 256>>>(A, BNA,       BNC,       w_idw, C, IS);
    dwconv_t<<<65536, 256>>>(B, BNA + 256, BNC + 256, w_ndw, D, NS);

    gemm_mma<0><<<cg, 256, GSM>>>(WT4,              C, A);   // q
    gemm_mma<0><<<cg, 256, GSM>>>(WT4 + 65536,      D, B);   // k
    gemm_mma<0><<<cg, 256, GSM>>>(WT4 + 2 * 65536,  X, C);   // v

    attn_kernel<<<dim3(1024, 8, 2), 64>>>(A, B, C, IS, NS, temp, D);

    gemm_mma<1><<<cg, 256, GSM>>>(WT4 + 3 * 65536,  D, out); // proj -> NCHW
}

// round 9
// speedup vs baseline: 4.3202x; 1.2117x over previous
#include <cuda_runtime.h>
#include <cuda_fp16.h>
#include <math.h>
#include <stdint.h>

#define HW 65536
#define NBUF (2*256*HW)

// ---------------- static scratch ----------------
__device__ float  g_A[NBUF];        // conv_iem raw [r][c] -> q (window layout)
__device__ float  g_B[NBUF];        // conv_nem raw [r][c] -> k (window layout)
__device__ float  g_C[NBUF];        // v (window layout)
__device__ __half g_Xh[NBUF];       // x [b][px][c] fp16
__device__ __half g_H1[NBUF];       // illum map [r][c] fp16
__device__ __half g_H2[NBUF];       // noise map [r][c] fp16
__device__ __half g_H3[NBUF];       // attn out [r][c] fp16
__device__ __half g_wct[2*589824];  // conv weights [m][tap][oc][c] fp16
__device__ __half g_wt4[4*65536];   // 1x1 weights [m][oc][c] fp16
__device__ float  g_part[524288];   // bn partials [512 blk][2][256 ch]
__device__ float  g_bna[512];
__device__ float  g_bnc[512];
__device__ float  g_is[2*HW];
__device__ float  g_ns[2*HW];

// ---------------- helpers ----------------
__device__ __forceinline__ void ffma2(unsigned long long& d, unsigned long long a,
                                      unsigned long long b) {
    asm("fma.rn.f32x2 %0, %1, %2, %0;" : "+l"(d) : "l"(a), "l"(b));
}
__device__ __forceinline__ unsigned long long pack2(float lo, float hi) {
    unsigned long long r;
    asm("mov.b64 %0, {%1, %2};" : "=l"(r) : "f"(lo), "f"(hi));
    return r;
}
__device__ __forceinline__ void unpack2(unsigned long long p, float& lo, float& hi) {
    asm("mov.b64 {%0, %1}, %2;" : "=f"(lo), "=f"(hi) : "l"(p));
}
__device__ __forceinline__ uint32_t smem_u32(const void* p) {
    uint32_t a;
    asm("{ .reg .u64 t; cvta.to.shared.u64 t, %1; cvt.u32.u64 %0, t; }" : "=r"(a) : "l"(p));
    return a;
}
__device__ __forceinline__ void cpa16(uint32_t s, const void* g, uint32_t n) {
    asm volatile("cp.async.cg.shared.global [%0], [%1], 16, %2;"
                 :: "r"(s), "l"(g), "r"(n) : "memory");
}
#define CP_COMMIT()  asm volatile("cp.async.commit_group;" ::: "memory")
#define CP_WAIT2()   asm volatile("cp.async.wait_group 2;" ::: "memory")
#define CP_WAIT1()   asm volatile("cp.async.wait_group 1;" ::: "memory")
#define CP_WAIT0()   asm volatile("cp.async.wait_group 0;" ::: "memory")

// fp16 m16n8k16 mma, fp32 accumulate (family-portable HMMA)
__device__ __forceinline__ void mma16(float* d, const uint32_t* a, const uint32_t* b) {
    asm volatile("mma.sync.aligned.m16n8k16.row.col.f32.f16.f16.f32 "
        "{%0,%1,%2,%3}, {%4,%5,%6,%7}, {%8,%9}, {%0,%1,%2,%3};"
        : "+f"(d[0]), "+f"(d[1]), "+f"(d[2]), "+f"(d[3])
        : "r"(a[0]), "r"(a[1]), "r"(a[2]), "r"(a[3]), "r"(b[0]), "r"(b[1]));
}

// ---------------- weight prep ----------------
// conv weights: [m][tap][oc][c] fp16
__global__ void tconv_kernel(const float* __restrict__ w0, const float* __restrict__ w1,
                             __half* __restrict__ out) {
    int i = blockIdx.x * 256 + threadIdx.x;          // 2*589824
    int m = i / 589824;
    int r = i - m * 589824;
    int tap = r >> 16;
    int rem = r & 65535;
    int oc  = rem >> 8;
    int c   = rem & 255;
    const float* w = m ? w1 : w0;
    out[i] = __float2half_rn(w[oc * 2304 + c * 9 + tap]);
}

// 1x1 weights: [m][oc][c] fp16
__global__ void t1x1_kernel(const float* __restrict__ wq, const float* __restrict__ wk,
                            const float* __restrict__ wv, const float* __restrict__ wp,
                            __half* __restrict__ out) {
    int i = blockIdx.x * 256 + threadIdx.x;          // 4*65536
    int m = i >> 16;
    int r = i & 65535;
    int o = r >> 8;
    int c = r & 255;
    const float* w = (m == 0) ? wq : (m == 1) ? wk : (m == 2) ? wv : wp;
    out[i] = __float2half_rn(w[o * 256 + c]);
}

// ---------------- x transpose: NCHW -> [b][px][c] fp16 ----------------
__global__ void xT_kernel(const float* __restrict__ x, __half* __restrict__ xT) {
    __shared__ float t[32][33];
    int b  = blockIdx.z;
    int c0 = blockIdx.y * 32;
    int p0 = blockIdx.x * 32;
    int tx = threadIdx.x, ty = threadIdx.y;
    t[ty][tx] = x[(((size_t)((b << 8) + c0 + ty)) << 16) + p0 + tx];
    __syncthreads();
    xT[(((size_t)((b << 16) + p0 + ty)) << 8) + c0 + tx] = __float2half_rn(t[tx][ty]);
}

// ---------------- 3x3 conv implicit GEMM (fp16 mma), 4-stage/3-deep ----------------
// CTA 128px x 128oc; K = 48 steps (16 chunks of 16ch x 3 ky); kx via smem row shift.
// Xs: [130 px][24 halves] (48B rows, conflict-free); Ws: [3kx][128 oc][24 halves].
#define CONV_STG_B 24672     // 130*48 + 3*128*48
#define CONV_XS_B  6240
__global__ void __launch_bounds__(256, 2) conv_mma(const __half* __restrict__ xT,
                                                   const __half* __restrict__ W2,
                                                   float* __restrict__ out) {
    extern __shared__ char smc[];
    const int tid  = threadIdx.x;
    const int w    = tid >> 5, lane = tid & 31;
    const int g    = lane >> 2, tg = lane & 3;
    const int y    = blockIdx.x >> 1;
    const int p0   = (blockIdx.x & 1) << 7;
    const int oc0  = blockIdx.y << 7;
    const int b    = blockIdx.z;
    const int wm   = w >> 2, wn = w & 3;
    const uint32_t sm_u = smem_u32(smc);

    float acc[4][4][4];
#pragma unroll
    for (int mi = 0; mi < 4; mi++)
#pragma unroll
        for (int ni = 0; ni < 4; ni++)
#pragma unroll
            for (int r = 0; r < 4; r++) acc[mi][ni][r] = 0.f;

    auto do_load = [&](int step, int buf) {
        int cc = step / 3;
        int ky = step - cc * 3;
        int c0 = cc * 16;
        uint32_t xs_u = sm_u + buf * CONV_STG_B;
        uint32_t ws_u = xs_u + CONV_XS_B;
        int yin = y + ky - 1;
        bool yok = (unsigned)yin < 256u;
        // X slab: 130 rows x 16 halves (2 x 16B per row)
#pragma unroll
        for (int jj = 0; jj < 2; jj++) {
            int j = jj * 256 + tid;
            if (j < 260) {
                int r = j >> 1, q = j & 1;
                int xin = p0 + r - 1;
                bool ok = yok && ((unsigned)xin < 256u);
                const __half* src = ok
                    ? xT + ((((size_t)b << 16) + ((size_t)yin << 8) + xin) << 8) + c0 + q * 8
                    : xT;
                cpa16(xs_u + r * 48 + q * 16, src, ok ? 16u : 0u);
            }
        }
        // W: 3 kx x [128 oc][16 halves]
#pragma unroll
        for (int jj = 0; jj < 3; jj++) {
            int j = jj * 256 + tid;
            int koc = j >> 1, q = j & 1;          // koc = kx*128+oc
            int kx = koc >> 7, oc = koc & 127;
            int tap = ky * 3 + kx;
            cpa16(ws_u + koc * 48 + q * 16,
                  W2 + (((size_t)(tap * 256 + oc0 + oc)) << 8) + c0 + q * 8, 16u);
        }
        CP_COMMIT();
    };

    auto do_compute = [&](int buf) {
        const char* Xs = smc + buf * CONV_STG_B;
        const char* Ws = Xs + CONV_XS_B;
#pragma unroll
        for (int kx = 0; kx < 3; kx++) {
            uint32_t af[4][4];
#pragma unroll
            for (int mi = 0; mi < 4; mi++) {
                const char* rp = Xs + (wm * 64 + mi * 16 + g + kx) * 48 + tg * 4;
                af[mi][0] = *(const uint32_t*)(rp);
                af[mi][1] = *(const uint32_t*)(rp + 8 * 48);
                af[mi][2] = *(const uint32_t*)(rp + 16);
                af[mi][3] = *(const uint32_t*)(rp + 8 * 48 + 16);
            }
            uint32_t bf[4][2];
#pragma unroll
            for (int ni = 0; ni < 4; ni++) {
                const char* bp = Ws + (kx * 128 + wn * 32 + ni * 8 + g) * 48 + tg * 4;
                bf[ni][0] = *(const uint32_t*)(bp);
                bf[ni][1] = *(const uint32_t*)(bp + 16);
            }
#pragma unroll
            for (int mi = 0; mi < 4; mi++)
#pragma unroll
                for (int ni = 0; ni < 4; ni++)
                    mma16(acc[mi][ni], af[mi], bf[ni]);
        }
    };

    do_load(0, 0);
    do_load(1, 1);
    do_load(2, 2);
    for (int s = 0; s < 48; s++) {
        if (s < 46) { CP_WAIT2(); } else if (s == 46) { CP_WAIT1(); } else { CP_WAIT0(); }
        __syncthreads();
        if (s + 3 < 48) do_load(s + 3, (s + 3) & 3);
        do_compute(s & 3);
    }
    __syncthreads();   // epilogue smem aliases pipeline buffers

    // epilogue: fragments -> smem S[px][oc] -> channel-last fp32 rows
    float* S = (float*)smc;     // 128*132*4 = 67584 <= 4*CONV_STG_B
#pragma unroll
    for (int mi = 0; mi < 4; mi++) {
        int px = wm * 64 + mi * 16 + g;
#pragma unroll
        for (int ni = 0; ni < 4; ni++) {
            int oc = wn * 32 + ni * 8 + 2 * tg;
            S[px * 132 + oc]           = acc[mi][ni][0];
            S[px * 132 + oc + 1]       = acc[mi][ni][1];
            S[(px + 8) * 132 + oc]     = acc[mi][ni][2];
            S[(px + 8) * 132 + oc + 1] = acc[mi][ni][3];
        }
    }
    __syncthreads();
#pragma unroll
    for (int it = 0; it < 16; it++) {
        int px = w + it * 8;
        float4 v = *(float4*)&S[px * 132 + lane * 4];
        *(float4*)&out[(((size_t)((b << 16) + (y << 8) + p0 + px)) << 8) + oc0 + lane * 4] = v;
    }
}

// ---------------- BN stats: deterministic 2-stage, channel-last ----------------
__global__ void bnstats1(const float* __restrict__ conv, float* __restrict__ part) {
    int c = threadIdx.x;
    int j = blockIdx.x;                 // 512 blocks x 256 rows
    size_t r0 = (size_t)j * 256;
    float s = 0.f, s2 = 0.f;
    for (int i = 0; i < 256; i++) {
        float v = conv[(r0 + i) * 256 + c];
        s += v; s2 += v * v;
    }
    part[j * 512 + c]       = s;
    part[j * 512 + 256 + c] = s2;
}

__global__ void bnstats2(const float* __restrict__ part,
                         const float* __restrict__ gamma, const float* __restrict__ beta,
                         float* __restrict__ pa, float* __restrict__ pc) {
    int c = threadIdx.x;
    float s = 0.f, s2 = 0.f;
    for (int j = 0; j < 512; j++) {
        s  += part[j * 512 + c];
        s2 += part[j * 512 + 256 + c];
    }
    float m   = s  * (1.f / 131072.f);
    float var = s2 * (1.f / 131072.f) - m * m;
    float a = gamma[c] * rsqrtf(var + 1e-5f);
    pa[c] = a;
    pc[c] = beta[c] - m * a;
}

// ---------------- depthwise conv, channel-last, BN+relu6 fused, fp16 out,
//                  2 pixels/thread, channel-mean fused ----------------
__global__ void dwconv_t(const float* __restrict__ in,
                         const float* __restrict__ pa, const float* __restrict__ pc,
                         const float* __restrict__ wdw, __half* __restrict__ out,
                         float* __restrict__ mean_out) {
    __shared__ float red0[8], red1[8];
    int j = blockIdx.x;          // handles global rows 2j, 2j+1 (same image row)
    int c = threadIdx.x;
    int r0 = j << 1;
    int p  = r0 & 65535;
    int y = p >> 8, xx = p & 255;          // xx even
    size_t bb = (size_t)(r0 - p) << 8;     // batch base
    float a = pa[c], cb = pc[c];
    float w[9];
#pragma unroll
    for (int t = 0; t < 9; t++) w[t] = wdw[c * 9 + t];
    float acc0 = 0.f, acc1 = 0.f;
#pragma unroll
    for (int ky = 0; ky < 3; ky++) {
        int yy = y + ky - 1;
        if ((unsigned)yy >= 256u) continue;
        float v[4];
#pragma unroll
        for (int dx = 0; dx < 4; dx++) {
            int xv = xx + dx - 1;
            bool ok = (unsigned)xv < 256u;
            float t = ok ? in[bb + (size_t)((yy << 8) + xv) * 256 + c] : 0.f;
            t = fminf(fmaxf(t * a + cb, 0.f), 6.f);
            v[dx] = ok ? t : 0.f;
        }
        acc0 = fmaf(w[ky * 3 + 0], v[0], acc0);
        acc0 = fmaf(w[ky * 3 + 1], v[1], acc0);
        acc0 = fmaf(w[ky * 3 + 2], v[2], acc0);
        acc1 = fmaf(w[ky * 3 + 0], v[1], acc1);
        acc1 = fmaf(w[ky * 3 + 1], v[2], acc1);
        acc1 = fmaf(w[ky * 3 + 2], v[3], acc1);
    }
    out[(size_t)r0 * 256 + c]       = __float2half_rn(acc0);
    out[(size_t)(r0 + 1) * 256 + c] = __float2half_rn(acc1);

    float s0 = acc0, s1 = acc1;
#pragma unroll
    for (int off = 16; off; off >>= 1) {
        s0 += __shfl_xor_sync(0xffffffffu, s0, off);
        s1 += __shfl_xor_sync(0xffffffffu, s1, off);
    }
    if ((c & 31) == 0) { red0[c >> 5] = s0; red1[c >> 5] = s1; }
    __syncthreads();
    if (c < 8) {
        float t0 = red0[c], t1 = red1[c];
#pragma unroll
        for (int off = 4; off; off >>= 1) {
            t0 += __shfl_xor_sync(0xffu, t0, off);
            t1 += __shfl_xor_sync(0xffu, t1, off);
        }
        if (c == 0) {
            mean_out[r0]     = t0 * (1.f / 256.f);
            mean_out[r0 + 1] = t1 * (1.f / 256.f);
        }
    }
}

// ---------------- 1x1 channel GEMM (fp16 mma), 4-stage/3-deep ----------------
// CTA 128px x 128oc, K=256 (16 chunks of 16).
// MODE 0: window-layout fp32 out. MODE 1: NCHW fp32 out.
#define GEMM_STG_B 12288     // 128*48 + 128*48
template <int MODE>
__global__ void __launch_bounds__(256, 2) gemm_mma(const __half* __restrict__ wt,
                                                   const __half* __restrict__ in,
                                                   float* __restrict__ out) {
    extern __shared__ char smc[];
    const int tid  = threadIdx.x;
    const int w    = tid >> 5, lane = tid & 31;
    const int g    = lane >> 2, tg = lane & 3;
    const int tile = blockIdx.x;
    const int oc0  = blockIdx.y << 7;
    const int b    = blockIdx.z;
    const int wm   = w >> 2, wn = w & 3;
    const uint32_t sm_u = smem_u32(smc);
    const size_t r0 = ((size_t)b << 16) + (size_t)tile * 128;

    float acc[4][4][4];
#pragma unroll
    for (int mi = 0; mi < 4; mi++)
#pragma unroll
        for (int ni = 0; ni < 4; ni++)
#pragma unroll
            for (int r = 0; r < 4; r++) acc[mi][ni][r] = 0.f;

    auto do_load = [&](int cc, int buf) {
        int c0 = cc * 16;
        uint32_t xs_u = sm_u + buf * GEMM_STG_B;
        uint32_t ws_u = xs_u + 6144;
        {
            int r = tid >> 1, q = tid & 1;
            cpa16(xs_u + r * 48 + q * 16, in + (r0 + r) * 256 + c0 + q * 8, 16u);
            cpa16(ws_u + r * 48 + q * 16, wt + (size_t)(oc0 + r) * 256 + c0 + q * 8, 16u);
        }
        CP_COMMIT();
    };

    auto do_compute = [&](int buf) {
        const char* Xs = smc + buf * GEMM_STG_B;
        const char* Ws = Xs + 6144;
        uint32_t af[4][4];
#pragma unroll
        for (int mi = 0; mi < 4; mi++) {
            const char* rp = Xs + (wm * 64 + mi * 16 + g) * 48 + tg * 4;
            af[mi][0] = *(const uint32_t*)(rp);
            af[mi][1] = *(const uint32_t*)(rp + 8 * 48);
            af[mi][2] = *(const uint32_t*)(rp + 16);
            af[mi][3] = *(const uint32_t*)(rp + 8 * 48 + 16);
        }
        uint32_t bf[4][2];
#pragma unroll
        for (int ni = 0; ni < 4; ni++) {
            const char* bp = Ws + (wn * 32 + ni * 8 + g) * 48 + tg * 4;
            bf[ni][0] = *(const uint32_t*)(bp);
            bf[ni][1] = *(const uint32_t*)(bp + 16);
        }
#pragma unroll
        for (int mi = 0; mi < 4; mi++)
#pragma unroll
            for (int ni = 0; ni < 4; ni++)
                mma16(acc[mi][ni], af[mi], bf[ni]);
    };

    do_load(0, 0);
    do_load(1, 1);
    do_load(2, 2);
    for (int s = 0; s < 16; s++) {
        if (s < 14) { CP_WAIT2(); } else if (s == 14) { CP_WAIT1(); } else { CP_WAIT0(); }
        __syncthreads();
        if (s + 3 < 16) do_load(s + 3, (s + 3) & 3);
        do_compute(s & 3);
    }
    __syncthreads();   // epilogue smem aliases pipeline buffers

    float* S = (float*)smc;
    if (MODE == 0) {
#pragma unroll
        for (int mi = 0; mi < 4; mi++) {
            int px = wm * 64 + mi * 16 + g;
#pragma unroll
            for (int ni = 0; ni < 4; ni++) {
                int oc = wn * 32 + ni * 8 + 2 * tg;
                S[px * 132 + oc]           = acc[mi][ni][0];
                S[px * 132 + oc + 1]       = acc[mi][ni][1];
                S[(px + 8) * 132 + oc]     = acc[mi][ni][2];
                S[(px + 8) * 132 + oc + 1] = acc[mi][ni][3];
            }
        }
        __syncthreads();
#pragma unroll
        for (int s2 = tid; s2 < 512; s2 += 256) {
            int px = s2 >> 2, seg = s2 & 3;
            int gp = tile * 128 + px;
            int y = gp >> 8, x = gp & 255;
            int win = ((y >> 3) << 5) + (x >> 3);
            int pix = ((y & 7) << 3) + (x & 7);
            int h = (oc0 >> 5) + seg;
            size_t dst = (((size_t)(b * 8 + h)) << 21) + ((size_t)win << 11) + (pix << 5);
            float4* src = (float4*)&S[px * 132 + seg * 32];
            float4* d4  = (float4*)&out[dst];
#pragma unroll
            for (int k = 0; k < 8; k++) d4[k] = src[k];
        }
    } else {
#pragma unroll
        for (int mi = 0; mi < 4; mi++) {
            int px = wm * 64 + mi * 16 + g;
#pragma unroll
            for (int ni = 0; ni < 4; ni++) {
                int oc = wn * 32 + ni * 8 + 2 * tg;
                S[oc * 132 + px]           = acc[mi][ni][0];
                S[(oc + 1) * 132 + px]     = acc[mi][ni][1];
                S[oc * 132 + px + 8]       = acc[mi][ni][2];
                S[(oc + 1) * 132 + px + 8] = acc[mi][ni][3];
            }
        }
        __syncthreads();
#pragma unroll
        for (int it = 0; it < 16; it++) {
            int oc = w + it * 8;
            float4 v = *(float4*)&S[oc * 132 + lane * 4];
            *(float4*)&out[(((size_t)(b * 256 + oc0 + oc)) << 16) + tile * 128 + lane * 4] = v;
        }
    }
}

// ---------------- windowed attention (f32x2 math; fp16 channel-last out) ----------------
__global__ void __launch_bounds__(64) attn_kernel(const float* __restrict__ q,
                                                  const float* __restrict__ k,
                                                  const float* __restrict__ v,
                                                  const float* __restrict__ is,
                                                  const float* __restrict__ ns,
                                                  const float* __restrict__ temp,
                                                  __half* __restrict__ out) {
    __shared__ __align__(16) float ks[64][32];
    __shared__ __align__(16) float vs[64][32];
    __shared__ float sc[64][65];
    const int i   = threadIdx.x;
    const int win = blockIdx.x;
    const int h   = blockIdx.y;
    const int b   = blockIdx.z;
    const size_t base = (((size_t)(b * 8 + h)) << 21) + ((size_t)win << 11);

    const int y = ((win >> 5) << 3) + (i >> 3);
    const int x = ((win & 31) << 3) + (i & 7);
    const int pidx = (b << 16) + (y << 8) + x;

    const float4* kp4 = (const float4*)(k + base + ((size_t)i << 5));
    const float4* vp4 = (const float4*)(v + base + ((size_t)i << 5));
    float kr[32];
    float kn = 0.f;
#pragma unroll
    for (int t = 0; t < 8; t++) {
        float4 kv = kp4[t];
        kr[4*t]   = kv.x; kr[4*t+1] = kv.y; kr[4*t+2] = kv.z; kr[4*t+3] = kv.w;
        kn = fmaf(kv.x, kv.x, kn); kn = fmaf(kv.y, kv.y, kn);
        kn = fmaf(kv.z, kv.z, kn); kn = fmaf(kv.w, kv.w, kn);
        *(float4*)&vs[i][4*t] = vp4[t];
    }
    float nsv = ns[pidx];
    float kmul = fminf(fmaxf(1.f - nsv, 0.f), 1.f) / fmaxf(sqrtf(kn), 1e-12f);
#pragma unroll
    for (int t = 0; t < 8; t++) {
        float4 o = {kr[4*t] * kmul, kr[4*t+1] * kmul, kr[4*t+2] * kmul, kr[4*t+3] * kmul};
        *(float4*)&ks[i][4*t] = o;
    }

    const float4* qp4 = (const float4*)(q + base + ((size_t)i << 5));
    float qr[32];
    float qn = 0.f;
#pragma unroll
    for (int t = 0; t < 8; t++) {
        float4 qv = qp4[t];
        qr[4*t]   = qv.x; qr[4*t+1] = qv.y; qr[4*t+2] = qv.z; qr[4*t+3] = qv.w;
        qn = fmaf(qv.x, qv.x, qn); qn = fmaf(qv.y, qv.y, qn);
        qn = fmaf(qv.z, qv.z, qn); qn = fmaf(qv.w, qv.w, qn);
    }
    float qmul = (1.f + is[pidx]) / fmaxf(sqrtf(qn), 1e-12f)
               * 0.17677669529663687f * temp[h];
    unsigned long long qp[16];
#pragma unroll
    for (int t = 0; t < 16; t++)
        qp[t] = pack2(qr[2*t] * qmul, qr[2*t+1] * qmul);

    __syncthreads();

    float mx = -1e30f;
#pragma unroll 4
    for (int j = 0; j < 64; j++) {
        const unsigned long long* kj = (const unsigned long long*)ks[j];
        unsigned long long a0 = 0ULL, a1 = 0ULL;
#pragma unroll
        for (int t = 0; t < 8; t++) {
            ffma2(a0, qp[2*t],     kj[2*t]);
            ffma2(a1, qp[2*t + 1], kj[2*t + 1]);
        }
        float l0, h0, l1, h1;
        unpack2(a0, l0, h0);
        unpack2(a1, l1, h1);
        float s = (l0 + h0) + (l1 + h1);
        sc[i][j] = s;
        mx = fmaxf(mx, s);
    }
    float sum = 0.f;
#pragma unroll
    for (int j = 0; j < 64; j++) {
        float e = __expf(sc[i][j] - mx);
        sc[i][j] = e;
        sum += e;
    }
    float inv = 1.f / sum;

    unsigned long long av[16];
#pragma unroll
    for (int t = 0; t < 16; t++) av[t] = 0ULL;
#pragma unroll 4
    for (int j = 0; j < 64; j++) {
        float p = sc[i][j];
        unsigned long long pp = pack2(p, p);
        const unsigned long long* vj = (const unsigned long long*)vs[j];
#pragma unroll
        for (int t = 0; t < 16; t++) ffma2(av[t], pp, vj[t]);
    }

    __half2* o2 = (__half2*)(out + (((size_t)pidx) << 8) + (h << 5));
#pragma unroll
    for (int t = 0; t < 16; t++) {
        float l, hh;
        unpack2(av[t], l, hh);
        o2[t] = __floats2half2_rn(l * inv, hh * inv);
    }
}

// ---------------- launch ----------------
extern "C" void kernel_launch(void* const* d_in, const int* in_sizes, int n_in,
                              void* d_out, int out_size) {
    const float* x      = (const float*)d_in[0];
    const float* w_iem  = (const float*)d_in[1];
    const float* g_iem  = (const float*)d_in[2];
    const float* b_iem  = (const float*)d_in[3];
    const float* w_nem  = (const float*)d_in[4];
    const float* g_nem  = (const float*)d_in[5];
    const float* b_nem  = (const float*)d_in[6];
    const float* w_idw  = (const float*)d_in[7];
    const float* w_ndw  = (const float*)d_in[8];
    const float* w_q    = (const float*)d_in[9];
    const float* w_k    = (const float*)d_in[10];
    const float* w_v    = (const float*)d_in[11];
    const float* w_proj = (const float*)d_in[12];
    const float* temp   = (const float*)d_in[13];
    float* out = (float*)d_out;

    float *A, *B, *C, *PART, *BNA, *BNC, *IS, *NS;
    __half *Xh, *H1, *H2, *H3, *WCT, *WT4;
    cudaGetSymbolAddress((void**)&A,    g_A);
    cudaGetSymbolAddress((void**)&B,    g_B);
    cudaGetSymbolAddress((void**)&C,    g_C);
    cudaGetSymbolAddress((void**)&Xh,   g_Xh);
    cudaGetSymbolAddress((void**)&H1,   g_H1);
    cudaGetSymbolAddress((void**)&H2,   g_H2);
    cudaGetSymbolAddress((void**)&H3,   g_H3);
    cudaGetSymbolAddress((void**)&WCT,  g_wct);
    cudaGetSymbolAddress((void**)&WT4,  g_wt4);
    cudaGetSymbolAddress((void**)&PART, g_part);
    cudaGetSymbolAddress((void**)&BNA,  g_bna);
    cudaGetSymbolAddress((void**)&BNC,  g_bnc);
    cudaGetSymbolAddress((void**)&IS,   g_is);
    cudaGetSymbolAddress((void**)&NS,   g_ns);

    const int CSM = CONV_STG_B * 4;               // 98688
    const int GSM = 67584;                        // max(4*GEMM_STG_B, epilogue)
    cudaFuncSetAttribute(conv_mma,    cudaFuncAttributeMaxDynamicSharedMemorySize, CSM);
    cudaFuncSetAttribute(gemm_mma<0>, cudaFuncAttributeMaxDynamicSharedMemorySize, GSM);
    cudaFuncSetAttribute(gemm_mma<1>, cudaFuncAttributeMaxDynamicSharedMemorySize, GSM);

    tconv_kernel<<<4608, 256>>>(w_iem, w_nem, WCT);
    t1x1_kernel<<<1024, 256>>>(w_q, w_k, w_v, w_proj, WT4);
    xT_kernel<<<dim3(2048, 8, 2), dim3(32, 32)>>>(x, Xh);

    dim3 cg(512, 2, 2);
    conv_mma<<<cg, 256, CSM>>>(Xh, WCT,          A);
    conv_mma<<<cg, 256, CSM>>>(Xh, WCT + 589824, B);

    bnstats1<<<512, 256>>>(A, PART);
    bnstats2<<<1, 256>>>(PART, g_iem, b_iem, BNA, BNC);
    bnstats1<<<512, 256>>>(B, PART);
    bnstats2<<<1, 256>>>(PART, g_nem, b_nem, BNA + 256, BNC + 256);

    dwconv_t<<<65536, 256>>>(A, BNA,       BNC,       w_idw, H1, IS);
    dwconv_t<<<65536, 256>>>(B, BNA + 256, BNC + 256, w_ndw, H2, NS);

    gemm_mma<0><<<cg, 256, GSM>>>(WT4,              H1, A);   // q
    gemm_mma<0><<<cg, 256, GSM>>>(WT4 + 65536,      H2, B);   // k
    gemm_mma<0><<<cg, 256, GSM>>>(WT4 + 2 * 65536,  Xh, C);   // v

    attn_kernel<<<dim3(1024, 8, 2), 64>>>(A, B, C, IS, NS, temp, H3);

    gemm_mma<1><<<cg, 256, GSM>>>(WT4 + 3 * 65536,  H3, out); // proj -> NCHW
}

// round 10
// speedup vs baseline: 4.6280x; 1.0713x over previous
#include <cuda_runtime.h>
#include <cuda_fp16.h>
#include <math.h>
#include <stdint.h>

#define HW 65536
#define NBUF (2*256*HW)

// ---------------- static scratch (all big intermediates fp16) ----------------
__device__ __half g_Xh[NBUF];       // x [b][px][c]
__device__ __half g_Hc1[NBUF];      // conv_iem out [r][c]
__device__ __half g_Hc2[NBUF];      // conv_nem out [r][c]
__device__ __half g_Hd1[NBUF];      // illum map [r][c]
__device__ __half g_Hd2[NBUF];      // noise map [r][c]
__device__ __half g_Hq[NBUF];       // q window layout
__device__ __half g_Hk[NBUF];       // k window layout
__device__ __half g_Hv[NBUF];       // v window layout
__device__ __half g_Ha[NBUF];       // attn out [r][c]
__device__ __half g_wct[2*589824];  // conv weights [m][tap][oc][c]
__device__ __half g_wt4[4*65536];   // 1x1 weights [m][oc][c]
__device__ float  g_part[524288];   // bn partials
__device__ float  g_bna[512];
__device__ float  g_bnc[512];
__device__ float  g_is[2*HW];
__device__ float  g_ns[2*HW];

// ---------------- helpers ----------------
__device__ __forceinline__ void ffma2(unsigned long long& d, unsigned long long a,
                                      unsigned long long b) {
    asm("fma.rn.f32x2 %0, %1, %2, %0;" : "+l"(d) : "l"(a), "l"(b));
}
__device__ __forceinline__ unsigned long long pack2(float lo, float hi) {
    unsigned long long r;
    asm("mov.b64 %0, {%1, %2};" : "=l"(r) : "f"(lo), "f"(hi));
    return r;
}
__device__ __forceinline__ void unpack2(unsigned long long p, float& lo, float& hi) {
    asm("mov.b64 {%0, %1}, %2;" : "=f"(lo), "=f"(hi) : "l"(p));
}
__device__ __forceinline__ uint32_t smem_u32(const void* p) {
    uint32_t a;
    asm("{ .reg .u64 t; cvta.to.shared.u64 t, %1; cvt.u32.u64 %0, t; }" : "=r"(a) : "l"(p));
    return a;
}
__device__ __forceinline__ uint32_t f2h2(float a, float b) {
    __half2 h = __floats2half2_rn(a, b);
    return *(uint32_t*)&h;
}
__device__ __forceinline__ void h8_to_f(uint4 t, float* f) {
    const __half2* hp = (const __half2*)&t;
#pragma unroll
    for (int u = 0; u < 4; u++) {
        float2 ff = __half22float2(hp[u]);
        f[2*u] = ff.x; f[2*u+1] = ff.y;
    }
}
__device__ __forceinline__ void cpa16(uint32_t s, const void* g, uint32_t n) {
    asm volatile("cp.async.cg.shared.global [%0], [%1], 16, %2;"
                 :: "r"(s), "l"(g), "r"(n) : "memory");
}
#define CP_COMMIT()  asm volatile("cp.async.commit_group;" ::: "memory")
#define CP_WAIT2()   asm volatile("cp.async.wait_group 2;" ::: "memory")
#define CP_WAIT1()   asm volatile("cp.async.wait_group 1;" ::: "memory")
#define CP_WAIT0()   asm volatile("cp.async.wait_group 0;" ::: "memory")

// fp16 m16n8k16 mma, fp32 accumulate (family-portable HMMA)
__device__ __forceinline__ void mma16(float* d, const uint32_t* a, const uint32_t* b) {
    asm volatile("mma.sync.aligned.m16n8k16.row.col.f32.f16.f16.f32 "
        "{%0,%1,%2,%3}, {%4,%5,%6,%7}, {%8,%9}, {%0,%1,%2,%3};"
        : "+f"(d[0]), "+f"(d[1]), "+f"(d[2]), "+f"(d[3])
        : "r"(a[0]), "r"(a[1]), "r"(a[2]), "r"(a[3]), "r"(b[0]), "r"(b[1]));
}

// ---------------- weight prep ----------------
__global__ void tconv_kernel(const float* __restrict__ w0, const float* __restrict__ w1,
                             __half* __restrict__ out) {
    int i = blockIdx.x * 256 + threadIdx.x;          // 2*589824
    int m = i / 589824;
    int r = i - m * 589824;
    int tap = r >> 16;
    int rem = r & 65535;
    int oc  = rem >> 8;
    int c   = rem & 255;
    const float* w = m ? w1 : w0;
    out[i] = __float2half_rn(w[oc * 2304 + c * 9 + tap]);
}

__global__ void t1x1_kernel(const float* __restrict__ wq, const float* __restrict__ wk,
                            const float* __restrict__ wv, const float* __restrict__ wp,
                            __half* __restrict__ out) {
    int i = blockIdx.x * 256 + threadIdx.x;          // 4*65536
    int m = i >> 16;
    int r = i & 65535;
    int o = r >> 8;
    int c = r & 255;
    const float* w = (m == 0) ? wq : (m == 1) ? wk : (m == 2) ? wv : wp;
    out[i] = __float2half_rn(w[o * 256 + c]);
}

// ---------------- x transpose: NCHW -> [b][px][c] fp16 ----------------
__global__ void xT_kernel(const float* __restrict__ x, __half* __restrict__ xT) {
    __shared__ float t[32][33];
    int b  = blockIdx.z;
    int c0 = blockIdx.y * 32;
    int p0 = blockIdx.x * 32;
    int tx = threadIdx.x, ty = threadIdx.y;
    t[ty][tx] = x[(((size_t)((b << 8) + c0 + ty)) << 16) + p0 + tx];
    __syncthreads();
    xT[(((size_t)((b << 16) + p0 + ty)) << 8) + c0 + tx] = __float2half_rn(t[tx][ty]);
}

// ---------------- 3x3 conv implicit GEMM (fp16 mma), 4-stage/3-deep ----------------
#define CONV_STG_B 24672     // 130*48 + 3*128*48
#define CONV_XS_B  6240
__global__ void __launch_bounds__(256, 2) conv_mma(const __half* __restrict__ xT,
                                                   const __half* __restrict__ W2,
                                                   __half* __restrict__ out) {
    extern __shared__ char smc[];
    const int tid  = threadIdx.x;
    const int w    = tid >> 5, lane = tid & 31;
    const int g    = lane >> 2, tg = lane & 3;
    const int y    = blockIdx.x >> 1;
    const int p0   = (blockIdx.x & 1) << 7;
    const int oc0  = blockIdx.y << 7;
    const int b    = blockIdx.z;
    const int wm   = w >> 2, wn = w & 3;
    const uint32_t sm_u = smem_u32(smc);

    float acc[4][4][4];
#pragma unroll
    for (int mi = 0; mi < 4; mi++)
#pragma unroll
        for (int ni = 0; ni < 4; ni++)
#pragma unroll
            for (int r = 0; r < 4; r++) acc[mi][ni][r] = 0.f;

    auto do_load = [&](int step, int buf) {
        int cc = step / 3;
        int ky = step - cc * 3;
        int c0 = cc * 16;
        uint32_t xs_u = sm_u + buf * CONV_STG_B;
        uint32_t ws_u = xs_u + CONV_XS_B;
        int yin = y + ky - 1;
        bool yok = (unsigned)yin < 256u;
#pragma unroll
        for (int jj = 0; jj < 2; jj++) {
            int j = jj * 256 + tid;
            if (j < 260) {
                int r = j >> 1, q = j & 1;
                int xin = p0 + r - 1;
                bool ok = yok && ((unsigned)xin < 256u);
                const __half* src = ok
                    ? xT + ((((size_t)b << 16) + ((size_t)yin << 8) + xin) << 8) + c0 + q * 8
                    : xT;
                cpa16(xs_u + r * 48 + q * 16, src, ok ? 16u : 0u);
            }
        }
#pragma unroll
        for (int jj = 0; jj < 3; jj++) {
            int j = jj * 256 + tid;
            int koc = j >> 1, q = j & 1;
            int kx = koc >> 7, oc = koc & 127;
            int tap = ky * 3 + kx;
            cpa16(ws_u + koc * 48 + q * 16,
                  W2 + (((size_t)(tap * 256 + oc0 + oc)) << 8) + c0 + q * 8, 16u);
        }
        CP_COMMIT();
    };

    auto do_compute = [&](int buf) {
        const char* Xs = smc + buf * CONV_STG_B;
        const char* Ws = Xs + CONV_XS_B;
#pragma unroll
        for (int kx = 0; kx < 3; kx++) {
            uint32_t af[4][4];
#pragma unroll
            for (int mi = 0; mi < 4; mi++) {
                const char* rp = Xs + (wm * 64 + mi * 16 + g + kx) * 48 + tg * 4;
                af[mi][0] = *(const uint32_t*)(rp);
                af[mi][1] = *(const uint32_t*)(rp + 8 * 48);
                af[mi][2] = *(const uint32_t*)(rp + 16);
                af[mi][3] = *(const uint32_t*)(rp + 8 * 48 + 16);
            }
            uint32_t bf[4][2];
#pragma unroll
            for (int ni = 0; ni < 4; ni++) {
                const char* bp = Ws + (kx * 128 + wn * 32 + ni * 8 + g) * 48 + tg * 4;
                bf[ni][0] = *(const uint32_t*)(bp);
                bf[ni][1] = *(const uint32_t*)(bp + 16);
            }
#pragma unroll
            for (int mi = 0; mi < 4; mi++)
#pragma unroll
                for (int ni = 0; ni < 4; ni++)
                    mma16(acc[mi][ni], af[mi], bf[ni]);
        }
    };

    do_load(0, 0);
    do_load(1, 1);
    do_load(2, 2);
    for (int s = 0; s < 48; s++) {
        if (s < 46) { CP_WAIT2(); } else if (s == 46) { CP_WAIT1(); } else { CP_WAIT0(); }
        __syncthreads();
        if (s + 3 < 48) do_load(s + 3, (s + 3) & 3);
        do_compute(s & 3);
    }
    __syncthreads();   // epilogue smem aliases pipeline buffers

    // epilogue: fragments -> smem S[px][oc] (fp32) -> channel-last fp16 rows
    float* S = (float*)smc;     // 128*132*4 = 67584 <= 4*CONV_STG_B
#pragma unroll
    for (int mi = 0; mi < 4; mi++) {
        int px = wm * 64 + mi * 16 + g;
#pragma unroll
        for (int ni = 0; ni < 4; ni++) {
            int oc = wn * 32 + ni * 8 + 2 * tg;
            S[px * 132 + oc]           = acc[mi][ni][0];
            S[px * 132 + oc + 1]       = acc[mi][ni][1];
            S[(px + 8) * 132 + oc]     = acc[mi][ni][2];
            S[(px + 8) * 132 + oc + 1] = acc[mi][ni][3];
        }
    }
    __syncthreads();
#pragma unroll
    for (int it = 0; it < 16; it++) {
        int px = w + it * 8;
        float4 v = *(float4*)&S[px * 132 + lane * 4];
        uint2 o;
        o.x = f2h2(v.x, v.y);
        o.y = f2h2(v.z, v.w);
        *(uint2*)(out + (((size_t)((b << 16) + (y << 8) + p0 + px)) << 8) + oc0 + lane * 4) = o;
    }
}

// ---------------- BN stats: deterministic 2-stage, channel-last fp16 in ----------------
__global__ void bnstats1(const __half* __restrict__ conv, float* __restrict__ part) {
    int c = threadIdx.x;
    int j = blockIdx.x;                 // 512 blocks x 256 rows
    size_t r0 = (size_t)j * 256;
    float s = 0.f, s2 = 0.f;
    for (int i = 0; i < 256; i++) {
        float v = __half2float(conv[(r0 + i) * 256 + c]);
        s += v; s2 += v * v;
    }
    part[j * 512 + c]       = s;
    part[j * 512 + 256 + c] = s2;
}

__global__ void bnstats2(const float* __restrict__ part,
                         const float* __restrict__ gamma, const float* __restrict__ beta,
                         float* __restrict__ pa, float* __restrict__ pc) {
    int c = threadIdx.x;
    float s = 0.f, s2 = 0.f;
    for (int j = 0; j < 512; j++) {
        s  += part[j * 512 + c];
        s2 += part[j * 512 + 256 + c];
    }
    float m   = s  * (1.f / 131072.f);
    float var = s2 * (1.f / 131072.f) - m * m;
    float a = gamma[c] * rsqrtf(var + 1e-5f);
    pa[c] = a;
    pc[c] = beta[c] - m * a;
}

// ---------------- depthwise conv, channel-last fp16 in/out, BN+relu6 fused,
//                  2 pixels/thread, channel-mean fused ----------------
__global__ void dwconv_t(const __half* __restrict__ in,
                         const float* __restrict__ pa, const float* __restrict__ pc,
                         const float* __restrict__ wdw, __half* __restrict__ out,
                         float* __restrict__ mean_out) {
    __shared__ float red0[8], red1[8];
    int j = blockIdx.x;          // rows 2j, 2j+1 (same image row)
    int c = threadIdx.x;
    int r0 = j << 1;
    int p  = r0 & 65535;
    int y = p >> 8, xx = p & 255;          // xx even
    size_t bb = (size_t)(r0 - p) << 8;
    float a = pa[c], cb = pc[c];
    float w[9];
#pragma unroll
    for (int t = 0; t < 9; t++) w[t] = wdw[c * 9 + t];
    float acc0 = 0.f, acc1 = 0.f;
#pragma unroll
    for (int ky = 0; ky < 3; ky++) {
        int yy = y + ky - 1;
        if ((unsigned)yy >= 256u) continue;
        float v[4];
#pragma unroll
        for (int dx = 0; dx < 4; dx++) {
            int xv = xx + dx - 1;
            bool ok = (unsigned)xv < 256u;
            float t = ok ? __half2float(in[bb + (size_t)((yy << 8) + xv) * 256 + c]) : 0.f;
            t = fminf(fmaxf(t * a + cb, 0.f), 6.f);
            v[dx] = ok ? t : 0.f;
        }
        acc0 = fmaf(w[ky * 3 + 0], v[0], acc0);
        acc0 = fmaf(w[ky * 3 + 1], v[1], acc0);
        acc0 = fmaf(w[ky * 3 + 2], v[2], acc0);
        acc1 = fmaf(w[ky * 3 + 0], v[1], acc1);
        acc1 = fmaf(w[ky * 3 + 1], v[2], acc1);
        acc1 = fmaf(w[ky * 3 + 2], v[3], acc1);
    }
    out[(size_t)r0 * 256 + c]       = __float2half_rn(acc0);
    out[(size_t)(r0 + 1) * 256 + c] = __float2half_rn(acc1);

    float s0 = acc0, s1 = acc1;
#pragma unroll
    for (int off = 16; off; off >>= 1) {
        s0 += __shfl_xor_sync(0xffffffffu, s0, off);
        s1 += __shfl_xor_sync(0xffffffffu, s1, off);
    }
    if ((c & 31) == 0) { red0[c >> 5] = s0; red1[c >> 5] = s1; }
    __syncthreads();
    if (c < 8) {
        float t0 = red0[c], t1 = red1[c];
#pragma unroll
        for (int off = 4; off; off >>= 1) {
            t0 += __shfl_xor_sync(0xffu, t0, off);
            t1 += __shfl_xor_sync(0xffu, t1, off);
        }
        if (c == 0) {
            mean_out[r0]     = t0 * (1.f / 256.f);
            mean_out[r0 + 1] = t1 * (1.f / 256.f);
        }
    }
}

// ---------------- 1x1 channel GEMM (fp16 mma), 4-stage/3-deep ----------------
// MODE 0: window-layout fp16 out. MODE 1: NCHW fp32 out.
#define GEMM_STG_B 12288     // 128*48 + 128*48
template <int MODE>
__global__ void __launch_bounds__(256, 2) gemm_mma(const __half* __restrict__ wt,
                                                   const __half* __restrict__ in,
                                                   void* __restrict__ outv) {
    extern __shared__ char smc[];
    const int tid  = threadIdx.x;
    const int w    = tid >> 5, lane = tid & 31;
    const int g    = lane >> 2, tg = lane & 3;
    const int tile = blockIdx.x;
    const int oc0  = blockIdx.y << 7;
    const int b    = blockIdx.z;
    const int wm   = w >> 2, wn = w & 3;
    const uint32_t sm_u = smem_u32(smc);
    const size_t r0 = ((size_t)b << 16) + (size_t)tile * 128;

    float acc[4][4][4];
#pragma unroll
    for (int mi = 0; mi < 4; mi++)
#pragma unroll
        for (int ni = 0; ni < 4; ni++)
#pragma unroll
            for (int r = 0; r < 4; r++) acc[mi][ni][r] = 0.f;

    auto do_load = [&](int cc, int buf) {
        int c0 = cc * 16;
        uint32_t xs_u = sm_u + buf * GEMM_STG_B;
        uint32_t ws_u = xs_u + 6144;
        {
            int r = tid >> 1, q = tid & 1;
            cpa16(xs_u + r * 48 + q * 16, in + (r0 + r) * 256 + c0 + q * 8, 16u);
            cpa16(ws_u + r * 48 + q * 16, wt + (size_t)(oc0 + r) * 256 + c0 + q * 8, 16u);
        }
        CP_COMMIT();
    };

    auto do_compute = [&](int buf) {
        const char* Xs = smc + buf * GEMM_STG_B;
        const char* Ws = Xs + 6144;
        uint32_t af[4][4];
#pragma unroll
        for (int mi = 0; mi < 4; mi++) {
            const char* rp = Xs + (wm * 64 + mi * 16 + g) * 48 + tg * 4;
            af[mi][0] = *(const uint32_t*)(rp);
            af[mi][1] = *(const uint32_t*)(rp + 8 * 48);
            af[mi][2] = *(const uint32_t*)(rp + 16);
            af[mi][3] = *(const uint32_t*)(rp + 8 * 48 + 16);
        }
        uint32_t bf[4][2];
#pragma unroll
        for (int ni = 0; ni < 4; ni++) {
            const char* bp = Ws + (wn * 32 + ni * 8 + g) * 48 + tg * 4;
            bf[ni][0] = *(const uint32_t*)(bp);
            bf[ni][1] = *(const uint32_t*)(bp + 16);
        }
#pragma unroll
        for (int mi = 0; mi < 4; mi++)
#pragma unroll
            for (int ni = 0; ni < 4; ni++)
                mma16(acc[mi][ni], af[mi], bf[ni]);
    };

    do_load(0, 0);
    do_load(1, 1);
    do_load(2, 2);
    for (int s = 0; s < 16; s++) {
        if (s < 14) { CP_WAIT2(); } else if (s == 14) { CP_WAIT1(); } else { CP_WAIT0(); }
        __syncthreads();
        if (s + 3 < 16) do_load(s + 3, (s + 3) & 3);
        do_compute(s & 3);
    }
    __syncthreads();   // epilogue smem aliases pipeline buffers

    float* S = (float*)smc;
    if (MODE == 0) {
        __half* out = (__half*)outv;
#pragma unroll
        for (int mi = 0; mi < 4; mi++) {
            int px = wm * 64 + mi * 16 + g;
#pragma unroll
            for (int ni = 0; ni < 4; ni++) {
                int oc = wn * 32 + ni * 8 + 2 * tg;
                S[px * 132 + oc]           = acc[mi][ni][0];
                S[px * 132 + oc + 1]       = acc[mi][ni][1];
                S[(px + 8) * 132 + oc]     = acc[mi][ni][2];
                S[(px + 8) * 132 + oc + 1] = acc[mi][ni][3];
            }
        }
        __syncthreads();
#pragma unroll
        for (int s2 = tid; s2 < 512; s2 += 256) {
            int px = s2 >> 2, seg = s2 & 3;
            int gp = tile * 128 + px;
            int y = gp >> 8, x = gp & 255;
            int win = ((y >> 3) << 5) + (x >> 3);
            int pix = ((y & 7) << 3) + (x & 7);
            int h = (oc0 >> 5) + seg;
            size_t dst = (((size_t)(b * 8 + h)) << 21) + ((size_t)win << 11) + (pix << 5);
            const float* src = &S[px * 132 + seg * 32];
            __half* dp = out + dst;
#pragma unroll
            for (int k2 = 0; k2 < 4; k2++) {
                float4 a2 = *(const float4*)&src[k2 * 8];
                float4 b2 = *(const float4*)&src[k2 * 8 + 4];
                uint4 o;
                o.x = f2h2(a2.x, a2.y); o.y = f2h2(a2.z, a2.w);
                o.z = f2h2(b2.x, b2.y); o.w = f2h2(b2.z, b2.w);
                *(uint4*)(dp + k2 * 8) = o;
            }
        }
    } else {
        float* out = (float*)outv;
#pragma unroll
        for (int mi = 0; mi < 4; mi++) {
            int px = wm * 64 + mi * 16 + g;
#pragma unroll
            for (int ni = 0; ni < 4; ni++) {
                int oc = wn * 32 + ni * 8 + 2 * tg;
                S[oc * 132 + px]           = acc[mi][ni][0];
                S[(oc + 1) * 132 + px]     = acc[mi][ni][1];
                S[oc * 132 + px + 8]       = acc[mi][ni][2];
                S[(oc + 1) * 132 + px + 8] = acc[mi][ni][3];
            }
        }
        __syncthreads();
#pragma unroll
        for (int it = 0; it < 16; it++) {
            int oc = w + it * 8;
            float4 v = *(float4*)&S[oc * 132 + lane * 4];
            *(float4*)&out[(((size_t)(b * 256 + oc0 + oc)) << 16) + tile * 128 + lane * 4] = v;
        }
    }
}

// ---------------- windowed attention (fp16 in, f32x2 math, fp16 out) ----------------
__global__ void __launch_bounds__(64) attn_kernel(const __half* __restrict__ q,
                                                  const __half* __restrict__ k,
                                                  const __half* __restrict__ v,
                                                  const float* __restrict__ is,
                                                  const float* __restrict__ ns,
                                                  const float* __restrict__ temp,
                                                  __half* __restrict__ out) {
    __shared__ __align__(16) float ks[64][32];
    __shared__ __align__(16) float vs[64][32];
    __shared__ float sc[64][65];
    const int i   = threadIdx.x;
    const int win = blockIdx.x;
    const int h   = blockIdx.y;
    const int b   = blockIdx.z;
    const size_t base = (((size_t)(b * 8 + h)) << 21) + ((size_t)win << 11);

    const int y = ((win >> 5) << 3) + (i >> 3);
    const int x = ((win & 31) << 3) + (i & 7);
    const int pidx = (b << 16) + (y << 8) + x;

    const uint4* kp4 = (const uint4*)(k + base + ((size_t)i << 5));
    const uint4* vp4 = (const uint4*)(v + base + ((size_t)i << 5));
    float kr[32];
    float kn = 0.f;
#pragma unroll
    for (int t = 0; t < 4; t++) {
        h8_to_f(kp4[t], kr + 8 * t);
        float vr[8];
        h8_to_f(vp4[t], vr);
#pragma unroll
        for (int u = 0; u < 8; u++) {
            kn = fmaf(kr[8*t + u], kr[8*t + u], kn);
            vs[i][8*t + u] = vr[u];
        }
    }
    float nsv = ns[pidx];
    float kmul = fminf(fmaxf(1.f - nsv, 0.f), 1.f) / fmaxf(sqrtf(kn), 1e-12f);
#pragma unroll
    for (int t = 0; t < 8; t++) {
        float4 o = {kr[4*t] * kmul, kr[4*t+1] * kmul, kr[4*t+2] * kmul, kr[4*t+3] * kmul};
        *(float4*)&ks[i][4*t] = o;
    }

    const uint4* qp4 = (const uint4*)(q + base + ((size_t)i << 5));
    float qr[32];
    float qn = 0.f;
#pragma unroll
    for (int t = 0; t < 4; t++) {
        h8_to_f(qp4[t], qr + 8 * t);
#pragma unroll
        for (int u = 0; u < 8; u++) qn = fmaf(qr[8*t + u], qr[8*t + u], qn);
    }
    float qmul = (1.f + is[pidx]) / fmaxf(sqrtf(qn), 1e-12f)
               * 0.17677669529663687f * temp[h];
    unsigned long long qp[16];
#pragma unroll
    for (int t = 0; t < 16; t++)
        qp[t] = pack2(qr[2*t] * qmul, qr[2*t+1] * qmul);

    __syncthreads();

    float mx = -1e30f;
#pragma unroll 4
    for (int j = 0; j < 64; j++) {
        const unsigned long long* kj = (const unsigned long long*)ks[j];
        unsigned long long a0 = 0ULL, a1 = 0ULL;
#pragma unroll
        for (int t = 0; t < 8; t++) {
            ffma2(a0, qp[2*t],     kj[2*t]);
            ffma2(a1, qp[2*t + 1], kj[2*t + 1]);
        }
        float l0, h0, l1, h1;
        unpack2(a0, l0, h0);
        unpack2(a1, l1, h1);
        float s = (l0 + h0) + (l1 + h1);
        sc[i][j] = s;
        mx = fmaxf(mx, s);
    }
    float sum = 0.f;
#pragma unroll
    for (int j = 0; j < 64; j++) {
        float e = __expf(sc[i][j] - mx);
        sc[i][j] = e;
        sum += e;
    }
    float inv = 1.f / sum;

    unsigned long long av[16];
#pragma unroll
    for (int t = 0; t < 16; t++) av[t] = 0ULL;
#pragma unroll 4
    for (int j = 0; j < 64; j++) {
        float p = sc[i][j];
        unsigned long long pp = pack2(p, p);
        const unsigned long long* vj = (const unsigned long long*)vs[j];
#pragma unroll
        for (int t = 0; t < 16; t++) ffma2(av[t], pp, vj[t]);
    }

    __half2* o2 = (__half2*)(out + (((size_t)pidx) << 8) + (h << 5));
#pragma unroll
    for (int t = 0; t < 16; t++) {
        float l, hh;
        unpack2(av[t], l, hh);
        o2[t] = __floats2half2_rn(l * inv, hh * inv);
    }
}

// ---------------- launch ----------------
extern "C" void kernel_launch(void* const* d_in, const int* in_sizes, int n_in,
                              void* d_out, int out_size) {
    const float* x      = (const float*)d_in[0];
    const float* w_iem  = (const float*)d_in[1];
    const float* g_iem  = (const float*)d_in[2];
    const float* b_iem  = (const float*)d_in[3];
    const float* w_nem  = (const float*)d_in[4];
    const float* g_nem  = (const float*)d_in[5];
    const float* b_nem  = (const float*)d_in[6];
    const float* w_idw  = (const float*)d_in[7];
    const float* w_ndw  = (const float*)d_in[8];
    const float* w_q    = (const float*)d_in[9];
    const float* w_k    = (const float*)d_in[10];
    const float* w_v    = (const float*)d_in[11];
    const float* w_proj = (const float*)d_in[12];
    const float* temp   = (const float*)d_in[13];
    float* out = (float*)d_out;

    float *PART, *BNA, *BNC, *IS, *NS;
    __half *Xh, *Hc1, *Hc2, *Hd1, *Hd2, *Hq, *Hk, *Hv, *Ha, *WCT, *WT4;
    cudaGetSymbolAddress((void**)&Xh,   g_Xh);
    cudaGetSymbolAddress((void**)&Hc1,  g_Hc1);
    cudaGetSymbolAddress((void**)&Hc2,  g_Hc2);
    cudaGetSymbolAddress((void**)&Hd1,  g_Hd1);
    cudaGetSymbolAddress((void**)&Hd2,  g_Hd2);
    cudaGetSymbolAddress((void**)&Hq,   g_Hq);
    cudaGetSymbolAddress((void**)&Hk,   g_Hk);
    cudaGetSymbolAddress((void**)&Hv,   g_Hv);
    cudaGetSymbolAddress((void**)&Ha,   g_Ha);
    cudaGetSymbolAddress((void**)&WCT,  g_wct);
    cudaGetSymbolAddress((void**)&WT4,  g_wt4);
    cudaGetSymbolAddress((void**)&PART, g_part);
    cudaGetSymbolAddress((void**)&BNA,  g_bna);
    cudaGetSymbolAddress((void**)&BNC,  g_bnc);
    cudaGetSymbolAddress((void**)&IS,   g_is);
    cudaGetSymbolAddress((void**)&NS,   g_ns);

    const int CSM = CONV_STG_B * 4;               // 98688
    const int GSM = 67584;
    cudaFuncSetAttribute(conv_mma,    cudaFuncAttributeMaxDynamicSharedMemorySize, CSM);
    cudaFuncSetAttribute(gemm_mma<0>, cudaFuncAttributeMaxDynamicSharedMemorySize, GSM);
    cudaFuncSetAttribute(gemm_mma<1>, cudaFuncAttributeMaxDynamicSharedMemorySize, GSM);

    tconv_kernel<<<4608, 256>>>(w_iem, w_nem, WCT);
    t1x1_kernel<<<1024, 256>>>(w_q, w_k, w_v, w_proj, WT4);
    xT_kernel<<<dim3(2048, 8, 2), dim3(32, 32)>>>(x, Xh);

    dim3 cg(512, 2, 2);
    conv_mma<<<cg, 256, CSM>>>(Xh, WCT,          Hc1);
    conv_mma<<<cg, 256, CSM>>>(Xh, WCT + 589824, Hc2);

    bnstats1<<<512, 256>>>(Hc1, PART);
    bnstats2<<<1, 256>>>(PART, g_iem, b_iem, BNA, BNC);
    bnstats1<<<512, 256>>>(Hc2, PART);
    bnstats2<<<1, 256>>>(PART, g_nem, b_nem, BNA + 256, BNC + 256);

    dwconv_t<<<65536, 256>>>(Hc1, BNA,       BNC,       w_idw, Hd1, IS);
    dwconv_t<<<65536, 256>>>(Hc2, BNA + 256, BNC + 256, w_ndw, Hd2, NS);

    gemm_mma<0><<<cg, 256, GSM>>>(WT4,              Hd1, Hq);   // q
    gemm_mma<0><<<cg, 256, GSM>>>(WT4 + 65536,      Hd2, Hk);   // k
    gemm_mma<0><<<cg, 256, GSM>>>(WT4 + 2 * 65536,  Xh,  Hv);   // v

    attn_kernel<<<dim3(1024, 8, 2), 64>>>(Hq, Hk, Hv, IS, NS, temp, Ha);

    gemm_mma<1><<<cg, 256, GSM>>>(WT4 + 3 * 65536,  Ha, out);   // proj -> NCHW
}

// round 11
// speedup vs baseline: 5.5272x; 1.1943x over previous
#include <cuda_runtime.h>
#include <cuda_fp16.h>
#include <math.h>
#include <stdint.h>

#define HW 65536
#define NBUF (2*256*HW)

// ---------------- static scratch (all big intermediates fp16) ----------------
__device__ __half g_Xh[NBUF];       // x [b][px][c]
__device__ __half g_Hc1[NBUF];      // conv_iem out [r][c]
__device__ __half g_Hc2[NBUF];      // conv_nem out [r][c]
__device__ __half g_Hd1[NBUF];      // illum map [r][c]
__device__ __half g_Hd2[NBUF];      // noise map [r][c]
__device__ __half g_Hq[NBUF];       // q window layout
__device__ __half g_Hk[NBUF];       // k window layout
__device__ __half g_Hv[NBUF];       // v window layout
__device__ __half g_Ha[NBUF];       // attn out [r][c]
__device__ __half g_wct[2*589824];  // conv weights [m][tap][oc][c]
__device__ __half g_wt4[4*65536];   // 1x1 weights [m][oc][c]
__device__ float  g_part[524288];   // bn partials [2][512 blk][2][256 ch]
__device__ float  g_bna[512];
__device__ float  g_bnc[512];
__device__ float  g_is[2*HW];
__device__ float  g_ns[2*HW];

// ---------------- helpers ----------------
__device__ __forceinline__ void ffma2(unsigned long long& d, unsigned long long a,
                                      unsigned long long b) {
    asm("fma.rn.f32x2 %0, %1, %2, %0;" : "+l"(d) : "l"(a), "l"(b));
}
__device__ __forceinline__ unsigned long long pack2(float lo, float hi) {
    unsigned long long r;
    asm("mov.b64 %0, {%1, %2};" : "=l"(r) : "f"(lo), "f"(hi));
    return r;
}
__device__ __forceinline__ void unpack2(unsigned long long p, float& lo, float& hi) {
    asm("mov.b64 {%0, %1}, %2;" : "=f"(lo), "=f"(hi) : "l"(p));
}
__device__ __forceinline__ uint32_t smem_u32(const void* p) {
    uint32_t a;
    asm("{ .reg .u64 t; cvta.to.shared.u64 t, %1; cvt.u32.u64 %0, t; }" : "=r"(a) : "l"(p));
    return a;
}
__device__ __forceinline__ uint32_t f2h2(float a, float b) {
    __half2 h = __floats2half2_rn(a, b);
    return *(uint32_t*)&h;
}
__device__ __forceinline__ void h8_to_f(uint4 t, float* f) {
    const __half2* hp = (const __half2*)&t;
#pragma unroll
    for (int u = 0; u < 4; u++) {
        float2 ff = __half22float2(hp[u]);
        f[2*u] = ff.x; f[2*u+1] = ff.y;
    }
}
__device__ __forceinline__ void cpa16(uint32_t s, const void* g, uint32_t n) {
    asm volatile("cp.async.cg.shared.global [%0], [%1], 16, %2;"
                 :: "r"(s), "l"(g), "r"(n) : "memory");
}
#define CP_COMMIT()  asm volatile("cp.async.commit_group;" ::: "memory")
#define CP_WAIT2()   asm volatile("cp.async.wait_group 2;" ::: "memory")
#define CP_WAIT1()   asm volatile("cp.async.wait_group 1;" ::: "memory")
#define CP_WAIT0()   asm volatile("cp.async.wait_group 0;" ::: "memory")

// fp16 m16n8k16 mma, fp32 accumulate (family-portable HMMA)
__device__ __forceinline__ void mma16(float* d, const uint32_t* a, const uint32_t* b) {
    asm volatile("mma.sync.aligned.m16n8k16.row.col.f32.f16.f16.f32 "
        "{%0,%1,%2,%3}, {%4,%5,%6,%7}, {%8,%9}, {%0,%1,%2,%3};"
        : "+f"(d[0]), "+f"(d[1]), "+f"(d[2]), "+f"(d[3])
        : "r"(a[0]), "r"(a[1]), "r"(a[2]), "r"(a[3]), "r"(b[0]), "r"(b[1]));
}
// ldmatrix x4 (sm_75+, family-portable)
__device__ __forceinline__ void ldsm4(uint32_t* r, uint32_t a) {
    asm volatile("ldmatrix.sync.aligned.m8n8.x4.shared.b16 {%0,%1,%2,%3}, [%4];"
        : "=r"(r[0]), "=r"(r[1]), "=r"(r[2]), "=r"(r[3]) : "r"(a));
}

// ---------------- weight prep ----------------
__global__ void tconv_kernel(const float* __restrict__ w0, const float* __restrict__ w1,
                             __half* __restrict__ out) {
    int i = blockIdx.x * 256 + threadIdx.x;          // 2*589824
    int m = i / 589824;
    int r = i - m * 589824;
    int tap = r >> 16;
    int rem = r & 65535;
    int oc  = rem >> 8;
    int c   = rem & 255;
    const float* w = m ? w1 : w0;
    out[i] = __float2half_rn(w[oc * 2304 + c * 9 + tap]);
}

__global__ void t1x1_kernel(const float* __restrict__ wq, const float* __restrict__ wk,
                            const float* __restrict__ wv, const float* __restrict__ wp,
                            __half* __restrict__ out) {
    int i = blockIdx.x * 256 + threadIdx.x;          // 4*65536
    int m = i >> 16;
    int r = i & 65535;
    int o = r >> 8;
    int c = r & 255;
    const float* w = (m == 0) ? wq : (m == 1) ? wk : (m == 2) ? wv : wp;
    out[i] = __float2half_rn(w[o * 256 + c]);
}

// ---------------- x transpose: NCHW -> [b][px][c] fp16 ----------------
__global__ void xT_kernel(const float* __restrict__ x, __half* __restrict__ xT) {
    __shared__ float t[32][33];
    int b  = blockIdx.z;
    int c0 = blockIdx.y * 32;
    int p0 = blockIdx.x * 32;
    int tx = threadIdx.x, ty = threadIdx.y;
    t[ty][tx] = x[(((size_t)((b << 8) + c0 + ty)) << 16) + p0 + tx];
    __syncthreads();
    xT[(((size_t)((b << 16) + p0 + ty)) << 8) + c0 + tx] = __float2half_rn(t[tx][ty]);
}

// ---------------- 3x3 conv implicit GEMM (fp16 mma + ldmatrix), 3-stage ----------------
// CTA 128px x 128oc; K = 24 steps (8 chunks of 32ch x 3 ky); kx via smem row shift.
// XOR-swizzled 64B rows: chunk q at byte (q ^ ((row>>1)&3))*16.
#define CONV_XS_B  8704      // X region (8320 used, padded to 512B multiple)
#define CONV_STG_B 33280     // stage: 8704 + 384*64
__global__ void __launch_bounds__(256, 2) conv_mma(const __half* __restrict__ xT,
                                                   const __half* __restrict__ W2,
                                                   __half* __restrict__ out) {
    extern __shared__ char smc[];
    const int tid  = threadIdx.x;
    const int w    = tid >> 5, lane = tid & 31;
    const int g    = lane >> 2, tg = lane & 3;
    const int y    = blockIdx.x >> 1;
    const int p0   = (blockIdx.x & 1) << 7;
    const int oc0  = blockIdx.y << 7;
    const int b    = blockIdx.z;
    const int wm   = w >> 2, wn = w & 3;
    const uint32_t sm_u = smem_u32(smc);
    // per-lane ldmatrix row bases
    const int aRowB = wm * 64 + (lane & 15);                       // A: rows 0-15 of tile
    const int bRowB = wn * 32 + ((lane >> 4) << 3) + (lane & 7);   // B: ni-pair rows
    const uint32_t aQ = (uint32_t)(lane >> 4);                     // A k-chunk parity
    const uint32_t bQ = (uint32_t)((lane >> 3) & 1);               // B k-chunk parity

    float acc[4][4][4];
#pragma unroll
    for (int mi = 0; mi < 4; mi++)
#pragma unroll
        for (int ni = 0; ni < 4; ni++)
#pragma unroll
            for (int r = 0; r < 4; r++) acc[mi][ni][r] = 0.f;

    auto do_load = [&](int step, int buf) {
        int cc = step / 3;
        int ky = step - cc * 3;
        int c0 = cc * 32;
        uint32_t xs = sm_u + buf * CONV_STG_B;
        uint32_t ws = xs + CONV_XS_B;
        int yin = y + ky - 1;
        bool yok = (unsigned)yin < 256u;
        // X slab: 130 rows x 32 halves (4 x 16B chunks), swizzled
#pragma unroll
        for (int jj = 0; jj < 3; jj++) {
            int j = jj * 256 + tid;
            if (j < 520) {
                int r = j >> 2, q = j & 3;
                int xin = p0 + r - 1;
                bool ok = yok && ((unsigned)xin < 256u);
                const __half* src = ok
                    ? xT + ((((size_t)b << 16) + ((size_t)yin << 8) + xin) << 8) + c0 + q * 8
                    : xT;
                cpa16(xs + r * 64 + ((q ^ ((r >> 1) & 3)) << 4), src, ok ? 16u : 0u);
            }
        }
        // W: 3 kx x [128 oc][32 halves], swizzled
#pragma unroll
        for (int jj = 0; jj < 6; jj++) {
            int j = jj * 256 + tid;
            int row = j >> 2, q = j & 3;          // row = kx*128+oc
            int kx = row >> 7, oc = row & 127;
            int tap = ky * 3 + kx;
            cpa16(ws + row * 64 + ((q ^ ((row >> 1) & 3)) << 4),
                  W2 + (((size_t)(tap * 256 + oc0 + oc)) << 8) + c0 + q * 8, 16u);
        }
        CP_COMMIT();
    };

    auto do_compute = [&](int buf) {
        uint32_t xs = sm_u + buf * CONV_STG_B;
        uint32_t ws = xs + CONV_XS_B;
#pragma unroll
        for (int kx = 0; kx < 3; kx++) {
#pragma unroll
            for (int ks = 0; ks < 2; ks++) {
                uint32_t af[4][4];
#pragma unroll
                for (int mi = 0; mi < 4; mi++) {
                    int row = aRowB + mi * 16 + kx;
                    uint32_t q = (uint32_t)(ks * 2) + aQ;
                    ldsm4(af[mi], xs + row * 64 + ((q ^ ((row >> 1) & 3)) << 4));
                }
                uint32_t bf[4][2];
#pragma unroll
                for (int pn = 0; pn < 2; pn++) {
                    int row = kx * 128 + bRowB + pn * 16;
                    uint32_t q = (uint32_t)(ks * 2) + bQ;
                    uint32_t t[4];
                    ldsm4(t, ws + row * 64 + ((q ^ ((row >> 1) & 3)) << 4));
                    bf[2*pn][0]   = t[0]; bf[2*pn][1]   = t[1];
                    bf[2*pn+1][0] = t[2]; bf[2*pn+1][1] = t[3];
                }
#pragma unroll
                for (int mi = 0; mi < 4; mi++)
#pragma unroll
                    for (int ni = 0; ni < 4; ni++)
                        mma16(acc[mi][ni], af[mi], bf[ni]);
            }
        }
    };

    do_load(0, 0);
    do_load(1, 1);
    for (int s = 0; s < 24; s++) {
        if (s < 23) { CP_WAIT1(); } else { CP_WAIT0(); }
        __syncthreads();
        if (s + 2 < 24) do_load(s + 2, (s + 2) % 3);
        do_compute(s % 3);
    }
    __syncthreads();   // epilogue smem aliases pipeline buffers

    // epilogue: fragments -> smem S[px][oc] (fp32) -> channel-last fp16 rows
    float* S = (float*)smc;     // 128*132*4 = 67584 <= 3*CONV_STG_B
#pragma unroll
    for (int mi = 0; mi < 4; mi++) {
        int px = wm * 64 + mi * 16 + g;
#pragma unroll
        for (int ni = 0; ni < 4; ni++) {
            int oc = wn * 32 + ni * 8 + 2 * tg;
            S[px * 132 + oc]           = acc[mi][ni][0];
            S[px * 132 + oc + 1]       = acc[mi][ni][1];
            S[(px + 8) * 132 + oc]     = acc[mi][ni][2];
            S[(px + 8) * 132 + oc + 1] = acc[mi][ni][3];
        }
    }
    __syncthreads();
#pragma unroll
    for (int it = 0; it < 16; it++) {
        int px = w + it * 8;
        float4 v = *(float4*)&S[px * 132 + lane * 4];
        uint2 o;
        o.x = f2h2(v.x, v.y);
        o.y = f2h2(v.z, v.w);
        *(uint2*)(out + (((size_t)((b << 16) + (y << 8) + p0 + px)) << 8) + oc0 + lane * 4) = o;
    }
}

// ---------------- BN stats: merged pair, deterministic 2-stage ----------------
__global__ void bnstats1(const __half* __restrict__ c1, const __half* __restrict__ c2,
                         float* __restrict__ part) {
    const __half* conv = blockIdx.y ? c2 : c1;
    float* p = part + (size_t)blockIdx.y * 262144;
    int c = threadIdx.x;
    int j = blockIdx.x;                 // 512 blocks x 256 rows
    size_t r0 = (size_t)j * 256;
    float s = 0.f, s2 = 0.f;
    for (int i = 0; i < 256; i++) {
        float v = __half2float(conv[(r0 + i) * 256 + c]);
        s += v; s2 += v * v;
    }
    p[j * 512 + c]       = s;
    p[j * 512 + 256 + c] = s2;
}

__global__ void bnstats2(const float* __restrict__ part,
                         const float* __restrict__ g1, const float* __restrict__ b1,
                         const float* __restrict__ g2, const float* __restrict__ b2,
                         float* __restrict__ pa, float* __restrict__ pc) {
    int m = blockIdx.x;
    const float* p = part + (size_t)m * 262144;
    const float* gamma = m ? g2 : g1;
    const float* beta  = m ? b2 : b1;
    int c = threadIdx.x;
    float s = 0.f, s2 = 0.f;
    for (int j = 0; j < 512; j++) {
        s  += p[j * 512 + c];
        s2 += p[j * 512 + 256 + c];
    }
    float mean = s  * (1.f / 131072.f);
    float var  = s2 * (1.f / 131072.f) - mean * mean;
    float a = gamma[c] * rsqrtf(var + 1e-5f);
    pa[m * 256 + c] = a;
    pc[m * 256 + c] = beta[c] - mean * a;
}

// ---------------- depthwise conv pair, channel-last fp16, BN+relu6 fused,
//                  2 pixels/thread, channel-mean fused ----------------
__global__ void dwconv_t(const __half* __restrict__ in1, const __half* __restrict__ in2,
                         const float* __restrict__ pa, const float* __restrict__ pc,
                         const float* __restrict__ wd1, const float* __restrict__ wd2,
                         __half* __restrict__ out1, __half* __restrict__ out2,
                         float* __restrict__ mean1, float* __restrict__ mean2) {
    __shared__ float red0[8], red1[8];
    int m = blockIdx.y;
    const __half* in  = m ? in2 : in1;
    const float*  wdw = m ? wd2 : wd1;
    __half* out       = m ? out2 : out1;
    float* mean_out   = m ? mean2 : mean1;
    int j = blockIdx.x;          // rows 2j, 2j+1 (same image row)
    int c = threadIdx.x;
    int r0 = j << 1;
    int p  = r0 & 65535;
    int y = p >> 8, xx = p & 255;          // xx even
    size_t bb = (size_t)(r0 - p) << 8;
    float a = pa[m * 256 + c], cb = pc[m * 256 + c];
    float w[9];
#pragma unroll
    for (int t = 0; t < 9; t++) w[t] = wdw[c * 9 + t];
    float acc0 = 0.f, acc1 = 0.f;
#pragma unroll
    for (int ky = 0; ky < 3; ky++) {
        int yy = y + ky - 1;
        if ((unsigned)yy >= 256u) continue;
        float v[4];
#pragma unroll
        for (int dx = 0; dx < 4; dx++) {
            int xv = xx + dx - 1;
            bool ok = (unsigned)xv < 256u;
            float t = ok ? __half2float(in[bb + (size_t)((yy << 8) + xv) * 256 + c]) : 0.f;
            t = fminf(fmaxf(t * a + cb, 0.f), 6.f);
            v[dx] = ok ? t : 0.f;
        }
        acc0 = fmaf(w[ky * 3 + 0], v[0], acc0);
        acc0 = fmaf(w[ky * 3 + 1], v[1], acc0);
        acc0 = fmaf(w[ky * 3 + 2], v[2], acc0);
        acc1 = fmaf(w[ky * 3 + 0], v[1], acc1);
        acc1 = fmaf(w[ky * 3 + 1], v[2], acc1);
        acc1 = fmaf(w[ky * 3 + 2], v[3], acc1);
    }
    out[(size_t)r0 * 256 + c]       = __float2half_rn(acc0);
    out[(size_t)(r0 + 1) * 256 + c] = __float2half_rn(acc1);

    float s0 = acc0, s1 = acc1;
#pragma unroll
    for (int off = 16; off; off >>= 1) {
        s0 += __shfl_xor_sync(0xffffffffu, s0, off);
        s1 += __shfl_xor_sync(0xffffffffu, s1, off);
    }
    if ((c & 31) == 0) { red0[c >> 5] = s0; red1[c >> 5] = s1; }
    __syncthreads();
    if (c < 8) {
        float t0 = red0[c], t1 = red1[c];
#pragma unroll
        for (int off = 4; off; off >>= 1) {
            t0 += __shfl_xor_sync(0xffu, t0, off);
            t1 += __shfl_xor_sync(0xffu, t1, off);
        }
        if (c == 0) {
            mean_out[r0]     = t0 * (1.f / 256.f);
            mean_out[r0 + 1] = t1 * (1.f / 256.f);
        }
    }
}

// ---------------- 1x1 channel GEMM (fp16 mma), 4-stage/3-deep ----------------
// MODE 0: window-layout fp16 out. MODE 1: NCHW fp32 out.
#define GEMM_STG_B 12288     // 128*48 + 128*48
template <int MODE>
__global__ void __launch_bounds__(256, 2) gemm_mma(const __half* __restrict__ wt,
                                                   const __half* __restrict__ in,
                                                   void* __restrict__ outv) {
    extern __shared__ char smc[];
    const int tid  = threadIdx.x;
    const int w    = tid >> 5, lane = tid & 31;
    const int g    = lane >> 2, tg = lane & 3;
    const int tile = blockIdx.x;
    const int oc0  = blockIdx.y << 7;
    const int b    = blockIdx.z;
    const int wm   = w >> 2, wn = w & 3;
    const uint32_t sm_u = smem_u32(smc);
    const size_t r0 = ((size_t)b << 16) + (size_t)tile * 128;

    float acc[4][4][4];
#pragma unroll
    for (int mi = 0; mi < 4; mi++)
#pragma unroll
        for (int ni = 0; ni < 4; ni++)
#pragma unroll
            for (int r = 0; r < 4; r++) acc[mi][ni][r] = 0.f;

    auto do_load = [&](int cc, int buf) {
        int c0 = cc * 16;
        uint32_t xs_u = sm_u + buf * GEMM_STG_B;
        uint32_t ws_u = xs_u + 6144;
        {
            int r = tid >> 1, q = tid & 1;
            cpa16(xs_u + r * 48 + q * 16, in + (r0 + r) * 256 + c0 + q * 8, 16u);
            cpa16(ws_u + r * 48 + q * 16, wt + (size_t)(oc0 + r) * 256 + c0 + q * 8, 16u);
        }
        CP_COMMIT();
    };

    auto do_compute = [&](int buf) {
        const char* Xs = smc + buf * GEMM_STG_B;
        const char* Ws = Xs + 6144;
        uint32_t af[4][4];
#pragma unroll
        for (int mi = 0; mi < 4; mi++) {
            const char* rp = Xs + (wm * 64 + mi * 16 + g) * 48 + tg * 4;
            af[mi][0] = *(const uint32_t*)(rp);
            af[mi][1] = *(const uint32_t*)(rp + 8 * 48);
            af[mi][2] = *(const uint32_t*)(rp + 16);
            af[mi][3] = *(const uint32_t*)(rp + 8 * 48 + 16);
        }
        uint32_t bf[4][2];
#pragma unroll
        for (int ni = 0; ni < 4; ni++) {
            const char* bp = Ws + (wn * 32 + ni * 8 + g) * 48 + tg * 4;
            bf[ni][0] = *(const uint32_t*)(bp);
            bf[ni][1] = *(const uint32_t*)(bp + 16);
        }
#pragma unroll
        for (int mi = 0; mi < 4; mi++)
#pragma unroll
            for (int ni = 0; ni < 4; ni++)
                mma16(acc[mi][ni], af[mi], bf[ni]);
    };

    do_load(0, 0);
    do_load(1, 1);
    do_load(2, 2);
    for (int s = 0; s < 16; s++) {
        if (s < 14) { CP_WAIT2(); } else if (s == 14) { CP_WAIT1(); } else { CP_WAIT0(); }
        __syncthreads();
        if (s + 3 < 16) do_load(s + 3, (s + 3) & 3);
        do_compute(s & 3);
    }
    __syncthreads();   // epilogue smem aliases pipeline buffers

    float* S = (float*)smc;
    if (MODE == 0) {
        __half* out = (__half*)outv;
#pragma unroll
        for (int mi = 0; mi < 4; mi++) {
            int px = wm * 64 + mi * 16 + g;
#pragma unroll
            for (int ni = 0; ni < 4; ni++) {
                int oc = wn * 32 + ni * 8 + 2 * tg;
                S[px * 132 + oc]           = acc[mi][ni][0];
                S[px * 132 + oc + 1]       = acc[mi][ni][1];
                S[(px + 8) * 132 + oc]     = acc[mi][ni][2];
                S[(px + 8) * 132 + oc + 1] = acc[mi][ni][3];
            }
        }
        __syncthreads();
#pragma unroll
        for (int s2 = tid; s2 < 512; s2 += 256) {
            int px = s2 >> 2, seg = s2 & 3;
            int gp = tile * 128 + px;
            int y = gp >> 8, x = gp & 255;
            int win = ((y >> 3) << 5) + (x >> 3);
            int pix = ((y & 7) << 3) + (x & 7);
            int h = (oc0 >> 5) + seg;
            size_t dst = (((size_t)(b * 8 + h)) << 21) + ((size_t)win << 11) + (pix << 5);
            const float* src = &S[px * 132 + seg * 32];
            __half* dp = out + dst;
#pragma unroll
            for (int k2 = 0; k2 < 4; k2++) {
                float4 a2 = *(const float4*)&src[k2 * 8];
                float4 b2 = *(const float4*)&src[k2 * 8 + 4];
                uint4 o;
                o.x = f2h2(a2.x, a2.y); o.y = f2h2(a2.z, a2.w);
                o.z = f2h2(b2.x, b2.y); o.w = f2h2(b2.z, b2.w);
                *(uint4*)(dp + k2 * 8) = o;
            }
        }
    } else {
        float* out = (float*)outv;
#pragma unroll
        for (int mi = 0; mi < 4; mi++) {
            int px = wm * 64 + mi * 16 + g;
#pragma unroll
            for (int ni = 0; ni < 4; ni++) {
                int oc = wn * 32 + ni * 8 + 2 * tg;
                S[oc * 132 + px]           = acc[mi][ni][0];
                S[(oc + 1) * 132 + px]     = acc[mi][ni][1];
                S[oc * 132 + px + 8]       = acc[mi][ni][2];
                S[(oc + 1) * 132 + px + 8] = acc[mi][ni][3];
            }
        }
        __syncthreads();
#pragma unroll
        for (int it = 0; it < 16; it++) {
            int oc = w + it * 8;
            float4 v = *(float4*)&S[oc * 132 + lane * 4];
            *(float4*)&out[(((size_t)(b * 256 + oc0 + oc)) << 16) + tile * 128 + lane * 4] = v;
        }
    }
}

// ---------------- windowed attention (fp16 in, f32x2 math, fp16 out) ----------------
__global__ void __launch_bounds__(64) attn_kernel(const __half* __restrict__ q,
                                                  const __half* __restrict__ k,
                                                  const __half* __restrict__ v,
                                                  const float* __restrict__ is,
                                                  const float* __restrict__ ns,
                                                  const float* __restrict__ temp,
                                                  __half* __restrict__ out) {
    __shared__ __align__(16) float ks[64][32];
    __shared__ __align__(16) float vs[64][32];
    __shared__ float sc[64][65];
    const int i   = threadIdx.x;
    const int win = blockIdx.x;
    const int h   = blockIdx.y;
    const int b   = blockIdx.z;
    const size_t base = (((size_t)(b * 8 + h)) << 21) + ((size_t)win << 11);

    const int y = ((win >> 5) << 3) + (i >> 3);
    const int x = ((win & 31) << 3) + (i & 7);
    const int pidx = (b << 16) + (y << 8) + x;

    const uint4* kp4 = (const uint4*)(k + base + ((size_t)i << 5));
    const uint4* vp4 = (const uint4*)(v + base + ((size_t)i << 5));
    float kr[32];
    float kn = 0.f;
#pragma unroll
    for (int t = 0; t < 4; t++) {
        h8_to_f(kp4[t], kr + 8 * t);
        float vr[8];
        h8_to_f(vp4[t], vr);
#pragma unroll
        for (int u = 0; u < 8; u++) {
            kn = fmaf(kr[8*t + u], kr[8*t + u], kn);
            vs[i][8*t + u] = vr[u];
        }
    }
    float nsv = ns[pidx];
    float kmul = fminf(fmaxf(1.f - nsv, 0.f), 1.f) / fmaxf(sqrtf(kn), 1e-12f);
#pragma unroll
    for (int t = 0; t < 8; t++) {
        float4 o = {kr[4*t] * kmul, kr[4*t+1] * kmul, kr[4*t+2] * kmul, kr[4*t+3] * kmul};
        *(float4*)&ks[i][4*t] = o;
    }

    const uint4* qp4 = (const uint4*)(q + base + ((size_t)i << 5));
    float qr[32];
    float qn = 0.f;
#pragma unroll
    for (int t = 0; t < 4; t++) {
        h8_to_f(qp4[t], qr + 8 * t);
#pragma unroll
        for (int u = 0; u < 8; u++) qn = fmaf(qr[8*t + u], qr[8*t + u], qn);
    }
    float qmul = (1.f + is[pidx]) / fmaxf(sqrtf(qn), 1e-12f)
               * 0.17677669529663687f * temp[h];
    unsigned long long qp[16];
#pragma unroll
    for (int t = 0; t < 16; t++)
        qp[t] = pack2(qr[2*t] * qmul, qr[2*t+1] * qmul);

    __syncthreads();

    float mx = -1e30f;
#pragma unroll 4
    for (int j = 0; j < 64; j++) {
        const unsigned long long* kj = (const unsigned long long*)ks[j];
        unsigned long long a0 = 0ULL, a1 = 0ULL;
#pragma unroll
        for (int t = 0; t < 8; t++) {
            ffma2(a0, qp[2*t],     kj[2*t]);
            ffma2(a1, qp[2*t + 1], kj[2*t + 1]);
        }
        float l0, h0, l1, h1;
        unpack2(a0, l0, h0);
        unpack2(a1, l1, h1);
        float s = (l0 + h0) + (l1 + h1);
        sc[i][j] = s;
        mx = fmaxf(mx, s);
    }
    float sum = 0.f;
#pragma unroll
    for (int j = 0; j < 64; j++) {
        float e = __expf(sc[i][j] - mx);
        sc[i][j] = e;
        sum += e;
    }
    float inv = 1.f / sum;

    unsigned long long av[16];
#pragma unroll
    for (int t = 0; t < 16; t++) av[t] = 0ULL;
#pragma unroll 4
    for (int j = 0; j < 64; j++) {
        float p = sc[i][j];
        unsigned long long pp = pack2(p, p);
        const unsigned long long* vj = (const unsigned long long*)vs[j];
#pragma unroll
        for (int t = 0; t < 16; t++) ffma2(av[t], pp, vj[t]);
    }

    __half2* o2 = (__half2*)(out + (((size_t)pidx) << 8) + (h << 5));
#pragma unroll
    for (int t = 0; t < 16; t++) {
        float l, hh;
        unpack2(av[t], l, hh);
        o2[t] = __floats2half2_rn(l * inv, hh * inv);
    }
}

// ---------------- launch ----------------
extern "C" void kernel_launch(void* const* d_in, const int* in_sizes, int n_in,
                              void* d_out, int out_size) {
    const float* x      = (const float*)d_in[0];
    const float* w_iem  = (const float*)d_in[1];
    const float* g_iem  = (const float*)d_in[2];
    const float* b_iem  = (const float*)d_in[3];
    const float* w_nem  = (const float*)d_in[4];
    const float* g_nem  = (const float*)d_in[5];
    const float* b_nem  = (const float*)d_in[6];
    const float* w_idw  = (const float*)d_in[7];
    const float* w_ndw  = (const float*)d_in[8];
    const float* w_q    = (const float*)d_in[9];
    const float* w_k    = (const float*)d_in[10];
    const float* w_v    = (const float*)d_in[11];
    const float* w_proj = (const float*)d_in[12];
    const float* temp   = (const float*)d_in[13];
    float* out = (float*)d_out;

    float *PART, *BNA, *BNC, *IS, *NS;
    __half *Xh, *Hc1, *Hc2, *Hd1, *Hd2, *Hq, *Hk, *Hv, *Ha, *WCT, *WT4;
    cudaGetSymbolAddress((void**)&Xh,   g_Xh);
    cudaGetSymbolAddress((void**)&Hc1,  g_Hc1);
    cudaGetSymbolAddress((void**)&Hc2,  g_Hc2);
    cudaGetSymbolAddress((void**)&Hd1,  g_Hd1);
    cudaGetSymbolAddress((void**)&Hd2,  g_Hd2);
    cudaGetSymbolAddress((void**)&Hq,   g_Hq);
    cudaGetSymbolAddress((void**)&Hk,   g_Hk);
    cudaGetSymbolAddress((void**)&Hv,   g_Hv);
    cudaGetSymbolAddress((void**)&Ha,   g_Ha);
    cudaGetSymbolAddress((void**)&WCT,  g_wct);
    cudaGetSymbolAddress((void**)&WT4,  g_wt4);
    cudaGetSymbolAddress((void**)&PART, g_part);
    cudaGetSymbolAddress((void**)&BNA,  g_bna);
    cudaGetSymbolAddress((void**)&BNC,  g_bnc);
    cudaGetSymbolAddress((void**)&IS,   g_is);
    cudaGetSymbolAddress((void**)&NS,   g_ns);

    const int CSM = CONV_STG_B * 3;               // 99840
    const int GSM = 67584;
    cudaFuncSetAttribute(conv_mma,    cudaFuncAttributeMaxDynamicSharedMemorySize, CSM);
    cudaFuncSetAttribute(gemm_mma<0>, cudaFuncAttributeMaxDynamicSharedMemorySize, GSM);
    cudaFuncSetAttribute(gemm_mma<1>, cudaFuncAttributeMaxDynamicSharedMemorySize, GSM);

    tconv_kernel<<<4608, 256>>>(w_iem, w_nem, WCT);
    t1x1_kernel<<<1024, 256>>>(w_q, w_k, w_v, w_proj, WT4);
    xT_kernel<<<dim3(2048, 8, 2), dim3(32, 32)>>>(x, Xh);

    dim3 cg(512, 2, 2);
    conv_mma<<<cg, 256, CSM>>>(Xh, WCT,          Hc1);
    conv_mma<<<cg, 256, CSM>>>(Xh, WCT + 589824, Hc2);

    bnstats1<<<dim3(512, 2), 256>>>(Hc1, Hc2, PART);
    bnstats2<<<2, 256>>>(PART, g_iem, b_iem, g_nem, b_nem, BNA, BNC);

    dwconv_t<<<dim3(65536, 2), 256>>>(Hc1, Hc2, BNA, BNC, w_idw, w_ndw,
                                      Hd1, Hd2, IS, NS);

    gemm_mma<0><<<cg, 256, GSM>>>(WT4,              Hd1, Hq);   // q
    gemm_mma<0><<<cg, 256, GSM>>>(WT4 + 65536,      Hd2, Hk);   // k
    gemm_mma<0><<<cg, 256, GSM>>>(WT4 + 2 * 65536,  Xh,  Hv);   // v

    attn_kernel<<<dim3(1024, 8, 2), 64>>>(Hq, Hk, Hv, IS, NS, temp, Ha);

    gemm_mma<1><<<cg, 256, GSM>>>(WT4 + 3 * 65536,  Ha, out);   // proj -> NCHW
}

// round 12
// speedup vs baseline: 5.9788x; 1.0817x over previous
#include <cuda_runtime.h>
#include <cuda_fp16.h>
#include <math.h>
#include <stdint.h>

#define HW 65536
#define NBUF (2*256*HW)

// ---------------- static scratch (all big intermediates fp16) ----------------
__device__ __half g_Xh[NBUF];       // x [b][px][c]
__device__ __half g_Hc1[NBUF];      // conv_iem out [r][c]
__device__ __half g_Hc2[NBUF];      // conv_nem out [r][c]
__device__ __half g_Hd1[NBUF];      // illum map [r][c]
__device__ __half g_Hd2[NBUF];      // noise map [r][c]
__device__ __half g_Hq[NBUF];       // q window layout
__device__ __half g_Hk[NBUF];       // k window layout
__device__ __half g_Hv[NBUF];       // v window layout
__device__ __half g_Ha[NBUF];       // attn out [r][c]
__device__ __half g_wct[2*589824];  // conv weights [m][tap][oc][c]
__device__ __half g_wt4[4*65536];   // 1x1 weights [m][oc][c]
__device__ float  g_part[1048576];  // bn partials [2][1024 cta][2][256 ch]
__device__ float  g_bna[512];
__device__ float  g_bnc[512];
__device__ float  g_is[2*HW];
__device__ float  g_ns[2*HW];

// ---------------- helpers ----------------
__device__ __forceinline__ void ffma2(unsigned long long& d, unsigned long long a,
                                      unsigned long long b) {
    asm("fma.rn.f32x2 %0, %1, %2, %0;" : "+l"(d) : "l"(a), "l"(b));
}
__device__ __forceinline__ unsigned long long pack2(float lo, float hi) {
    unsigned long long r;
    asm("mov.b64 %0, {%1, %2};" : "=l"(r) : "f"(lo), "f"(hi));
    return r;
}
__device__ __forceinline__ void unpack2(unsigned long long p, float& lo, float& hi) {
    asm("mov.b64 {%0, %1}, %2;" : "=f"(lo), "=f"(hi) : "l"(p));
}
__device__ __forceinline__ uint32_t smem_u32(const void* p) {
    uint32_t a;
    asm("{ .reg .u64 t; cvta.to.shared.u64 t, %1; cvt.u32.u64 %0, t; }" : "=r"(a) : "l"(p));
    return a;
}
__device__ __forceinline__ uint32_t f2h2(float a, float b) {
    __half2 h = __floats2half2_rn(a, b);
    return *(uint32_t*)&h;
}
__device__ __forceinline__ void h8_to_f(uint4 t, float* f) {
    const __half2* hp = (const __half2*)&t;
#pragma unroll
    for (int u = 0; u < 4; u++) {
        float2 ff = __half22float2(hp[u]);
        f[2*u] = ff.x; f[2*u+1] = ff.y;
    }
}
__device__ __forceinline__ void cpa16(uint32_t s, const void* g, uint32_t n) {
    asm volatile("cp.async.cg.shared.global [%0], [%1], 16, %2;"
                 :: "r"(s), "l"(g), "r"(n) : "memory");
}
#define CP_COMMIT()  asm volatile("cp.async.commit_group;" ::: "memory")
#define CP_WAIT1()   asm volatile("cp.async.wait_group 1;" ::: "memory")
#define CP_WAIT0()   asm volatile("cp.async.wait_group 0;" ::: "memory")

// fp16 m16n8k16 mma, fp32 accumulate (family-portable HMMA)
__device__ __forceinline__ void mma16(float* d, const uint32_t* a, const uint32_t* b) {
    asm volatile("mma.sync.aligned.m16n8k16.row.col.f32.f16.f16.f32 "
        "{%0,%1,%2,%3}, {%4,%5,%6,%7}, {%8,%9}, {%0,%1,%2,%3};"
        : "+f"(d[0]), "+f"(d[1]), "+f"(d[2]), "+f"(d[3])
        : "r"(a[0]), "r"(a[1]), "r"(a[2]), "r"(a[3]), "r"(b[0]), "r"(b[1]));
}
// ldmatrix x4 (sm_75+, family-portable)
__device__ __forceinline__ void ldsm4(uint32_t* r, uint32_t a) {
    asm volatile("ldmatrix.sync.aligned.m8n8.x4.shared.b16 {%0,%1,%2,%3}, [%4];"
        : "=r"(r[0]), "=r"(r[1]), "=r"(r[2]), "=r"(r[3]) : "r"(a));
}

// ---------------- weight prep ----------------
__global__ void tconv_kernel(const float* __restrict__ w0, const float* __restrict__ w1,
                             __half* __restrict__ out) {
    int i = blockIdx.x * 256 + threadIdx.x;          // 2*589824
    int m = i / 589824;
    int r = i - m * 589824;
    int tap = r >> 16;
    int rem = r & 65535;
    int oc  = rem >> 8;
    int c   = rem & 255;
    const float* w = m ? w1 : w0;
    out[i] = __float2half_rn(w[oc * 2304 + c * 9 + tap]);
}

__global__ void t1x1_kernel(const float* __restrict__ wq, const float* __restrict__ wk,
                            const float* __restrict__ wv, const float* __restrict__ wp,
                            __half* __restrict__ out) {
    int i = blockIdx.x * 256 + threadIdx.x;          // 4*65536
    int m = i >> 16;
    int r = i & 65535;
    int o = r >> 8;
    int c = r & 255;
    const float* w = (m == 0) ? wq : (m == 1) ? wk : (m == 2) ? wv : wp;
    out[i] = __float2half_rn(w[o * 256 + c]);
}

// ---------------- x transpose: NCHW -> [b][px][c] fp16 ----------------
__global__ void xT_kernel(const float* __restrict__ x, __half* __restrict__ xT) {
    __shared__ float t[32][33];
    int b  = blockIdx.z;
    int c0 = blockIdx.y * 32;
    int p0 = blockIdx.x * 32;
    int tx = threadIdx.x, ty = threadIdx.y;
    t[ty][tx] = x[(((size_t)((b << 8) + c0 + ty)) << 16) + p0 + tx];
    __syncthreads();
    xT[(((size_t)((b << 16) + p0 + ty)) << 8) + c0 + tx] = __float2half_rn(t[tx][ty]);
}

// ---------------- 3x3 conv implicit GEMM (fp16 mma + ldmatrix), 3-stage,
//                  both convs in one launch, BN partials fused ----------------
// grid (512, 2, 4): x=(y,p0), y=oc half, z: m = z>>1, b = z&1.
#define CONV_XS_B  8704      // X region (8320 used, padded)
#define CONV_STG_B 33280     // stage: 8704 + 384*64
__global__ void __launch_bounds__(256, 2) conv_mma(const __half* __restrict__ xT,
                                                   const __half* __restrict__ W2base,
                                                   __half* __restrict__ out1,
                                                   __half* __restrict__ out2,
                                                   float* __restrict__ part) {
    extern __shared__ char smc[];
    const int tid  = threadIdx.x;
    const int w    = tid >> 5, lane = tid & 31;
    const int g    = lane >> 2, tg = lane & 3;
    const int y    = blockIdx.x >> 1;
    const int p0   = (blockIdx.x & 1) << 7;
    const int oc0  = blockIdx.y << 7;
    const int m    = blockIdx.z >> 1;
    const int b    = blockIdx.z & 1;
    const __half* W2 = W2base + (size_t)m * 589824;
    __half* out = m ? out2 : out1;
    const int wm   = w >> 2, wn = w & 3;
    const uint32_t sm_u = smem_u32(smc);
    const int aRowB = wm * 64 + (lane & 15);
    const int bRowB = wn * 32 + ((lane >> 4) << 3) + (lane & 7);
    const uint32_t aQ = (uint32_t)(lane >> 4);
    const uint32_t bQ = (uint32_t)((lane >> 3) & 1);

    float acc[4][4][4];
#pragma unroll
    for (int mi = 0; mi < 4; mi++)
#pragma unroll
        for (int ni = 0; ni < 4; ni++)
#pragma unroll
            for (int r = 0; r < 4; r++) acc[mi][ni][r] = 0.f;

    auto do_load = [&](int step, int buf) {
        int cc = step / 3;
        int ky = step - cc * 3;
        int c0 = cc * 32;
        uint32_t xs = sm_u + buf * CONV_STG_B;
        uint32_t ws = xs + CONV_XS_B;
        int yin = y + ky - 1;
        bool yok = (unsigned)yin < 256u;
#pragma unroll
        for (int jj = 0; jj < 3; jj++) {
            int j = jj * 256 + tid;
            if (j < 520) {
                int r = j >> 2, q = j & 3;
                int xin = p0 + r - 1;
                bool ok = yok && ((unsigned)xin < 256u);
                const __half* src = ok
                    ? xT + ((((size_t)b << 16) + ((size_t)yin << 8) + xin) << 8) + c0 + q * 8
                    : xT;
                cpa16(xs + r * 64 + ((q ^ ((r >> 1) & 3)) << 4), src, ok ? 16u : 0u);
            }
        }
#pragma unroll
        for (int jj = 0; jj < 6; jj++) {
            int j = jj * 256 + tid;
            int row = j >> 2, q = j & 3;          // row = kx*128+oc
            int kx = row >> 7, oc = row & 127;
            int tap = ky * 3 + kx;
            cpa16(ws + row * 64 + ((q ^ ((row >> 1) & 3)) << 4),
                  W2 + (((size_t)(tap * 256 + oc0 + oc)) << 8) + c0 + q * 8, 16u);
        }
        CP_COMMIT();
    };

    auto do_compute = [&](int buf) {
        uint32_t xs = sm_u + buf * CONV_STG_B;
        uint32_t ws = xs + CONV_XS_B;
#pragma unroll
        for (int kx = 0; kx < 3; kx++) {
#pragma unroll
            for (int ks = 0; ks < 2; ks++) {
                uint32_t af[4][4];
#pragma unroll
                for (int mi = 0; mi < 4; mi++) {
                    int row = aRowB + mi * 16 + kx;
                    uint32_t q = (uint32_t)(ks * 2) + aQ;
                    ldsm4(af[mi], xs + row * 64 + ((q ^ ((row >> 1) & 3)) << 4));
                }
                uint32_t bf[4][2];
#pragma unroll
                for (int pn = 0; pn < 2; pn++) {
                    int row = kx * 128 + bRowB + pn * 16;
                    uint32_t q = (uint32_t)(ks * 2) + bQ;
                    uint32_t t[4];
                    ldsm4(t, ws + row * 64 + ((q ^ ((row >> 1) & 3)) << 4));
                    bf[2*pn][0]   = t[0]; bf[2*pn][1]   = t[1];
                    bf[2*pn+1][0] = t[2]; bf[2*pn+1][1] = t[3];
                }
#pragma unroll
                for (int mi = 0; mi < 4; mi++)
#pragma unroll
                    for (int ni = 0; ni < 4; ni++)
                        mma16(acc[mi][ni], af[mi], bf[ni]);
            }
        }
    };

    do_load(0, 0);
    do_load(1, 1);
    for (int s = 0; s < 24; s++) {
        if (s < 23) { CP_WAIT1(); } else { CP_WAIT0(); }
        __syncthreads();
        if (s + 2 < 24) do_load(s + 2, (s + 2) % 3);
        do_compute(s % 3);
    }
    __syncthreads();   // epilogue smem aliases pipeline buffers

    // epilogue: fragments -> smem S[px][oc] (fp32)
    float* S = (float*)smc;     // 128*132*4 = 67584
#pragma unroll
    for (int mi = 0; mi < 4; mi++) {
        int px = wm * 64 + mi * 16 + g;
#pragma unroll
        for (int ni = 0; ni < 4; ni++) {
            int oc = wn * 32 + ni * 8 + 2 * tg;
            S[px * 132 + oc]           = acc[mi][ni][0];
            S[px * 132 + oc + 1]       = acc[mi][ni][1];
            S[(px + 8) * 132 + oc]     = acc[mi][ni][2];
            S[(px + 8) * 132 + oc + 1] = acc[mi][ni][3];
        }
    }
    __syncthreads();
    // channel-last fp16 stores
#pragma unroll
    for (int it = 0; it < 16; it++) {
        int px = w + it * 8;
        float4 v = *(float4*)&S[px * 132 + lane * 4];
        uint2 o;
        o.x = f2h2(v.x, v.y);
        o.y = f2h2(v.z, v.w);
        *(uint2*)(out + (((size_t)((b << 16) + (y << 8) + p0 + px)) << 8) + oc0 + lane * 4) = o;
    }
    // fused BN partials (deterministic order: px 0..63 then 64..127)
    float* R = (float*)(smc + 67584);
    {
        int ocl = tid & 127, half = tid >> 7;
        float s = 0.f, s2 = 0.f;
#pragma unroll 8
        for (int px = 0; px < 64; px++) {
            float v = S[(half * 64 + px) * 132 + ocl];
            s += v; s2 = fmaf(v, v, s2);
        }
        R[(half * 128 + ocl) * 2]     = s;
        R[(half * 128 + ocl) * 2 + 1] = s2;
    }
    __syncthreads();
    if (tid < 128) {
        float s  = R[tid * 2]     + R[(128 + tid) * 2];
        float s2 = R[tid * 2 + 1] + R[(128 + tid) * 2 + 1];
        size_t base = ((size_t)(m * 1024 + b * 512 + blockIdx.x) * 2) * 256 + oc0 + tid;
        part[base]       = s;
        part[base + 256] = s2;
    }
}

// ---------------- BN stats stage 2: reduce 1024 CTA partials per channel ----------------
__global__ void bnstats2(const float* __restrict__ part,
                         const float* __restrict__ g1, const float* __restrict__ b1,
                         const float* __restrict__ g2, const float* __restrict__ b2,
                         float* __restrict__ pa, float* __restrict__ pc) {
    int m = blockIdx.x;
    const float* gamma = m ? g2 : g1;
    const float* beta  = m ? b2 : b1;
    int c = threadIdx.x;
    float s = 0.f, s2 = 0.f;
    for (int row = 0; row < 1024; row++) {
        size_t base = ((size_t)(m * 1024 + row) * 2) * 256;
        s  += part[base + c];
        s2 += part[base + 256 + c];
    }
    float mean = s  * (1.f / 131072.f);
    float var  = s2 * (1.f / 131072.f) - mean * mean;
    float a = gamma[c] * rsqrtf(var + 1e-5f);
    pa[m * 256 + c] = a;
    pc[m * 256 + c] = beta[c] - mean * a;
}

// ---------------- depthwise conv pair, channel-last fp16, BN+relu6 fused,
//                  2 pixels/thread, channel-mean fused ----------------
__global__ void dwconv_t(const __half* __restrict__ in1, const __half* __restrict__ in2,
                         const float* __restrict__ pa, const float* __restrict__ pc,
                         const float* __restrict__ wd1, const float* __restrict__ wd2,
                         __half* __restrict__ out1, __half* __restrict__ out2,
                         float* __restrict__ mean1, float* __restrict__ mean2) {
    __shared__ float red0[8], red1[8];
    int m = blockIdx.y;
    const __half* in  = m ? in2 : in1;
    const float*  wdw = m ? wd2 : wd1;
    __half* out       = m ? out2 : out1;
    float* mean_out   = m ? mean2 : mean1;
    int j = blockIdx.x;          // rows 2j, 2j+1 (same image row)
    int c = threadIdx.x;
    int r0 = j << 1;
    int p  = r0 & 65535;
    int y = p >> 8, xx = p & 255;          // xx even
    size_t bb = (size_t)(r0 - p) << 8;
    float a = pa[m * 256 + c], cb = pc[m * 256 + c];
    float w[9];
#pragma unroll
    for (int t = 0; t < 9; t++) w[t] = wdw[c * 9 + t];
    float acc0 = 0.f, acc1 = 0.f;
#pragma unroll
    for (int ky = 0; ky < 3; ky++) {
        int yy = y + ky - 1;
        if ((unsigned)yy >= 256u) continue;
        float v[4];
#pragma unroll
        for (int dx = 0; dx < 4; dx++) {
            int xv = xx + dx - 1;
            bool ok = (unsigned)xv < 256u;
            float t = ok ? __half2float(in[bb + (size_t)((yy << 8) + xv) * 256 + c]) : 0.f;
            t = fminf(fmaxf(t * a + cb, 0.f), 6.f);
            v[dx] = ok ? t : 0.f;
        }
        acc0 = fmaf(w[ky * 3 + 0], v[0], acc0);
        acc0 = fmaf(w[ky * 3 + 1], v[1], acc0);
        acc0 = fmaf(w[ky * 3 + 2], v[2], acc0);
        acc1 = fmaf(w[ky * 3 + 0], v[1], acc1);
        acc1 = fmaf(w[ky * 3 + 1], v[2], acc1);
        acc1 = fmaf(w[ky * 3 + 2], v[3], acc1);
    }
    out[(size_t)r0 * 256 + c]       = __float2half_rn(acc0);
    out[(size_t)(r0 + 1) * 256 + c] = __float2half_rn(acc1);

    float s0 = acc0, s1 = acc1;
#pragma unroll
    for (int off = 16; off; off >>= 1) {
        s0 += __shfl_xor_sync(0xffffffffu, s0, off);
        s1 += __shfl_xor_sync(0xffffffffu, s1, off);
    }
    if ((c & 31) == 0) { red0[c >> 5] = s0; red1[c >> 5] = s1; }
    __syncthreads();
    if (c < 8) {
        float t0 = red0[c], t1 = red1[c];
#pragma unroll
        for (int off = 4; off; off >>= 1) {
            t0 += __shfl_xor_sync(0xffu, t0, off);
            t1 += __shfl_xor_sync(0xffu, t1, off);
        }
        if (c == 0) {
            mean_out[r0]     = t0 * (1.f / 256.f);
            mean_out[r0 + 1] = t1 * (1.f / 256.f);
        }
    }
}

// ---------------- 1x1 GEMM core (fp16 mma + ldmatrix), 3-stage ----------------
#define GEMM_XS_B  8192
#define GEMM_STG_B 16384
struct GemmCtx {
    float acc[4][4][4];
};
__device__ __forceinline__ void gemm_core(const __half* __restrict__ wt,
                                          const __half* __restrict__ in,
                                          char* smc, uint32_t sm_u,
                                          int tid, int lane, int wm, int wn,
                                          size_t r0, int oc0, float acc[4][4][4]) {
    const int aRowB = wm * 64 + (lane & 15);
    const int bRowB = wn * 32 + ((lane >> 4) << 3) + (lane & 7);
    const uint32_t aQ = (uint32_t)(lane >> 4);
    const uint32_t bQ = (uint32_t)((lane >> 3) & 1);

    auto do_load = [&](int cc, int buf) {
        int c0 = cc * 32;
        uint32_t xs = sm_u + buf * GEMM_STG_B;
        uint32_t ws = xs + GEMM_XS_B;
#pragma unroll
        for (int jj = 0; jj < 2; jj++) {
            int j = jj * 256 + tid;
            int r = j >> 2, q = j & 3;
            cpa16(xs + r * 64 + ((q ^ ((r >> 1) & 3)) << 4),
                  in + (r0 + r) * 256 + c0 + q * 8, 16u);
        }
#pragma unroll
        for (int jj = 0; jj < 2; jj++) {
            int j = jj * 256 + tid;
            int r = j >> 2, q = j & 3;
            cpa16(ws + r * 64 + ((q ^ ((r >> 1) & 3)) << 4),
                  wt + (size_t)(oc0 + r) * 256 + c0 + q * 8, 16u);
        }
        CP_COMMIT();
    };

    auto do_compute = [&](int buf) {
        uint32_t xs = sm_u + buf * GEMM_STG_B;
        uint32_t ws = xs + GEMM_XS_B;
#pragma unroll
        for (int ks = 0; ks < 2; ks++) {
            uint32_t af[4][4];
#pragma unroll
            for (int mi = 0; mi < 4; mi++) {
                int row = aRowB + mi * 16;
                uint32_t q = (uint32_t)(ks * 2) + aQ;
                ldsm4(af[mi], xs + row * 64 + ((q ^ ((row >> 1) & 3)) << 4));
            }
            uint32_t bf[4][2];
#pragma unroll
            for (int pn = 0; pn < 2; pn++) {
                int row = bRowB + pn * 16;
                uint32_t q = (uint32_t)(ks * 2) + bQ;
                uint32_t t[4];
                ldsm4(t, ws + row * 64 + ((q ^ ((row >> 1) & 3)) << 4));
                bf[2*pn][0]   = t[0]; bf[2*pn][1]   = t[1];
                bf[2*pn+1][0] = t[2]; bf[2*pn+1][1] = t[3];
            }
#pragma unroll
            for (int mi = 0; mi < 4; mi++)
#pragma unroll
                for (int ni = 0; ni < 4; ni++)
                    mma16(acc[mi][ni], af[mi], bf[ni]);
        }
    };

    do_load(0, 0);
    do_load(1, 1);
    for (int s = 0; s < 8; s++) {
        if (s < 7) { CP_WAIT1(); } else { CP_WAIT0(); }
        __syncthreads();
        if (s + 2 < 8) do_load(s + 2, (s + 2) % 3);
        do_compute(s % 3);
    }
    __syncthreads();   // epilogue smem aliases pipeline buffers
}

// q/k/v in one launch: grid (512, 2, 6), z: which = z>>1, b = z&1
__global__ void __launch_bounds__(256, 2) gemm_qkv(const __half* __restrict__ wtb,
                                                   const __half* __restrict__ in1,
                                                   const __half* __restrict__ in2,
                                                   const __half* __restrict__ in3,
                                                   __half* __restrict__ o1,
                                                   __half* __restrict__ o2,
                                                   __half* __restrict__ o3) {
    extern __shared__ char smc[];
    const int tid  = threadIdx.x;
    const int w    = tid >> 5, lane = tid & 31;
    const int g    = lane >> 2, tg = lane & 3;
    const int tile = blockIdx.x;
    const int oc0  = blockIdx.y << 7;
    const int which = blockIdx.z >> 1;
    const int b    = blockIdx.z & 1;
    const int wm   = w >> 2, wn = w & 3;
    const __half* wt = wtb + (size_t)which * 65536;
    const __half* in = (which == 0) ? in1 : (which == 1) ? in2 : in3;
    __half* out      = (which == 0) ? o1  : (which == 1) ? o2  : o3;
    const uint32_t sm_u = smem_u32(smc);
    const size_t r0 = ((size_t)b << 16) + (size_t)tile * 128;

    float acc[4][4][4];
#pragma unroll
    for (int mi = 0; mi < 4; mi++)
#pragma unroll
        for (int ni = 0; ni < 4; ni++)
#pragma unroll
            for (int r = 0; r < 4; r++) acc[mi][ni][r] = 0.f;

    gemm_core(wt, in, smc, sm_u, tid, lane, wm, wn, r0, oc0, acc);

    float* S = (float*)smc;
#pragma unroll
    for (int mi = 0; mi < 4; mi++) {
        int px = wm * 64 + mi * 16 + g;
#pragma unroll
        for (int ni = 0; ni < 4; ni++) {
            int oc = wn * 32 + ni * 8 + 2 * tg;
            S[px * 132 + oc]           = acc[mi][ni][0];
            S[px * 132 + oc + 1]       = acc[mi][ni][1];
            S[(px + 8) * 132 + oc]     = acc[mi][ni][2];
            S[(px + 8) * 132 + oc + 1] = acc[mi][ni][3];
        }
    }
    __syncthreads();
#pragma unroll
    for (int s2 = tid; s2 < 512; s2 += 256) {
        int px = s2 >> 2, seg = s2 & 3;
        int gp = tile * 128 + px;
        int y = gp >> 8, x = gp & 255;
        int win = ((y >> 3) << 5) + (x >> 3);
        int pix = ((y & 7) << 3) + (x & 7);
        int h = (oc0 >> 5) + seg;
        size_t dst = (((size_t)(b * 8 + h)) << 21) + ((size_t)win << 11) + (pix << 5);
        const float* src = &S[px * 132 + seg * 32];
        __half* dp = out + dst;
#pragma unroll
        for (int k2 = 0; k2 < 4; k2++) {
            float4 a2 = *(const float4*)&src[k2 * 8];
            float4 b2 = *(const float4*)&src[k2 * 8 + 4];
            uint4 o;
            o.x = f2h2(a2.x, a2.y); o.y = f2h2(a2.z, a2.w);
            o.z = f2h2(b2.x, b2.y); o.w = f2h2(b2.z, b2.w);
            *(uint4*)(dp + k2 * 8) = o;
        }
    }
}

// proj: NCHW fp32 out
__global__ void __launch_bounds__(256, 2) gemm_proj(const __half* __restrict__ wt,
                                                    const __half* __restrict__ in,
                                                    float* __restrict__ out) {
    extern __shared__ char smc[];
    const int tid  = threadIdx.x;
    const int w    = tid >> 5, lane = tid & 31;
    const int g    = lane >> 2, tg = lane & 3;
    const int tile = blockIdx.x;
    const int oc0  = blockIdx.y << 7;
    const int b    = blockIdx.z;
    const int wm   = w >> 2, wn = w & 3;
    const uint32_t sm_u = smem_u32(smc);
    const size_t r0 = ((size_t)b << 16) + (size_t)tile * 128;

    float acc[4][4][4];
#pragma unroll
    for (int mi = 0; mi < 4; mi++)
#pragma unroll
        for (int ni = 0; ni < 4; ni++)
#pragma unroll
            for (int r = 0; r < 4; r++) acc[mi][ni][r] = 0.f;

    gemm_core(wt, in, smc, sm_u, tid, lane, wm, wn, r0, oc0, acc);

    float* S = (float*)smc;
#pragma unroll
    for (int mi = 0; mi < 4; mi++) {
        int px = wm * 64 + mi * 16 + g;
#pragma unroll
        for (int ni = 0; ni < 4; ni++) {
            int oc = wn * 32 + ni * 8 + 2 * tg;
            S[oc * 132 + px]           = acc[mi][ni][0];
            S[(oc + 1) * 132 + px]     = acc[mi][ni][1];
            S[oc * 132 + px + 8]       = acc[mi][ni][2];
            S[(oc + 1) * 132 + px + 8] = acc[mi][ni][3];
        }
    }
    __syncthreads();
#pragma unroll
    for (int it = 0; it < 16; it++) {
        int oc = w + it * 8;
        float4 v = *(float4*)&S[oc * 132 + lane * 4];
        *(float4*)&out[(((size_t)(b * 256 + oc0 + oc)) << 16) + tile * 128 + lane * 4] = v;
    }
}

// ---------------- windowed attention (fp16 in, f32x2 math, fp16 out) ----------------
__global__ void __launch_bounds__(64) attn_kernel(const __half* __restrict__ q,
                                                  const __half* __restrict__ k,
                                                  const __half* __restrict__ v,
                                                  const float* __restrict__ is,
                                                  const float* __restrict__ ns,
                                                  const float* __restrict__ temp,
                                                  __half* __restrict__ out) {
    __shared__ __align__(16) float ks[64][32];
    __shared__ __align__(16) float vs[64][32];
    __shared__ float sc[64][65];
    const int i   = threadIdx.x;
    const int win = blockIdx.x;
    const int h   = blockIdx.y;
    const int b   = blockIdx.z;
    const size_t base = (((size_t)(b * 8 + h)) << 21) + ((size_t)win << 11);

    const int y = ((win >> 5) << 3) + (i >> 3);
    const int x = ((win & 31) << 3) + (i & 7);
    const int pidx = (b << 16) + (y << 8) + x;

    const uint4* kp4 = (const uint4*)(k + base + ((size_t)i << 5));
    const uint4* vp4 = (const uint4*)(v + base + ((size_t)i << 5));
    float kr[32];
    float kn = 0.f;
#pragma unroll
    for (int t = 0; t < 4; t++) {
        h8_to_f(kp4[t], kr + 8 * t);
        float vr[8];
        h8_to_f(vp4[t], vr);
#pragma unroll
        for (int u = 0; u < 8; u++) {
            kn = fmaf(kr[8*t + u], kr[8*t + u], kn);
            vs[i][8*t + u] = vr[u];
        }
    }
    float nsv = ns[pidx];
    float kmul = fminf(fmaxf(1.f - nsv, 0.f), 1.f) / fmaxf(sqrtf(kn), 1e-12f);
#pragma unroll
    for (int t = 0; t < 8; t++) {
        float4 o = {kr[4*t] * kmul, kr[4*t+1] * kmul, kr[4*t+2] * kmul, kr[4*t+3] * kmul};
        *(float4*)&ks[i][4*t] = o;
    }

    const uint4* qp4 = (const uint4*)(q + base + ((size_t)i << 5));
    float qr[32];
    float qn = 0.f;
#pragma unroll
    for (int t = 0; t < 4; t++) {
        h8_to_f(qp4[t], qr + 8 * t);
#pragma unroll
        for (int u = 0; u < 8; u++) qn = fmaf(qr[8*t + u], qr[8*t + u], qn);
    }
    float qmul = (1.f + is[pidx]) / fmaxf(sqrtf(qn), 1e-12f)
               * 0.17677669529663687f * temp[h];
    unsigned long long qp[16];
#pragma unroll
    for (int t = 0; t < 16; t++)
        qp[t] = pack2(qr[2*t] * qmul, qr[2*t+1] * qmul);

    __syncthreads();

    float mx = -1e30f;
#pragma unroll 4
    for (int j = 0; j < 64; j++) {
        const unsigned long long* kj = (const unsigned long long*)ks[j];
        unsigned long long a0 = 0ULL, a1 = 0ULL;
#pragma unroll
        for (int t = 0; t < 8; t++) {
            ffma2(a0, qp[2*t],     kj[2*t]);
            ffma2(a1, qp[2*t + 1], kj[2*t + 1]);
        }
        float l0, h0, l1, h1;
        unpack2(a0, l0, h0);
        unpack2(a1, l1, h1);
        float s = (l0 + h0) + (l1 + h1);
        sc[i][j] = s;
        mx = fmaxf(mx, s);
    }
    float sum = 0.f;
#pragma unroll
    for (int j = 0; j < 64; j++) {
        float e = __expf(sc[i][j] - mx);
        sc[i][j] = e;
        sum += e;
    }
    float inv = 1.f / sum;

    unsigned long long av[16];
#pragma unroll
    for (int t = 0; t < 16; t++) av[t] = 0ULL;
#pragma unroll 4
    for (int j = 0; j < 64; j++) {
        float p = sc[i][j];
        unsigned long long pp = pack2(p, p);
        const unsigned long long* vj = (const unsigned long long*)vs[j];
#pragma unroll
        for (int t = 0; t < 16; t++) ffma2(av[t], pp, vj[t]);
    }

    __half2* o2 = (__half2*)(out + (((size_t)pidx) << 8) + (h << 5));
#pragma unroll
    for (int t = 0; t < 16; t++) {
        float l, hh;
        unpack2(av[t], l, hh);
        o2[t] = __floats2half2_rn(l * inv, hh * inv);
    }
}

// ---------------- launch ----------------
extern "C" void kernel_launch(void* const* d_in, const int* in_sizes, int n_in,
                              void* d_out, int out_size) {
    const float* x      = (const float*)d_in[0];
    const float* w_iem  = (const float*)d_in[1];
    const float* g_iem  = (const float*)d_in[2];
    const float* b_iem  = (const float*)d_in[3];
    const float* w_nem  = (const float*)d_in[4];
    const float* g_nem  = (const float*)d_in[5];
    const float* b_nem  = (const float*)d_in[6];
    const float* w_idw  = (const float*)d_in[7];
    const float* w_ndw  = (const float*)d_in[8];
    const float* w_q    = (const float*)d_in[9];
    const float* w_k    = (const float*)d_in[10];
    const float* w_v    = (const float*)d_in[11];
    const float* w_proj = (const float*)d_in[12];
    const float* temp   = (const float*)d_in[13];
    float* out = (float*)d_out;

    float *PART, *BNA, *BNC, *IS, *NS;
    __half *Xh, *Hc1, *Hc2, *Hd1, *Hd2, *Hq, *Hk, *Hv, *Ha, *WCT, *WT4;
    cudaGetSymbolAddress((void**)&Xh,   g_Xh);
    cudaGetSymbolAddress((void**)&Hc1,  g_Hc1);
    cudaGetSymbolAddress((void**)&Hc2,  g_Hc2);
    cudaGetSymbolAddress((void**)&Hd1,  g_Hd1);
    cudaGetSymbolAddress((void**)&Hd2,  g_Hd2);
    cudaGetSymbolAddress((void**)&Hq,   g_Hq);
    cudaGetSymbolAddress((void**)&Hk,   g_Hk);
    cudaGetSymbolAddress((void**)&Hv,   g_Hv);
    cudaGetSymbolAddress((void**)&Ha,   g_Ha);
    cudaGetSymbolAddress((void**)&WCT,  g_wct);
    cudaGetSymbolAddress((void**)&WT4,  g_wt4);
    cudaGetSymbolAddress((void**)&PART, g_part);
    cudaGetSymbolAddress((void**)&BNA,  g_bna);
    cudaGetSymbolAddress((void**)&BNC,  g_bnc);
    cudaGetSymbolAddress((void**)&IS,   g_is);
    cudaGetSymbolAddress((void**)&NS,   g_ns);

    const int CSM = CONV_STG_B * 3;               // 99840
    const int GSM = 67584;                        // max(3*GEMM_STG_B=49152, epilogue)
    cudaFuncSetAttribute(conv_mma,  cudaFuncAttributeMaxDynamicSharedMemorySize, CSM);
    cudaFuncSetAttribute(gemm_qkv,  cudaFuncAttributeMaxDynamicSharedMemorySize, GSM);
    cudaFuncSetAttribute(gemm_proj, cudaFuncAttributeMaxDynamicSharedMemorySize, GSM);

    tconv_kernel<<<4608, 256>>>(w_iem, w_nem, WCT);
    t1x1_kernel<<<1024, 256>>>(w_q, w_k, w_v, w_proj, WT4);
    xT_kernel<<<dim3(2048, 8, 2), dim3(32, 32)>>>(x, Xh);

    conv_mma<<<dim3(512, 2, 4), 256, CSM>>>(Xh, WCT, Hc1, Hc2, PART);

    bnstats2<<<2, 256>>>(PART, g_iem, b_iem, g_nem, b_nem, BNA, BNC);

    dwconv_t<<<dim3(65536, 2), 256>>>(Hc1, Hc2, BNA, BNC, w_idw, w_ndw,
                                      Hd1, Hd2, IS, NS);

    gemm_qkv<<<dim3(512, 2, 6), 256, GSM>>>(WT4, Hd1, Hd2, Xh, Hq, Hk, Hv);

    attn_kernel<<<dim3(1024, 8, 2), 64>>>(Hq, Hk, Hv, IS, NS, temp, Ha);

    gemm_proj<<<dim3(512, 2, 2), 256, GSM>>>(WT4 + 3 * 65536, Ha, out);
}

// round 13
// speedup vs baseline: 6.5641x; 1.0979x over previous
#include <cuda_runtime.h>
#include <cuda_fp16.h>
#include <math.h>
#include <stdint.h>

#define HW 65536
#define NBUF (2*256*HW)

// ---------------- static scratch (all big intermediates fp16) ----------------
__device__ __half g_Xh[NBUF];       // x [b][px][c]
__device__ __half g_Hc1[NBUF];      // conv_iem out [r][c]
__device__ __half g_Hc2[NBUF];      // conv_nem out [r][c]
__device__ __half g_Hd1[NBUF];      // illum map [r][c]
__device__ __half g_Hd2[NBUF];      // noise map [r][c]
__device__ __half g_Hq[NBUF];       // q [r][c]
__device__ __half g_Hk[NBUF];       // k [r][c]
__device__ __half g_Hv[NBUF];       // v [r][c]
__device__ __half g_Ha[NBUF];       // attn out [r][c]
__device__ __half g_wct[2*589824];  // conv weights [m][tap][oc][c]
__device__ __half g_wt4[4*65536];   // 1x1 weights [m][oc][c]
__device__ float  g_part[1048576];  // bn partials [2][1024 cta][2][256 ch]
__device__ float  g_part2[32768];   // bn partials lvl2 [2][32][2][256]
__device__ float  g_bna[512];
__device__ float  g_bnc[512];
__device__ float  g_is[2*HW];
__device__ float  g_ns[2*HW];

// ---------------- helpers ----------------
__device__ __forceinline__ void ffma2(unsigned long long& d, unsigned long long a,
                                      unsigned long long b) {
    asm("fma.rn.f32x2 %0, %1, %2, %0;" : "+l"(d) : "l"(a), "l"(b));
}
__device__ __forceinline__ unsigned long long pack2(float lo, float hi) {
    unsigned long long r;
    asm("mov.b64 %0, {%1, %2};" : "=l"(r) : "f"(lo), "f"(hi));
    return r;
}
__device__ __forceinline__ void unpack2(unsigned long long p, float& lo, float& hi) {
    asm("mov.b64 {%0, %1}, %2;" : "=f"(lo), "=f"(hi) : "l"(p));
}
__device__ __forceinline__ uint32_t smem_u32(const void* p) {
    uint32_t a;
    asm("{ .reg .u64 t; cvta.to.shared.u64 t, %1; cvt.u32.u64 %0, t; }" : "=r"(a) : "l"(p));
    return a;
}
__device__ __forceinline__ uint32_t f2h2(float a, float b) {
    __half2 h = __floats2half2_rn(a, b);
    return *(uint32_t*)&h;
}
__device__ __forceinline__ void h8_to_f(uint4 t, float* f) {
    const __half2* hp = (const __half2*)&t;
#pragma unroll
    for (int u = 0; u < 4; u++) {
        float2 ff = __half22float2(hp[u]);
        f[2*u] = ff.x; f[2*u+1] = ff.y;
    }
}
__device__ __forceinline__ void cpa16(uint32_t s, const void* g, uint32_t n) {
    asm volatile("cp.async.cg.shared.global [%0], [%1], 16, %2;"
                 :: "r"(s), "l"(g), "r"(n) : "memory");
}
#define CP_COMMIT()  asm volatile("cp.async.commit_group;" ::: "memory")
#define CP_WAIT2()   asm volatile("cp.async.wait_group 2;" ::: "memory")
#define CP_WAIT1()   asm volatile("cp.async.wait_group 1;" ::: "memory")
#define CP_WAIT0()   asm volatile("cp.async.wait_group 0;" ::: "memory")

// fp16 m16n8k16 mma, fp32 accumulate (family-portable HMMA)
__device__ __forceinline__ void mma16(float* d, const uint32_t* a, const uint32_t* b) {
    asm volatile("mma.sync.aligned.m16n8k16.row.col.f32.f16.f16.f32 "
        "{%0,%1,%2,%3}, {%4,%5,%6,%7}, {%8,%9}, {%0,%1,%2,%3};"
        : "+f"(d[0]), "+f"(d[1]), "+f"(d[2]), "+f"(d[3])
        : "r"(a[0]), "r"(a[1]), "r"(a[2]), "r"(a[3]), "r"(b[0]), "r"(b[1]));
}
// ldmatrix x4 (sm_75+, family-portable)
__device__ __forceinline__ void ldsm4(uint32_t* r, uint32_t a) {
    asm volatile("ldmatrix.sync.aligned.m8n8.x4.shared.b16 {%0,%1,%2,%3}, [%4];"
        : "=r"(r[0]), "=r"(r[1]), "=r"(r[2]), "=r"(r[3]) : "r"(a));
}

// ---------------- weight prep ----------------
__global__ void tconv_kernel(const float* __restrict__ w0, const float* __restrict__ w1,
                             __half* __restrict__ out) {
    int i = blockIdx.x * 256 + threadIdx.x;          // 2*589824
    int m = i / 589824;
    int r = i - m * 589824;
    int tap = r >> 16;
    int rem = r & 65535;
    int oc  = rem >> 8;
    int c   = rem & 255;
    const float* w = m ? w1 : w0;
    out[i] = __float2half_rn(w[oc * 2304 + c * 9 + tap]);
}

__global__ void t1x1_kernel(const float* __restrict__ wq, const float* __restrict__ wk,
                            const float* __restrict__ wv, const float* __restrict__ wp,
                            __half* __restrict__ out) {
    int i = blockIdx.x * 256 + threadIdx.x;          // 4*65536
    int m = i >> 16;
    int r = i & 65535;
    int o = r >> 8;
    int c = r & 255;
    const float* w = (m == 0) ? wq : (m == 1) ? wk : (m == 2) ? wv : wp;
    out[i] = __float2half_rn(w[o * 256 + c]);
}

// ---------------- x transpose: NCHW -> [b][px][c] fp16 ----------------
__global__ void xT_kernel(const float* __restrict__ x, __half* __restrict__ xT) {
    __shared__ float t[32][33];
    int b  = blockIdx.z;
    int c0 = blockIdx.y * 32;
    int p0 = blockIdx.x * 32;
    int tx = threadIdx.x, ty = threadIdx.y;
    t[ty][tx] = x[(((size_t)((b << 8) + c0 + ty)) << 16) + p0 + tx];
    __syncthreads();
    xT[(((size_t)((b << 16) + p0 + ty)) << 8) + c0 + tx] = __float2half_rn(t[tx][ty]);
}

// ---------------- 3x3 conv implicit GEMM (fp16 mma + ldmatrix), 3-stage,
//                  both convs in one launch, BN partials fused ----------------
#define CONV_XS_B  8704
#define CONV_STG_B 33280
__global__ void __launch_bounds__(256, 2) conv_mma(const __half* __restrict__ xT,
                                                   const __half* __restrict__ W2base,
                                                   __half* __restrict__ out1,
                                                   __half* __restrict__ out2,
                                                   float* __restrict__ part) {
    extern __shared__ char smc[];
    const int tid  = threadIdx.x;
    const int w    = tid >> 5, lane = tid & 31;
    const int g    = lane >> 2, tg = lane & 3;
    const int y    = blockIdx.x >> 1;
    const int p0   = (blockIdx.x & 1) << 7;
    const int oc0  = blockIdx.y << 7;
    const int m    = blockIdx.z >> 1;
    const int b    = blockIdx.z & 1;
    const __half* W2 = W2base + (size_t)m * 589824;
    __half* out = m ? out2 : out1;
    const int wm   = w >> 2, wn = w & 3;
    const uint32_t sm_u = smem_u32(smc);
    const int aRowB = wm * 64 + (lane & 15);
    const int bRowB = wn * 32 + ((lane >> 4) << 3) + (lane & 7);
    const uint32_t aQ = (uint32_t)(lane >> 4);
    const uint32_t bQ = (uint32_t)((lane >> 3) & 1);

    float acc[4][4][4];
#pragma unroll
    for (int mi = 0; mi < 4; mi++)
#pragma unroll
        for (int ni = 0; ni < 4; ni++)
#pragma unroll
            for (int r = 0; r < 4; r++) acc[mi][ni][r] = 0.f;

    auto do_load = [&](int step, int buf) {
        int cc = step / 3;
        int ky = step - cc * 3;
        int c0 = cc * 32;
        uint32_t xs = sm_u + buf * CONV_STG_B;
        uint32_t ws = xs + CONV_XS_B;
        int yin = y + ky - 1;
        bool yok = (unsigned)yin < 256u;
#pragma unroll
        for (int jj = 0; jj < 3; jj++) {
            int j = jj * 256 + tid;
            if (j < 520) {
                int r = j >> 2, q = j & 3;
                int xin = p0 + r - 1;
                bool ok = yok && ((unsigned)xin < 256u);
                const __half* src = ok
                    ? xT + ((((size_t)b << 16) + ((size_t)yin << 8) + xin) << 8) + c0 + q * 8
                    : xT;
                cpa16(xs + r * 64 + ((q ^ ((r >> 1) & 3)) << 4), src, ok ? 16u : 0u);
            }
        }
#pragma unroll
        for (int jj = 0; jj < 6; jj++) {
            int j = jj * 256 + tid;
            int row = j >> 2, q = j & 3;          // row = kx*128+oc
            int kx = row >> 7, oc = row & 127;
            int tap = ky * 3 + kx;
            cpa16(ws + row * 64 + ((q ^ ((row >> 1) & 3)) << 4),
                  W2 + (((size_t)(tap * 256 + oc0 + oc)) << 8) + c0 + q * 8, 16u);
        }
        CP_COMMIT();
    };

    auto do_compute = [&](int buf) {
        uint32_t xs = sm_u + buf * CONV_STG_B;
        uint32_t ws = xs + CONV_XS_B;
#pragma unroll
        for (int kx = 0; kx < 3; kx++) {
#pragma unroll
            for (int ks = 0; ks < 2; ks++) {
                uint32_t af[4][4];
#pragma unroll
                for (int mi = 0; mi < 4; mi++) {
                    int row = aRowB + mi * 16 + kx;
                    uint32_t q = (uint32_t)(ks * 2) + aQ;
                    ldsm4(af[mi], xs + row * 64 + ((q ^ ((row >> 1) & 3)) << 4));
                }
                uint32_t bf[4][2];
#pragma unroll
                for (int pn = 0; pn < 2; pn++) {
                    int row = kx * 128 + bRowB + pn * 16;
                    uint32_t q = (uint32_t)(ks * 2) + bQ;
                    uint32_t t[4];
                    ldsm4(t, ws + row * 64 + ((q ^ ((row >> 1) & 3)) << 4));
                    bf[2*pn][0]   = t[0]; bf[2*pn][1]   = t[1];
                    bf[2*pn+1][0] = t[2]; bf[2*pn+1][1] = t[3];
                }
#pragma unroll
                for (int mi = 0; mi < 4; mi++)
#pragma unroll
                    for (int ni = 0; ni < 4; ni++)
                        mma16(acc[mi][ni], af[mi], bf[ni]);
            }
        }
    };

    do_load(0, 0);
    do_load(1, 1);
    for (int s = 0; s < 24; s++) {
        if (s < 23) { CP_WAIT1(); } else { CP_WAIT0(); }
        __syncthreads();
        if (s + 2 < 24) do_load(s + 2, (s + 2) % 3);
        do_compute(s % 3);
    }
    __syncthreads();

    float* S = (float*)smc;     // 128*132*4 = 67584
#pragma unroll
    for (int mi = 0; mi < 4; mi++) {
        int px = wm * 64 + mi * 16 + g;
#pragma unroll
        for (int ni = 0; ni < 4; ni++) {
            int oc = wn * 32 + ni * 8 + 2 * tg;
            S[px * 132 + oc]           = acc[mi][ni][0];
            S[px * 132 + oc + 1]       = acc[mi][ni][1];
            S[(px + 8) * 132 + oc]     = acc[mi][ni][2];
            S[(px + 8) * 132 + oc + 1] = acc[mi][ni][3];
        }
    }
    __syncthreads();
#pragma unroll
    for (int it = 0; it < 16; it++) {
        int px = w + it * 8;
        float4 v = *(float4*)&S[px * 132 + lane * 4];
        uint2 o;
        o.x = f2h2(v.x, v.y);
        o.y = f2h2(v.z, v.w);
        *(uint2*)(out + (((size_t)((b << 16) + (y << 8) + p0 + px)) << 8) + oc0 + lane * 4) = o;
    }
    // fused BN partials
    float* R = (float*)(smc + 67584);
    {
        int ocl = tid & 127, half = tid >> 7;
        float s = 0.f, s2 = 0.f;
#pragma unroll 8
        for (int px = 0; px < 64; px++) {
            float v = S[(half * 64 + px) * 132 + ocl];
            s += v; s2 = fmaf(v, v, s2);
        }
        R[(half * 128 + ocl) * 2]     = s;
        R[(half * 128 + ocl) * 2 + 1] = s2;
    }
    __syncthreads();
    if (tid < 128) {
        float s  = R[tid * 2]     + R[(128 + tid) * 2];
        float s2 = R[tid * 2 + 1] + R[(128 + tid) * 2 + 1];
        size_t base = ((size_t)(m * 1024 + b * 512 + blockIdx.x) * 2) * 256 + oc0 + tid;
        part[base]       = s;
        part[base + 256] = s2;
    }
}

// ---------------- BN stats: two-stage parallel reduce ----------------
__global__ void bnstats2a(const float* __restrict__ part, float* __restrict__ part2) {
    int m = blockIdx.x, chunk = blockIdx.y;
    int c = threadIdx.x;
    float s = 0.f, s2 = 0.f;
    for (int r = 0; r < 32; r++) {
        size_t base = ((size_t)(m * 1024 + chunk * 32 + r) * 2) * 256;
        s  += part[base + c];
        s2 += part[base + 256 + c];
    }
    size_t ob = ((size_t)(m * 32 + chunk) * 2) * 256;
    part2[ob + c]       = s;
    part2[ob + 256 + c] = s2;
}

__global__ void bnstats2b(const float* __restrict__ part2,
                          const float* __restrict__ g1, const float* __restrict__ b1,
                          const float* __restrict__ g2, const float* __restrict__ b2,
                          float* __restrict__ pa, float* __restrict__ pc) {
    int m = blockIdx.x;
    const float* gamma = m ? g2 : g1;
    const float* beta  = m ? b2 : b1;
    int c = threadIdx.x;
    float s = 0.f, s2 = 0.f;
    for (int r = 0; r < 32; r++) {
        size_t base = ((size_t)(m * 32 + r) * 2) * 256;
        s  += part2[base + c];
        s2 += part2[base + 256 + c];
    }
    float mean = s  * (1.f / 131072.f);
    float var  = s2 * (1.f / 131072.f) - mean * mean;
    float a = gamma[c] * rsqrtf(var + 1e-5f);
    pa[m * 256 + c] = a;
    pc[m * 256 + c] = beta[c] - mean * a;
}

// ---------------- depthwise conv pair, half2 loads, 2ch x 2px per thread,
//                  BN+relu6 fused, channel-mean fused ----------------
__global__ void __launch_bounds__(128) dwconv_t(
                         const __half* __restrict__ in1, const __half* __restrict__ in2,
                         const float* __restrict__ pa, const float* __restrict__ pc,
                         const float* __restrict__ wd1, const float* __restrict__ wd2,
                         __half* __restrict__ out1, __half* __restrict__ out2,
                         float* __restrict__ mean1, float* __restrict__ mean2) {
    __shared__ float red0[4], red1[4];
    int m = blockIdx.y;
    const __half* in  = m ? in2 : in1;
    const float*  wdw = m ? wd2 : wd1;
    __half* out       = m ? out2 : out1;
    float* mean_out   = m ? mean2 : mean1;
    int j = blockIdx.x;          // rows 2j, 2j+1 (same image row)
    int c2 = threadIdx.x;        // channel pair 0..127
    int r0 = j << 1;
    int p  = r0 & 65535;
    int y = p >> 8, xx = p & 255;          // xx even
    size_t bb = (size_t)(r0 - p) << 8;
    float a0 = pa[m * 256 + 2 * c2],     cb0 = pc[m * 256 + 2 * c2];
    float a1 = pa[m * 256 + 2 * c2 + 1], cb1 = pc[m * 256 + 2 * c2 + 1];
    float w0[9], w1[9];
#pragma unroll
    for (int t = 0; t < 9; t++) {
        w0[t] = wdw[(2 * c2) * 9 + t];
        w1[t] = wdw[(2 * c2 + 1) * 9 + t];
    }
    float accA0 = 0.f, accA1 = 0.f, accB0 = 0.f, accB1 = 0.f;  // (px, ch)
#pragma unroll
    for (int ky = 0; ky < 3; ky++) {
        int yy = y + ky - 1;
        if ((unsigned)yy >= 256u) continue;
        float v0[4], v1[4];
#pragma unroll
        for (int dx = 0; dx < 4; dx++) {
            int xv = xx + dx - 1;
            bool ok = (unsigned)xv < 256u;
            float2 f = {0.f, 0.f};
            if (ok) {
                __half2 hv = *(const __half2*)(in + (bb + (size_t)((yy << 8) + xv) * 256) + 2 * c2);
                f = __half22float2(hv);
            }
            float t0 = fminf(fmaxf(f.x * a0 + cb0, 0.f), 6.f);
            float t1 = fminf(fmaxf(f.y * a1 + cb1, 0.f), 6.f);
            v0[dx] = ok ? t0 : 0.f;
            v1[dx] = ok ? t1 : 0.f;
        }
        accA0 = fmaf(w0[ky*3+0], v0[0], accA0); accA0 = fmaf(w0[ky*3+1], v0[1], accA0); accA0 = fmaf(w0[ky*3+2], v0[2], accA0);
        accA1 = fmaf(w1[ky*3+0], v1[0], accA1); accA1 = fmaf(w1[ky*3+1], v1[1], accA1); accA1 = fmaf(w1[ky*3+2], v1[2], accA1);
        accB0 = fmaf(w0[ky*3+0], v0[1], accB0); accB0 = fmaf(w0[ky*3+1], v0[2], accB0); accB0 = fmaf(w0[ky*3+2], v0[3], accB0);
        accB1 = fmaf(w1[ky*3+0], v1[1], accB1); accB1 = fmaf(w1[ky*3+1], v1[2], accB1); accB1 = fmaf(w1[ky*3+2], v1[3], accB1);
    }
    *(__half2*)(out + (size_t)r0 * 256 + 2 * c2)       = __floats2half2_rn(accA0, accA1);
    *(__half2*)(out + (size_t)(r0 + 1) * 256 + 2 * c2) = __floats2half2_rn(accB0, accB1);

    float s0 = accA0 + accA1, s1 = accB0 + accB1;
#pragma unroll
    for (int off = 16; off; off >>= 1) {
        s0 += __shfl_xor_sync(0xffffffffu, s0, off);
        s1 += __shfl_xor_sync(0xffffffffu, s1, off);
    }
    if ((c2 & 31) == 0) { red0[c2 >> 5] = s0; red1[c2 >> 5] = s1; }
    __syncthreads();
    if (c2 < 4) {
        float t0 = red0[c2], t1 = red1[c2];
#pragma unroll
        for (int off = 2; off; off >>= 1) {
            t0 += __shfl_xor_sync(0xfu, t0, off);
            t1 += __shfl_xor_sync(0xfu, t1, off);
        }
        if (c2 == 0) {
            mean_out[r0]     = t0 * (1.f / 256.f);
            mean_out[r0 + 1] = t1 * (1.f / 256.f);
        }
    }
}

// ---------------- 1x1 GEMM core (fp16 mma + ldmatrix), 4-stage/3-deep ----------------
#define GEMM_XS_B  8192
#define GEMM_STG_B 16384
__device__ __forceinline__ void gemm_core(const __half* __restrict__ wt,
                                          const __half* __restrict__ in,
                                          uint32_t sm_u,
                                          int tid, int lane, int wm, int wn,
                                          size_t r0, int oc0, float acc[4][4][4]) {
    const int aRowB = wm * 64 + (lane & 15);
    const int bRowB = wn * 32 + ((lane >> 4) << 3) + (lane & 7);
    const uint32_t aQ = (uint32_t)(lane >> 4);
    const uint32_t bQ = (uint32_t)((lane >> 3) & 1);

    auto do_load = [&](int cc, int buf) {
        int c0 = cc * 32;
        uint32_t xs = sm_u + buf * GEMM_STG_B;
        uint32_t ws = xs + GEMM_XS_B;
#pragma unroll
        for (int jj = 0; jj < 2; jj++) {
            int j = jj * 256 + tid;
            int r = j >> 2, q = j & 3;
            cpa16(xs + r * 64 + ((q ^ ((r >> 1) & 3)) << 4),
                  in + (r0 + r) * 256 + c0 + q * 8, 16u);
        }
#pragma unroll
        for (int jj = 0; jj < 2; jj++) {
            int j = jj * 256 + tid;
            int r = j >> 2, q = j & 3;
            cpa16(ws + r * 64 + ((q ^ ((r >> 1) & 3)) << 4),
                  wt + (size_t)(oc0 + r) * 256 + c0 + q * 8, 16u);
        }
        CP_COMMIT();
    };

    auto do_compute = [&](int buf) {
        uint32_t xs = sm_u + buf * GEMM_STG_B;
        uint32_t ws = xs + GEMM_XS_B;
#pragma unroll
        for (int ks = 0; ks < 2; ks++) {
            uint32_t af[4][4];
#pragma unroll
            for (int mi = 0; mi < 4; mi++) {
                int row = aRowB + mi * 16;
                uint32_t q = (uint32_t)(ks * 2) + aQ;
                ldsm4(af[mi], xs + row * 64 + ((q ^ ((row >> 1) & 3)) << 4));
            }
            uint32_t bf[4][2];
#pragma unroll
            for (int pn = 0; pn < 2; pn++) {
                int row = bRowB + pn * 16;
                uint32_t q = (uint32_t)(ks * 2) + bQ;
                uint32_t t[4];
                ldsm4(t, ws + row * 64 + ((q ^ ((row >> 1) & 3)) << 4));
                bf[2*pn][0]   = t[0]; bf[2*pn][1]   = t[1];
                bf[2*pn+1][0] = t[2]; bf[2*pn+1][1] = t[3];
            }
#pragma unroll
            for (int mi = 0; mi < 4; mi++)
#pragma unroll
                for (int ni = 0; ni < 4; ni++)
                    mma16(acc[mi][ni], af[mi], bf[ni]);
        }
    };

    do_load(0, 0);
    do_load(1, 1);
    do_load(2, 2);
    for (int s = 0; s < 8; s++) {
        if (s < 6) { CP_WAIT2(); } else if (s == 6) { CP_WAIT1(); } else { CP_WAIT0(); }
        __syncthreads();
        if (s + 3 < 8) do_load(s + 3, (s + 3) & 3);
        do_compute(s & 3);
    }
    __syncthreads();   // epilogue smem aliases pipeline buffers
}

// q/k/v in one launch: grid (512, 2, 6); outputs plain [r][c] fp16
__global__ void __launch_bounds__(256, 2) gemm_qkv(const __half* __restrict__ wtb,
                                                   const __half* __restrict__ in1,
                                                   const __half* __restrict__ in2,
                                                   const __half* __restrict__ in3,
                                                   __half* __restrict__ o1,
                                                   __half* __restrict__ o2,
                                                   __half* __restrict__ o3) {
    extern __shared__ char smc[];
    const int tid  = threadIdx.x;
    const int w    = tid >> 5, lane = tid & 31;
    const int g    = lane >> 2, tg = lane & 3;
    const int tile = blockIdx.x;
    const int oc0  = blockIdx.y << 7;
    const int which = blockIdx.z >> 1;
    const int b    = blockIdx.z & 1;
    const int wm   = w >> 2, wn = w & 3;
    const __half* wt = wtb + (size_t)which * 65536;
    const __half* in = (which == 0) ? in1 : (which == 1) ? in2 : in3;
    __half* out      = (which == 0) ? o1  : (which == 1) ? o2  : o3;
    const uint32_t sm_u = smem_u32(smc);
    const size_t r0 = ((size_t)b << 16) + (size_t)tile * 128;

    float acc[4][4][4];
#pragma unroll
    for (int mi = 0; mi < 4; mi++)
#pragma unroll
        for (int ni = 0; ni < 4; ni++)
#pragma unroll
            for (int r = 0; r < 4; r++) acc[mi][ni][r] = 0.f;

    gemm_core(wt, in, sm_u, tid, lane, wm, wn, r0, oc0, acc);

    float* S = (float*)smc;
#pragma unroll
    for (int mi = 0; mi < 4; mi++) {
        int px = wm * 64 + mi * 16 + g;
#pragma unroll
        for (int ni = 0; ni < 4; ni++) {
            int oc = wn * 32 + ni * 8 + 2 * tg;
            S[px * 132 + oc]           = acc[mi][ni][0];
            S[px * 132 + oc + 1]       = acc[mi][ni][1];
            S[(px + 8) * 132 + oc]     = acc[mi][ni][2];
            S[(px + 8) * 132 + oc + 1] = acc[mi][ni][3];
        }
    }
    __syncthreads();
#pragma unroll
    for (int it = 0; it < 16; it++) {
        int px = w + it * 8;
        float4 v = *(float4*)&S[px * 132 + lane * 4];
        uint2 o;
        o.x = f2h2(v.x, v.y);
        o.y = f2h2(v.z, v.w);
        *(uint2*)(out + ((r0 + px) << 8) + oc0 + lane * 4) = o;
    }
}

// proj: NCHW fp32 out
__global__ void __launch_bounds__(256, 2) gemm_proj(const __half* __restrict__ wt,
                                                    const __half* __restrict__ in,
                                                    float* __restrict__ out) {
    extern __shared__ char smc[];
    const int tid  = threadIdx.x;
    const int w    = tid >> 5, lane = tid & 31;
    const int g    = lane >> 2, tg = lane & 3;
    const int tile = blockIdx.x;
    const int oc0  = blockIdx.y << 7;
    const int b    = blockIdx.z;
    const int wm   = w >> 2, wn = w & 3;
    const uint32_t sm_u = smem_u32(smc);
    const size_t r0 = ((size_t)b << 16) + (size_t)tile * 128;

    float acc[4][4][4];
#pragma unroll
    for (int mi = 0; mi < 4; mi++)
#pragma unroll
        for (int ni = 0; ni < 4; ni++)
#pragma unroll
            for (int r = 0; r < 4; r++) acc[mi][ni][r] = 0.f;

    gemm_core(wt, in, sm_u, tid, lane, wm, wn, r0, oc0, acc);

    float* S = (float*)smc;
#pragma unroll
    for (int mi = 0; mi < 4; mi++) {
        int px = wm * 64 + mi * 16 + g;
#pragma unroll
        for (int ni = 0; ni < 4; ni++) {
            int oc = wn * 32 + ni * 8 + 2 * tg;
            S[oc * 132 + px]           = acc[mi][ni][0];
            S[(oc + 1) * 132 + px]     = acc[mi][ni][1];
            S[oc * 132 + px + 8]       = acc[mi][ni][2];
            S[(oc + 1) * 132 + px + 8] = acc[mi][ni][3];
        }
    }
    __syncthreads();
#pragma unroll
    for (int it = 0; it < 16; it++) {
        int oc = w + it * 8;
        float4 v = *(float4*)&S[oc * 132 + lane * 4];
        *(float4*)&out[(((size_t)(b * 256 + oc0 + oc)) << 16) + tile * 128 + lane * 4] = v;
    }
}

// ---------------- windowed attention (fp16 [r][c] in, f32x2 math, fp16 out) ----------------
__global__ void __launch_bounds__(64) attn_kernel(const __half* __restrict__ q,
                                                  const __half* __restrict__ k,
                                                  const __half* __restrict__ v,
                                                  const float* __restrict__ is,
                                                  const float* __restrict__ ns,
                                                  const float* __restrict__ temp,
                                                  __half* __restrict__ out) {
    __shared__ __align__(16) float ks[64][32];
    __shared__ __align__(16) float vs[64][32];
    __shared__ float sc[64][65];
    const int i   = threadIdx.x;
    const int win = blockIdx.x;
    const int h   = blockIdx.y;
    const int b   = blockIdx.z;

    const int y = ((win >> 5) << 3) + (i >> 3);
    const int x = ((win & 31) << 3) + (i & 7);
    const int pidx = (b << 16) + (y << 8) + x;
    const size_t rc = ((size_t)pidx << 8) + (h << 5);

    const uint4* kp4 = (const uint4*)(k + rc);
    const uint4* vp4 = (const uint4*)(v + rc);
    float kr[32];
    float kn = 0.f;
#pragma unroll
    for (int t = 0; t < 4; t++) {
        h8_to_f(kp4[t], kr + 8 * t);
        float vr[8];
        h8_to_f(vp4[t], vr);
#pragma unroll
        for (int u = 0; u < 8; u++) {
            kn = fmaf(kr[8*t + u], kr[8*t + u], kn);
            vs[i][8*t + u] = vr[u];
        }
    }
    float nsv = ns[pidx];
    float kmul = fminf(fmaxf(1.f - nsv, 0.f), 1.f) / fmaxf(sqrtf(kn), 1e-12f);
#pragma unroll
    for (int t = 0; t < 8; t++) {
        float4 o = {kr[4*t] * kmul, kr[4*t+1] * kmul, kr[4*t+2] * kmul, kr[4*t+3] * kmul};
        *(float4*)&ks[i][4*t] = o;
    }

    const uint4* qp4 = (const uint4*)(q + rc);
    float qr[32];
    float qn = 0.f;
#pragma unroll
    for (int t = 0; t < 4; t++) {
        h8_to_f(qp4[t], qr + 8 * t);
#pragma unroll
        for (int u = 0; u < 8; u++) qn = fmaf(qr[8*t + u], qr[8*t + u], qn);
    }
    float qmul = (1.f + is[pidx]) / fmaxf(sqrtf(qn), 1e-12f)
               * 0.17677669529663687f * temp[h];
    unsigned long long qp[16];
#pragma unroll
    for (int t = 0; t < 16; t++)
        qp[t] = pack2(qr[2*t] * qmul, qr[2*t+1] * qmul);

    __syncthreads();

    float mx = -1e30f;
#pragma unroll 4
    for (int j = 0; j < 64; j++) {
        const unsigned long long* kj = (const unsigned long long*)ks[j];
        unsigned long long a0 = 0ULL, a1 = 0ULL;
#pragma unroll
        for (int t = 0; t < 8; t++) {
            ffma2(a0, qp[2*t],     kj[2*t]);
            ffma2(a1, qp[2*t + 1], kj[2*t + 1]);
        }
        float l0, h0, l1, h1;
        unpack2(a0, l0, h0);
        unpack2(a1, l1, h1);
        float s = (l0 + h0) + (l1 + h1);
        sc[i][j] = s;
        mx = fmaxf(mx, s);
    }
    float sum = 0.f;
#pragma unroll
    for (int j = 0; j < 64; j++) {
        float e = __expf(sc[i][j] - mx);
        sc[i][j] = e;
        sum += e;
    }
    float inv = 1.f / sum;

    unsigned long long av[16];
#pragma unroll
    for (int t = 0; t < 16; t++) av[t] = 0ULL;
#pragma unroll 4
    for (int j = 0; j < 64; j++) {
        float p = sc[i][j];
        unsigned long long pp = pack2(p, p);
        const unsigned long long* vj = (const unsigned long long*)vs[j];
#pragma unroll
        for (int t = 0; t < 16; t++) ffma2(av[t], pp, vj[t]);
    }

    __half2* o2 = (__half2*)(out + rc);
#pragma unroll
    for (int t = 0; t < 16; t++) {
        float l, hh;
        unpack2(av[t], l, hh);
        o2[t] = __floats2half2_rn(l * inv, hh * inv);
    }
}

// ---------------- launch ----------------
extern "C" void kernel_launch(void* const* d_in, const int* in_sizes, int n_in,
                              void* d_out, int out_size) {
    const float* x      = (const float*)d_in[0];
    const float* w_iem  = (const float*)d_in[1];
    const float* g_iem  = (const float*)d_in[2];
    const float* b_iem  = (const float*)d_in[3];
    const float* w_nem  = (const float*)d_in[4];
    const float* g_nem  = (const float*)d_in[5];
    const float* b_nem  = (const float*)d_in[6];
    const float* w_idw  = (const float*)d_in[7];
    const float* w_ndw  = (const float*)d_in[8];
    const float* w_q    = (const float*)d_in[9];
    const float* w_k    = (const float*)d_in[10];
    const float* w_v    = (const float*)d_in[11];
    const float* w_proj = (const float*)d_in[12];
    const float* temp   = (const float*)d_in[13];
    float* out = (float*)d_out;

    float *PART, *PART2, *BNA, *BNC, *IS, *NS;
    __half *Xh, *Hc1, *Hc2, *Hd1, *Hd2, *Hq, *Hk, *Hv, *Ha, *WCT, *WT4;
    cudaGetSymbolAddress((void**)&Xh,    g_Xh);
    cudaGetSymbolAddress((void**)&Hc1,   g_Hc1);
    cudaGetSymbolAddress((void**)&Hc2,   g_Hc2);
    cudaGetSymbolAddress((void**)&Hd1,   g_Hd1);
    cudaGetSymbolAddress((void**)&Hd2,   g_Hd2);
    cudaGetSymbolAddress((void**)&Hq,    g_Hq);
    cudaGetSymbolAddress((void**)&Hk,    g_Hk);
    cudaGetSymbolAddress((void**)&Hv,    g_Hv);
    cudaGetSymbolAddress((void**)&Ha,    g_Ha);
    cudaGetSymbolAddress((void**)&WCT,   g_wct);
    cudaGetSymbolAddress((void**)&WT4,   g_wt4);
    cudaGetSymbolAddress((void**)&PART,  g_part);
    cudaGetSymbolAddress((void**)&PART2, g_part2);
    cudaGetSymbolAddress((void**)&BNA,   g_bna);
    cudaGetSymbolAddress((void**)&BNC,   g_bnc);
    cudaGetSymbolAddress((void**)&IS,    g_is);
    cudaGetSymbolAddress((void**)&NS,    g_ns);

    const int CSM = CONV_STG_B * 3;               // 99840
    const int GSM = 67584;                        // max(4*GEMM_STG_B=65536, epilogue)
    cudaFuncSetAttribute(conv_mma,  cudaFuncAttributeMaxDynamicSharedMemorySize, CSM);
    cudaFuncSetAttribute(gemm_qkv,  cudaFuncAttributeMaxDynamicSharedMemorySize, GSM);
    cudaFuncSetAttribute(gemm_proj, cudaFuncAttributeMaxDynamicSharedMemorySize, GSM);

    tconv_kernel<<<4608, 256>>>(w_iem, w_nem, WCT);
    t1x1_kernel<<<1024, 256>>>(w_q, w_k, w_v, w_proj, WT4);
    xT_kernel<<<dim3(2048, 8, 2), dim3(32, 32)>>>(x, Xh);

    conv_mma<<<dim3(512, 2, 4), 256, CSM>>>(Xh, WCT, Hc1, Hc2, PART);

    bnstats2a<<<dim3(2, 32), 256>>>(PART, PART2);
    bnstats2b<<<2, 256>>>(PART2, g_iem, b_iem, g_nem, b_nem, BNA, BNC);

    dwconv_t<<<dim3(65536, 2), 128>>>(Hc1, Hc2, BNA, BNC, w_idw, w_ndw,
                                      Hd1, Hd2, IS, NS);

    gemm_qkv<<<dim3(512, 2, 6), 256, GSM>>>(WT4, Hd1, Hd2, Xh, Hq, Hk, Hv);

    attn_kernel<<<dim3(1024, 8, 2), 64>>>(Hq, Hk, Hv, IS, NS, temp, Ha);

    gemm_proj<<<dim3(512, 2, 2), 256, GSM>>>(WT4 + 3 * 65536, Ha, out);
}

// round 14
// speedup vs baseline: 8.2122x; 1.2511x over previous
#include <cuda_runtime.h>
#include <cuda_fp16.h>
#include <math.h>
#include <stdint.h>

#define HW 65536
#define NBUF (2*256*HW)

// ---------------- static scratch (all big intermediates fp16) ----------------
__device__ __half g_Xh[NBUF];       // x [b][px][c]
__device__ __half g_Hc1[NBUF];      // conv_iem out [r][c]
__device__ __half g_Hc2[NBUF];      // conv_nem out [r][c]
__device__ __half g_Hd1[NBUF];      // illum map [r][c]
__device__ __half g_Hd2[NBUF];      // noise map [r][c]
__device__ __half g_Hq[NBUF];       // q [r][c]
__device__ __half g_Hk[NBUF];       // k [r][c]
__device__ __half g_Hv[NBUF];       // v [r][c]
__device__ __half g_Ha[NBUF];       // attn out [r][c]
__device__ __half g_wct[2*589824];  // conv weights [m][tap][oc][c]
__device__ __half g_wt4[4*65536];   // 1x1 weights [m][oc][c]
__device__ float  g_part[1048576];  // bn partials [2][1024 cta][2][256 ch]
__device__ float  g_part2[32768];   // bn partials lvl2 [2][32][2][256]
__device__ float  g_bna[512];
__device__ float  g_bnc[512];
__device__ float  g_is[2*HW];
__device__ float  g_ns[2*HW];

// ---------------- helpers ----------------
__device__ __forceinline__ uint32_t smem_u32(const void* p) {
    uint32_t a;
    asm("{ .reg .u64 t; cvta.to.shared.u64 t, %1; cvt.u32.u64 %0, t; }" : "=r"(a) : "l"(p));
    return a;
}
__device__ __forceinline__ uint32_t f2h2(float a, float b) {
    __half2 h = __floats2half2_rn(a, b);
    return *(uint32_t*)&h;
}
__device__ __forceinline__ void h8_to_f(uint4 t, float* f) {
    const __half2* hp = (const __half2*)&t;
#pragma unroll
    for (int u = 0; u < 4; u++) {
        float2 ff = __half22float2(hp[u]);
        f[2*u] = ff.x; f[2*u+1] = ff.y;
    }
}
__device__ __forceinline__ void cpa16(uint32_t s, const void* g, uint32_t n) {
    asm volatile("cp.async.cg.shared.global [%0], [%1], 16, %2;"
                 :: "r"(s), "l"(g), "r"(n) : "memory");
}
#define CP_COMMIT()  asm volatile("cp.async.commit_group;" ::: "memory")
#define CP_WAIT2()   asm volatile("cp.async.wait_group 2;" ::: "memory")
#define CP_WAIT1()   asm volatile("cp.async.wait_group 1;" ::: "memory")
#define CP_WAIT0()   asm volatile("cp.async.wait_group 0;" ::: "memory")

// fp16 m16n8k16 mma, fp32 accumulate (family-portable HMMA)
__device__ __forceinline__ void mma16(float* d, const uint32_t* a, const uint32_t* b) {
    asm volatile("mma.sync.aligned.m16n8k16.row.col.f32.f16.f16.f32 "
        "{%0,%1,%2,%3}, {%4,%5,%6,%7}, {%8,%9}, {%0,%1,%2,%3};"
        : "+f"(d[0]), "+f"(d[1]), "+f"(d[2]), "+f"(d[3])
        : "r"(a[0]), "r"(a[1]), "r"(a[2]), "r"(a[3]), "r"(b[0]), "r"(b[1]));
}
// ldmatrix x4 (sm_75+, family-portable)
__device__ __forceinline__ void ldsm4(uint32_t* r, uint32_t a) {
    asm volatile("ldmatrix.sync.aligned.m8n8.x4.shared.b16 {%0,%1,%2,%3}, [%4];"
        : "=r"(r[0]), "=r"(r[1]), "=r"(r[2]), "=r"(r[3]) : "r"(a));
}

// ---------------- weight prep ----------------
__global__ void tconv_kernel(const float* __restrict__ w0, const float* __restrict__ w1,
                             __half* __restrict__ out) {
    int i = blockIdx.x * 256 + threadIdx.x;          // 2*589824
    int m = i / 589824;
    int r = i - m * 589824;
    int tap = r >> 16;
    int rem = r & 65535;
    int oc  = rem >> 8;
    int c   = rem & 255;
    const float* w = m ? w1 : w0;
    out[i] = __float2half_rn(w[oc * 2304 + c * 9 + tap]);
}

__global__ void t1x1_kernel(const float* __restrict__ wq, const float* __restrict__ wk,
                            const float* __restrict__ wv, const float* __restrict__ wp,
                            __half* __restrict__ out) {
    int i = blockIdx.x * 256 + threadIdx.x;          // 4*65536
    int m = i >> 16;
    int r = i & 65535;
    int o = r >> 8;
    int c = r & 255;
    const float* w = (m == 0) ? wq : (m == 1) ? wk : (m == 2) ? wv : wp;
    out[i] = __float2half_rn(w[o * 256 + c]);
}

// ---------------- x transpose: NCHW -> [b][px][c] fp16 ----------------
__global__ void xT_kernel(const float* __restrict__ x, __half* __restrict__ xT) {
    __shared__ float t[32][33];
    int b  = blockIdx.z;
    int c0 = blockIdx.y * 32;
    int p0 = blockIdx.x * 32;
    int tx = threadIdx.x, ty = threadIdx.y;
    t[ty][tx] = x[(((size_t)((b << 8) + c0 + ty)) << 16) + p0 + tx];
    __syncthreads();
    xT[(((size_t)((b << 16) + p0 + ty)) << 8) + c0 + tx] = __float2half_rn(t[tx][ty]);
}

// ---------------- 3x3 conv implicit GEMM (fp16 mma + ldmatrix), 3-stage,
//                  both convs in one launch, BN partials fused ----------------
#define CONV_XS_B  8704
#define CONV_STG_B 33280
__global__ void __launch_bounds__(256, 2) conv_mma(const __half* __restrict__ xT,
                                                   const __half* __restrict__ W2base,
                                                   __half* __restrict__ out1,
                                                   __half* __restrict__ out2,
                                                   float* __restrict__ part) {
    extern __shared__ char smc[];
    const int tid  = threadIdx.x;
    const int w    = tid >> 5, lane = tid & 31;
    const int g    = lane >> 2, tg = lane & 3;
    const int y    = blockIdx.x >> 1;
    const int p0   = (blockIdx.x & 1) << 7;
    const int oc0  = blockIdx.y << 7;
    const int m    = blockIdx.z >> 1;
    const int b    = blockIdx.z & 1;
    const __half* W2 = W2base + (size_t)m * 589824;
    __half* out = m ? out2 : out1;
    const int wm   = w >> 2, wn = w & 3;
    const uint32_t sm_u = smem_u32(smc);
    const int aRowB = wm * 64 + (lane & 15);
    const int bRowB = wn * 32 + ((lane >> 4) << 3) + (lane & 7);
    const uint32_t aQ = (uint32_t)(lane >> 4);
    const uint32_t bQ = (uint32_t)((lane >> 3) & 1);

    float acc[4][4][4];
#pragma unroll
    for (int mi = 0; mi < 4; mi++)
#pragma unroll
        for (int ni = 0; ni < 4; ni++)
#pragma unroll
            for (int r = 0; r < 4; r++) acc[mi][ni][r] = 0.f;

    auto do_load = [&](int step, int buf) {
        int cc = step / 3;
        int ky = step - cc * 3;
        int c0 = cc * 32;
        uint32_t xs = sm_u + buf * CONV_STG_B;
        uint32_t ws = xs + CONV_XS_B;
        int yin = y + ky - 1;
        bool yok = (unsigned)yin < 256u;
#pragma unroll
        for (int jj = 0; jj < 3; jj++) {
            int j = jj * 256 + tid;
            if (j < 520) {
                int r = j >> 2, q = j & 3;
                int xin = p0 + r - 1;
                bool ok = yok && ((unsigned)xin < 256u);
                const __half* src = ok
                    ? xT + ((((size_t)b << 16) + ((size_t)yin << 8) + xin) << 8) + c0 + q * 8
                    : xT;
                cpa16(xs + r * 64 + ((q ^ ((r >> 1) & 3)) << 4), src, ok ? 16u : 0u);
            }
        }
#pragma unroll
        for (int jj = 0; jj < 6; jj++) {
            int j = jj * 256 + tid;
            int row = j >> 2, q = j & 3;          // row = kx*128+oc
            int kx = row >> 7, oc = row & 127;
            int tap = ky * 3 + kx;
            cpa16(ws + row * 64 + ((q ^ ((row >> 1) & 3)) << 4),
                  W2 + (((size_t)(tap * 256 + oc0 + oc)) << 8) + c0 + q * 8, 16u);
        }
        CP_COMMIT();
    };

    auto do_compute = [&](int buf) {
        uint32_t xs = sm_u + buf * CONV_STG_B;
        uint32_t ws = xs + CONV_XS_B;
#pragma unroll
        for (int kx = 0; kx < 3; kx++) {
#pragma unroll
            for (int ks = 0; ks < 2; ks++) {
                uint32_t af[4][4];
#pragma unroll
                for (int mi = 0; mi < 4; mi++) {
                    int row = aRowB + mi * 16 + kx;
                    uint32_t q = (uint32_t)(ks * 2) + aQ;
                    ldsm4(af[mi], xs + row * 64 + ((q ^ ((row >> 1) & 3)) << 4));
                }
                uint32_t bf[4][2];
#pragma unroll
                for (int pn = 0; pn < 2; pn++) {
                    int row = kx * 128 + bRowB + pn * 16;
                    uint32_t q = (uint32_t)(ks * 2) + bQ;
                    uint32_t t[4];
                    ldsm4(t, ws + row * 64 + ((q ^ ((row >> 1) & 3)) << 4));
                    bf[2*pn][0]   = t[0]; bf[2*pn][1]   = t[1];
                    bf[2*pn+1][0] = t[2]; bf[2*pn+1][1] = t[3];
                }
#pragma unroll
                for (int mi = 0; mi < 4; mi++)
#pragma unroll
                    for (int ni = 0; ni < 4; ni++)
                        mma16(acc[mi][ni], af[mi], bf[ni]);
            }
        }
    };

    do_load(0, 0);
    do_load(1, 1);
    for (int s = 0; s < 24; s++) {
        if (s < 23) { CP_WAIT1(); } else { CP_WAIT0(); }
        __syncthreads();
        if (s + 2 < 24) do_load(s + 2, (s + 2) % 3);
        do_compute(s % 3);
    }
    __syncthreads();

    float* S = (float*)smc;     // 128*132*4 = 67584
#pragma unroll
    for (int mi = 0; mi < 4; mi++) {
        int px = wm * 64 + mi * 16 + g;
#pragma unroll
        for (int ni = 0; ni < 4; ni++) {
            int oc = wn * 32 + ni * 8 + 2 * tg;
            S[px * 132 + oc]           = acc[mi][ni][0];
            S[px * 132 + oc + 1]       = acc[mi][ni][1];
            S[(px + 8) * 132 + oc]     = acc[mi][ni][2];
            S[(px + 8) * 132 + oc + 1] = acc[mi][ni][3];
        }
    }
    __syncthreads();
#pragma unroll
    for (int it = 0; it < 16; it++) {
        int px = w + it * 8;
        float4 v = *(float4*)&S[px * 132 + lane * 4];
        uint2 o;
        o.x = f2h2(v.x, v.y);
        o.y = f2h2(v.z, v.w);
        *(uint2*)(out + (((size_t)((b << 16) + (y << 8) + p0 + px)) << 8) + oc0 + lane * 4) = o;
    }
    // fused BN partials
    float* R = (float*)(smc + 67584);
    {
        int ocl = tid & 127, half = tid >> 7;
        float s = 0.f, s2 = 0.f;
#pragma unroll 8
        for (int px = 0; px < 64; px++) {
            float v = S[(half * 64 + px) * 132 + ocl];
            s += v; s2 = fmaf(v, v, s2);
        }
        R[(half * 128 + ocl) * 2]     = s;
        R[(half * 128 + ocl) * 2 + 1] = s2;
    }
    __syncthreads();
    if (tid < 128) {
        float s  = R[tid * 2]     + R[(128 + tid) * 2];
        float s2 = R[tid * 2 + 1] + R[(128 + tid) * 2 + 1];
        size_t base = ((size_t)(m * 1024 + b * 512 + blockIdx.x) * 2) * 256 + oc0 + tid;
        part[base]       = s;
        part[base + 256] = s2;
    }
}

// ---------------- BN stats: two-stage parallel reduce ----------------
__global__ void bnstats2a(const float* __restrict__ part, float* __restrict__ part2) {
    int m = blockIdx.x, chunk = blockIdx.y;
    int c = threadIdx.x;
    float s = 0.f, s2 = 0.f;
    for (int r = 0; r < 32; r++) {
        size_t base = ((size_t)(m * 1024 + chunk * 32 + r) * 2) * 256;
        s  += part[base + c];
        s2 += part[base + 256 + c];
    }
    size_t ob = ((size_t)(m * 32 + chunk) * 2) * 256;
    part2[ob + c]       = s;
    part2[ob + 256 + c] = s2;
}

__global__ void bnstats2b(const float* __restrict__ part2,
                          const float* __restrict__ g1, const float* __restrict__ b1,
                          const float* __restrict__ g2, const float* __restrict__ b2,
                          float* __restrict__ pa, float* __restrict__ pc) {
    int m = blockIdx.x;
    const float* gamma = m ? g2 : g1;
    const float* beta  = m ? b2 : b1;
    int c = threadIdx.x;
    float s = 0.f, s2 = 0.f;
    for (int r = 0; r < 32; r++) {
        size_t base = ((size_t)(m * 32 + r) * 2) * 256;
        s  += part2[base + c];
        s2 += part2[base + 256 + c];
    }
    float mean = s  * (1.f / 131072.f);
    float var  = s2 * (1.f / 131072.f) - mean * mean;
    float a = gamma[c] * rsqrtf(var + 1e-5f);
    pa[m * 256 + c] = a;
    pc[m * 256 + c] = beta[c] - mean * a;
}

// ---------------- depthwise conv pair, half2 loads, 2ch x 2px per thread,
//                  BN+relu6 fused, channel-mean fused ----------------
__global__ void __launch_bounds__(128) dwconv_t(
                         const __half* __restrict__ in1, const __half* __restrict__ in2,
                         const float* __restrict__ pa, const float* __restrict__ pc,
                         const float* __restrict__ wd1, const float* __restrict__ wd2,
                         __half* __restrict__ out1, __half* __restrict__ out2,
                         float* __restrict__ mean1, float* __restrict__ mean2) {
    __shared__ float red0[4], red1[4];
    int m = blockIdx.y;
    const __half* in  = m ? in2 : in1;
    const float*  wdw = m ? wd2 : wd1;
    __half* out       = m ? out2 : out1;
    float* mean_out   = m ? mean2 : mean1;
    int j = blockIdx.x;          // rows 2j, 2j+1 (same image row)
    int c2 = threadIdx.x;        // channel pair 0..127
    int r0 = j << 1;
    int p  = r0 & 65535;
    int y = p >> 8, xx = p & 255;          // xx even
    size_t bb = (size_t)(r0 - p) << 8;
    float a0 = pa[m * 256 + 2 * c2],     cb0 = pc[m * 256 + 2 * c2];
    float a1 = pa[m * 256 + 2 * c2 + 1], cb1 = pc[m * 256 + 2 * c2 + 1];
    float w0[9], w1[9];
#pragma unroll
    for (int t = 0; t < 9; t++) {
        w0[t] = wdw[(2 * c2) * 9 + t];
        w1[t] = wdw[(2 * c2 + 1) * 9 + t];
    }
    float accA0 = 0.f, accA1 = 0.f, accB0 = 0.f, accB1 = 0.f;
#pragma unroll
    for (int ky = 0; ky < 3; ky++) {
        int yy = y + ky - 1;
        if ((unsigned)yy >= 256u) continue;
        float v0[4], v1[4];
#pragma unroll
        for (int dx = 0; dx < 4; dx++) {
            int xv = xx + dx - 1;
            bool ok = (unsigned)xv < 256u;
            float2 f = {0.f, 0.f};
            if (ok) {
                __half2 hv = *(const __half2*)(in + (bb + (size_t)((yy << 8) + xv) * 256) + 2 * c2);
                f = __half22float2(hv);
            }
            float t0 = fminf(fmaxf(f.x * a0 + cb0, 0.f), 6.f);
            float t1 = fminf(fmaxf(f.y * a1 + cb1, 0.f), 6.f);
            v0[dx] = ok ? t0 : 0.f;
            v1[dx] = ok ? t1 : 0.f;
        }
        accA0 = fmaf(w0[ky*3+0], v0[0], accA0); accA0 = fmaf(w0[ky*3+1], v0[1], accA0); accA0 = fmaf(w0[ky*3+2], v0[2], accA0);
        accA1 = fmaf(w1[ky*3+0], v1[0], accA1); accA1 = fmaf(w1[ky*3+1], v1[1], accA1); accA1 = fmaf(w1[ky*3+2], v1[2], accA1);
        accB0 = fmaf(w0[ky*3+0], v0[1], accB0); accB0 = fmaf(w0[ky*3+1], v0[2], accB0); accB0 = fmaf(w0[ky*3+2], v0[3], accB0);
        accB1 = fmaf(w1[ky*3+0], v1[1], accB1); accB1 = fmaf(w1[ky*3+1], v1[2], accB1); accB1 = fmaf(w1[ky*3+2], v1[3], accB1);
    }
    *(__half2*)(out + (size_t)r0 * 256 + 2 * c2)       = __floats2half2_rn(accA0, accA1);
    *(__half2*)(out + (size_t)(r0 + 1) * 256 + 2 * c2) = __floats2half2_rn(accB0, accB1);

    float s0 = accA0 + accA1, s1 = accB0 + accB1;
#pragma unroll
    for (int off = 16; off; off >>= 1) {
        s0 += __shfl_xor_sync(0xffffffffu, s0, off);
        s1 += __shfl_xor_sync(0xffffffffu, s1, off);
    }
    if ((c2 & 31) == 0) { red0[c2 >> 5] = s0; red1[c2 >> 5] = s1; }
    __syncthreads();
    if (c2 < 4) {
        float t0 = red0[c2], t1 = red1[c2];
#pragma unroll
        for (int off = 2; off; off >>= 1) {
            t0 += __shfl_xor_sync(0xfu, t0, off);
            t1 += __shfl_xor_sync(0xfu, t1, off);
        }
        if (c2 == 0) {
            mean_out[r0]     = t0 * (1.f / 256.f);
            mean_out[r0 + 1] = t1 * (1.f / 256.f);
        }
    }
}

// ---------------- 1x1 GEMM core (fp16 mma + ldmatrix), 4-stage/3-deep ----------------
#define GEMM_XS_B  8192
#define GEMM_STG_B 16384
__device__ __forceinline__ void gemm_core(const __half* __restrict__ wt,
                                          const __half* __restrict__ in,
                                          uint32_t sm_u,
                                          int tid, int lane, int wm, int wn,
                                          size_t r0, int oc0, float acc[4][4][4]) {
    const int aRowB = wm * 64 + (lane & 15);
    const int bRowB = wn * 32 + ((lane >> 4) << 3) + (lane & 7);
    const uint32_t aQ = (uint32_t)(lane >> 4);
    const uint32_t bQ = (uint32_t)((lane >> 3) & 1);

    auto do_load = [&](int cc, int buf) {
        int c0 = cc * 32;
        uint32_t xs = sm_u + buf * GEMM_STG_B;
        uint32_t ws = xs + GEMM_XS_B;
#pragma unroll
        for (int jj = 0; jj < 2; jj++) {
            int j = jj * 256 + tid;
            int r = j >> 2, q = j & 3;
            cpa16(xs + r * 64 + ((q ^ ((r >> 1) & 3)) << 4),
                  in + (r0 + r) * 256 + c0 + q * 8, 16u);
        }
#pragma unroll
        for (int jj = 0; jj < 2; jj++) {
            int j = jj * 256 + tid;
            int r = j >> 2, q = j & 3;
            cpa16(ws + r * 64 + ((q ^ ((r >> 1) & 3)) << 4),
                  wt + (size_t)(oc0 + r) * 256 + c0 + q * 8, 16u);
        }
        CP_COMMIT();
    };

    auto do_compute = [&](int buf) {
        uint32_t xs = sm_u + buf * GEMM_STG_B;
        uint32_t ws = xs + GEMM_XS_B;
#pragma unroll
        for (int ks = 0; ks < 2; ks++) {
            uint32_t af[4][4];
#pragma unroll
            for (int mi = 0; mi < 4; mi++) {
                int row = aRowB + mi * 16;
                uint32_t q = (uint32_t)(ks * 2) + aQ;
                ldsm4(af[mi], xs + row * 64 + ((q ^ ((row >> 1) & 3)) << 4));
            }
            uint32_t bf[4][2];
#pragma unroll
            for (int pn = 0; pn < 2; pn++) {
                int row = bRowB + pn * 16;
                uint32_t q = (uint32_t)(ks * 2) + bQ;
                uint32_t t[4];
                ldsm4(t, ws + row * 64 + ((q ^ ((row >> 1) & 3)) << 4));
                bf[2*pn][0]   = t[0]; bf[2*pn][1]   = t[1];
                bf[2*pn+1][0] = t[2]; bf[2*pn+1][1] = t[3];
            }
#pragma unroll
            for (int mi = 0; mi < 4; mi++)
#pragma unroll
                for (int ni = 0; ni < 4; ni++)
                    mma16(acc[mi][ni], af[mi], bf[ni]);
        }
    };

    do_load(0, 0);
    do_load(1, 1);
    do_load(2, 2);
    for (int s = 0; s < 8; s++) {
        if (s < 6) { CP_WAIT2(); } else if (s == 6) { CP_WAIT1(); } else { CP_WAIT0(); }
        __syncthreads();
        if (s + 3 < 8) do_load(s + 3, (s + 3) & 3);
        do_compute(s & 3);
    }
    __syncthreads();
}

// q/k/v in one launch: grid (512, 2, 6); outputs plain [r][c] fp16
__global__ void __launch_bounds__(256, 2) gemm_qkv(const __half* __restrict__ wtb,
                                                   const __half* __restrict__ in1,
                                                   const __half* __restrict__ in2,
                                                   const __half* __restrict__ in3,
                                                   __half* __restrict__ o1,
                                                   __half* __restrict__ o2,
                                                   __half* __restrict__ o3) {
    extern __shared__ char smc[];
    const int tid  = threadIdx.x;
    const int w    = tid >> 5, lane = tid & 31;
    const int g    = lane >> 2, tg = lane & 3;
    const int tile = blockIdx.x;
    const int oc0  = blockIdx.y << 7;
    const int which = blockIdx.z >> 1;
    const int b    = blockIdx.z & 1;
    const int wm   = w >> 2, wn = w & 3;
    const __half* wt = wtb + (size_t)which * 65536;
    const __half* in = (which == 0) ? in1 : (which == 1) ? in2 : in3;
    __half* out      = (which == 0) ? o1  : (which == 1) ? o2  : o3;
    const uint32_t sm_u = smem_u32(smc);
    const size_t r0 = ((size_t)b << 16) + (size_t)tile * 128;

    float acc[4][4][4];
#pragma unroll
    for (int mi = 0; mi < 4; mi++)
#pragma unroll
        for (int ni = 0; ni < 4; ni++)
#pragma unroll
            for (int r = 0; r < 4; r++) acc[mi][ni][r] = 0.f;

    gemm_core(wt, in, sm_u, tid, lane, wm, wn, r0, oc0, acc);

    float* S = (float*)smc;
#pragma unroll
    for (int mi = 0; mi < 4; mi++) {
        int px = wm * 64 + mi * 16 + g;
#pragma unroll
        for (int ni = 0; ni < 4; ni++) {
            int oc = wn * 32 + ni * 8 + 2 * tg;
            S[px * 132 + oc]           = acc[mi][ni][0];
            S[px * 132 + oc + 1]       = acc[mi][ni][1];
            S[(px + 8) * 132 + oc]     = acc[mi][ni][2];
            S[(px + 8) * 132 + oc + 1] = acc[mi][ni][3];
        }
    }
    __syncthreads();
#pragma unroll
    for (int it = 0; it < 16; it++) {
        int px = w + it * 8;
        float4 v = *(float4*)&S[px * 132 + lane * 4];
        uint2 o;
        o.x = f2h2(v.x, v.y);
        o.y = f2h2(v.z, v.w);
        *(uint2*)(out + ((r0 + px) << 8) + oc0 + lane * 4) = o;
    }
}

// proj: NCHW fp32 out
__global__ void __launch_bounds__(256, 2) gemm_proj(const __half* __restrict__ wt,
                                                    const __half* __restrict__ in,
                                                    float* __restrict__ out) {
    extern __shared__ char smc[];
    const int tid  = threadIdx.x;
    const int w    = tid >> 5, lane = tid & 31;
    const int g    = lane >> 2, tg = lane & 3;
    const int tile = blockIdx.x;
    const int oc0  = blockIdx.y << 7;
    const int b    = blockIdx.z;
    const int wm   = w >> 2, wn = w & 3;
    const uint32_t sm_u = smem_u32(smc);
    const size_t r0 = ((size_t)b << 16) + (size_t)tile * 128;

    float acc[4][4][4];
#pragma unroll
    for (int mi = 0; mi < 4; mi++)
#pragma unroll
        for (int ni = 0; ni < 4; ni++)
#pragma unroll
            for (int r = 0; r < 4; r++) acc[mi][ni][r] = 0.f;

    gemm_core(wt, in, sm_u, tid, lane, wm, wn, r0, oc0, acc);

    float* S = (float*)smc;
#pragma unroll
    for (int mi = 0; mi < 4; mi++) {
        int px = wm * 64 + mi * 16 + g;
#pragma unroll
        for (int ni = 0; ni < 4; ni++) {
            int oc = wn * 32 + ni * 8 + 2 * tg;
            S[oc * 132 + px]           = acc[mi][ni][0];
            S[(oc + 1) * 132 + px]     = acc[mi][ni][1];
            S[oc * 132 + px + 8]       = acc[mi][ni][2];
            S[(oc + 1) * 132 + px + 8] = acc[mi][ni][3];
        }
    }
    __syncthreads();
#pragma unroll
    for (int it = 0; it < 16; it++) {
        int oc = w + it * 8;
        float4 v = *(float4*)&S[oc * 132 + lane * 4];
        *(float4*)&out[(((size_t)(b * 256 + oc0 + oc)) << 16) + tile * 128 + lane * 4] = v;
    }
}

// ---------------- windowed attention on tensor cores ----------------
// 1 block = 1 window, 128 threads = 4 warps (warp w owns q-rows 16w..16w+15).
__global__ void __launch_bounds__(128) attn_mma(const __half* __restrict__ q,
                                                const __half* __restrict__ k,
                                                const __half* __restrict__ v,
                                                const float* __restrict__ is,
                                                const float* __restrict__ ns,
                                                const float* __restrict__ temp,
                                                __half* __restrict__ out) {
    __shared__ __align__(16) __half Qs[64 * 40];   // 80B rows
    __shared__ __align__(16) __half Ks[64 * 40];
    __shared__ __align__(16) __half Vt[32 * 72];   // 144B rows, [d][j]
    const int t   = threadIdx.x;
    const int win = blockIdx.x;
    const int h   = blockIdx.y;
    const int b   = blockIdx.z;
    const int w   = t >> 5, lane = t & 31;
    const int g   = lane >> 2, tg = lane & 3;

    // ---- load + scale phase: 2 threads per row ----
    {
        int i = t >> 1, hp = t & 1;
        int y = ((win >> 5) << 3) + (i >> 3);
        int x = ((win & 31) << 3) + (i & 7);
        int pidx = (b << 16) + (y << 8) + x;
        size_t rc = ((size_t)pidx << 8) + (h << 5) + hp * 16;
        float qf[16], kf[16], vf[16];
        {
            const uint4* p4 = (const uint4*)(q + rc);
            h8_to_f(p4[0], qf); h8_to_f(p4[1], qf + 8);
        }
        {
            const uint4* p4 = (const uint4*)(k + rc);
            h8_to_f(p4[0], kf); h8_to_f(p4[1], kf + 8);
        }
        {
            const uint4* p4 = (const uint4*)(v + rc);
            h8_to_f(p4[0], vf); h8_to_f(p4[1], vf + 8);
        }
        float qn = 0.f, kn = 0.f;
#pragma unroll
        for (int u = 0; u < 16; u++) {
            qn = fmaf(qf[u], qf[u], qn);
            kn = fmaf(kf[u], kf[u], kn);
        }
        qn += __shfl_xor_sync(0xffffffffu, qn, 1);
        kn += __shfl_xor_sync(0xffffffffu, kn, 1);
        float nsv = ns[pidx];
        float kmul = fminf(fmaxf(1.f - nsv, 0.f), 1.f) / fmaxf(sqrtf(kn), 1e-12f);
        float qmul = (1.f + is[pidx]) / fmaxf(sqrtf(qn), 1e-12f)
                   * 0.17677669529663687f * temp[h];
        __half2* qrow = (__half2*)(Qs + i * 40 + hp * 16);
        __half2* krow = (__half2*)(Ks + i * 40 + hp * 16);
#pragma unroll
        for (int u = 0; u < 8; u++) {
            qrow[u] = __floats2half2_rn(qf[2*u] * qmul, qf[2*u+1] * qmul);
            krow[u] = __floats2half2_rn(kf[2*u] * kmul, kf[2*u+1] * kmul);
        }
#pragma unroll
        for (int u = 0; u < 16; u++)
            Vt[(hp * 16 + u) * 72 + i] = __float2half_rn(vf[u]);
    }
    __syncthreads();

    const uint32_t qs_u = smem_u32(Qs);
    const uint32_t ks_u = smem_u32(Ks);
    const uint32_t vt_u = smem_u32(Vt);

    // ---- QK^T: M=64 N=64 K=32 ----
    float s[8][4];
#pragma unroll
    for (int ni = 0; ni < 8; ni++)
#pragma unroll
        for (int r = 0; r < 4; r++) s[ni][r] = 0.f;
#pragma unroll
    for (int ks = 0; ks < 2; ks++) {
        uint32_t af[4];
        ldsm4(af, qs_u + (16 * w + (lane & 15)) * 80 + ks * 32 + (lane >> 4) * 16);
#pragma unroll
        for (int pn = 0; pn < 4; pn++) {
            uint32_t tt[4];
            ldsm4(tt, ks_u + (pn * 16 + ((lane >> 4) << 3) + (lane & 7)) * 80
                       + ks * 32 + ((lane >> 3) & 1) * 16);
            mma16(s[2*pn],     af, tt);
            mma16(s[2*pn + 1], af, tt + 2);
        }
    }

    // ---- softmax in fragments (rows g, g+8 of warp block) ----
    float mx0 = -1e30f, mx1 = -1e30f;
#pragma unroll
    for (int ni = 0; ni < 8; ni++) {
        mx0 = fmaxf(mx0, fmaxf(s[ni][0], s[ni][1]));
        mx1 = fmaxf(mx1, fmaxf(s[ni][2], s[ni][3]));
    }
    mx0 = fmaxf(mx0, __shfl_xor_sync(0xffffffffu, mx0, 1));
    mx0 = fmaxf(mx0, __shfl_xor_sync(0xffffffffu, mx0, 2));
    mx1 = fmaxf(mx1, __shfl_xor_sync(0xffffffffu, mx1, 1));
    mx1 = fmaxf(mx1, __shfl_xor_sync(0xffffffffu, mx1, 2));
    float sum0 = 0.f, sum1 = 0.f;
#pragma unroll
    for (int ni = 0; ni < 8; ni++) {
        s[ni][0] = __expf(s[ni][0] - mx0);
        s[ni][1] = __expf(s[ni][1] - mx0);
        s[ni][2] = __expf(s[ni][2] - mx1);
        s[ni][3] = __expf(s[ni][3] - mx1);
        sum0 += s[ni][0] + s[ni][1];
        sum1 += s[ni][2] + s[ni][3];
    }
    sum0 += __shfl_xor_sync(0xffffffffu, sum0, 1);
    sum0 += __shfl_xor_sync(0xffffffffu, sum0, 2);
    sum1 += __shfl_xor_sync(0xffffffffu, sum1, 1);
    sum1 += __shfl_xor_sync(0xffffffffu, sum1, 2);
    float inv0 = 1.f / sum0, inv1 = 1.f / sum1;

    // ---- P x V: M=64 N=32 K=64 (P repacked c-frag -> a-frag) ----
    float o[4][4];
#pragma unroll
    for (int nd = 0; nd < 4; nd++)
#pragma unroll
        for (int r = 0; r < 4; r++) o[nd][r] = 0.f;
#pragma unroll
    for (int s4 = 0; s4 < 4; s4++) {
        uint32_t ap[4];
        ap[0] = f2h2(s[2*s4][0],     s[2*s4][1]);
        ap[1] = f2h2(s[2*s4][2],     s[2*s4][3]);
        ap[2] = f2h2(s[2*s4 + 1][0], s[2*s4 + 1][1]);
        ap[3] = f2h2(s[2*s4 + 1][2], s[2*s4 + 1][3]);
        uint32_t tt[4];
        ldsm4(tt, vt_u + (((lane >> 4) << 3) + (lane & 7)) * 144
                   + s4 * 32 + ((lane >> 3) & 1) * 16);
        mma16(o[0], ap, tt);
        mma16(o[1], ap, tt + 2);
        ldsm4(tt, vt_u + (16 + ((lane >> 4) << 3) + (lane & 7)) * 144
                   + s4 * 32 + ((lane >> 3) & 1) * 16);
        mma16(o[2], ap, tt);
        mma16(o[3], ap, tt + 2);
    }

    // ---- stage output in smem (reuse Qs: own rows only), coalesced store ----
    __half2* Os = (__half2*)Qs;
#pragma unroll
    for (int nd = 0; nd < 4; nd++) {
        int col2 = (nd * 8 + 2 * tg) >> 1;
        Os[(16 * w + g)     * 20 + col2] = __floats2half2_rn(o[nd][0] * inv0, o[nd][1] * inv0);
        Os[(16 * w + g + 8) * 20 + col2] = __floats2half2_rn(o[nd][2] * inv1, o[nd][3] * inv1);
    }
    __syncthreads();
    {
        int i = t >> 1, hp = t & 1;
        int y = ((win >> 5) << 3) + (i >> 3);
        int x = ((win & 31) << 3) + (i & 7);
        int pidx = (b << 16) + (y << 8) + x;
        size_t rc = ((size_t)pidx << 8) + (h << 5) + hp * 16;
        const uint4* src = (const uint4*)(Qs + i * 40 + hp * 16);
        uint4* dst = (uint4*)(out + rc);
        dst[0] = src[0];
        dst[1] = src[1];
    }
}

// ---------------- launch ----------------
extern "C" void kernel_launch(void* const* d_in, const int* in_sizes, int n_in,
                              void* d_out, int out_size) {
    const float* x      = (const float*)d_in[0];
    const float* w_iem  = (const float*)d_in[1];
    const float* g_iem  = (const float*)d_in[2];
    const float* b_iem  = (const float*)d_in[3];
    const float* w_nem  = (const float*)d_in[4];
    const float* g_nem  = (const float*)d_in[5];
    const float* b_nem  = (const float*)d_in[6];
    const float* w_idw  = (const float*)d_in[7];
    const float* w_ndw  = (const float*)d_in[8];
    const float* w_q    = (const float*)d_in[9];
    const float* w_k    = (const float*)d_in[10];
    const float* w_v    = (const float*)d_in[11];
    const float* w_proj = (const float*)d_in[12];
    const float* temp   = (const float*)d_in[13];
    float* out = (float*)d_out;

    float *PART, *PART2, *BNA, *BNC, *IS, *NS;
    __half *Xh, *Hc1, *Hc2, *Hd1, *Hd2, *Hq, *Hk, *Hv, *Ha, *WCT, *WT4;
    cudaGetSymbolAddress((void**)&Xh,    g_Xh);
    cudaGetSymbolAddress((void**)&Hc1,   g_Hc1);
    cudaGetSymbolAddress((void**)&Hc2,   g_Hc2);
    cudaGetSymbolAddress((void**)&Hd1,   g_Hd1);
    cudaGetSymbolAddress((void**)&Hd2,   g_Hd2);
    cudaGetSymbolAddress((void**)&Hq,    g_Hq);
    cudaGetSymbolAddress((void**)&Hk,    g_Hk);
    cudaGetSymbolAddress((void**)&Hv,    g_Hv);
    cudaGetSymbolAddress((void**)&Ha,    g_Ha);
    cudaGetSymbolAddress((void**)&WCT,   g_wct);
    cudaGetSymbolAddress((void**)&WT4,   g_wt4);
    cudaGetSymbolAddress((void**)&PART,  g_part);
    cudaGetSymbolAddress((void**)&PART2, g_part2);
    cudaGetSymbolAddress((void**)&BNA,   g_bna);
    cudaGetSymbolAddress((void**)&BNC,   g_bnc);
    cudaGetSymbolAddress((void**)&IS,    g_is);
    cudaGetSymbolAddress((void**)&NS,    g_ns);

    const int CSM = CONV_STG_B * 3;               // 99840
    const int GSM = 67584;
    cudaFuncSetAttribute(conv_mma,  cudaFuncAttributeMaxDynamicSharedMemorySize, CSM);
    cudaFuncSetAttribute(gemm_qkv,  cudaFuncAttributeMaxDynamicSharedMemorySize, GSM);
    cudaFuncSetAttribute(gemm_proj, cudaFuncAttributeMaxDynamicSharedMemorySize, GSM);

    tconv_kernel<<<4608, 256>>>(w_iem, w_nem, WCT);
    t1x1_kernel<<<1024, 256>>>(w_q, w_k, w_v, w_proj, WT4);
    xT_kernel<<<dim3(2048, 8, 2), dim3(32, 32)>>>(x, Xh);

    conv_mma<<<dim3(512, 2, 4), 256, CSM>>>(Xh, WCT, Hc1, Hc2, PART);

    bnstats2a<<<dim3(2, 32), 256>>>(PART, PART2);
    bnstats2b<<<2, 256>>>(PART2, g_iem, b_iem, g_nem, b_nem, BNA, BNC);

    dwconv_t<<<dim3(65536, 2), 128>>>(Hc1, Hc2, BNA, BNC, w_idw, w_ndw,
                                      Hd1, Hd2, IS, NS);

    gemm_qkv<<<dim3(512, 2, 6), 256, GSM>>>(WT4, Hd1, Hd2, Xh, Hq, Hk, Hv);

    attn_mma<<<dim3(1024, 8, 2), 128>>>(Hq, Hk, Hv, IS, NS, temp, Ha);

    gemm_proj<<<dim3(512, 2, 2), 256, GSM>>>(WT4 + 3 * 65536, Ha, out);
}